// round 2
// baseline (speedup 1.0000x reference)
#include <cuda_runtime.h>
#include <math.h>

// ---------------- problem constants ----------------
#define BB     32
#define NENT   1024
#define LQL    128
#define DFEAT  2112
#define CTX    512
#define CMD    512
#define TT     4
#define MROWS  (BB*NENT)     // 32768
#define NEGV   (-1e30f)

// ---------------- scratch (device globals; no allocation allowed) ----------------
__device__ float g_invnorm[MROWS];
__device__ float g_xloc   [(size_t)MROWS*CTX];
__device__ float g_xctx0  [(size_t)MROWS*CTX];
__device__ float g_xctx1  [(size_t)MROWS*CTX];
__device__ float g_projloc[(size_t)MROWS*CTX];
__device__ float g_pp     [(size_t)MROWS*CTX];
__device__ float g_q      [(size_t)MROWS*CTX];
__device__ float g_k      [(size_t)MROWS*CTX];
__device__ float g_v      [(size_t)MROWS*CTX];
__device__ float g_msg    [(size_t)MROWS*CTX];
__device__ float g_score  [(size_t)BB*NENT*NENT];
__device__ float g_qbase  [BB*CMD];
__device__ float g_qcmd   [BB*CMD];
__device__ float g_cmd    [BB*CMD];
__device__ float g_pkg    [BB*CTX];
__device__ float g_pvg    [BB*CTX];

// ---------------- generic tiled SGEMM ----------------
// C[M,N] = epilogue( A @ B ),  A row-major (optionally a virtual concat of up
// to 3 buffers each 512 cols wide), B row-major [K,N] or (TB) row-major [N,K].
// Tile 128x128x8, 256 threads, 8x8 per thread. All dims are exact multiples.
#define BM 128
#define BN 128
#define BK 8
#define TM 8
#define TN 8
#define SPAD 4

// EPI: 0: out = acc*alpha + bias[n]
//      1: out = acc*extra[m] + bias[n]                      (row scale: initKB)
//      2: out = (acc + bias[n]) * extra[(m>>10)*ldgate + n] (per-batch gate: k,v)
//      3: out = (acc + bias[n]) * extra[m*ldc + n]          (elementwise: pp)
template<int NSRC, bool TB, int EPI>
__global__ __launch_bounds__(256, 2)
void gemm_kernel(const float* __restrict__ A0, const float* __restrict__ A1,
                 const float* __restrict__ A2, const float* __restrict__ Bm,
                 const float* __restrict__ bias, const float* __restrict__ extra,
                 float* __restrict__ C,
                 int K, int lda, int ldb, int ldc, int ldgate,
                 size_t sA, size_t sB, size_t sC, float alpha)
{
    __shared__ float As[BK][BM + SPAD];
    __shared__ float Bs[BK][BN + SPAD];

    const int z = blockIdx.z;
    const float* Abase = A0 + (size_t)z * sA;
    const float* Bbase = Bm + (size_t)z * sB;
    float* Cbase = C + (size_t)z * sC;

    const int m0 = blockIdx.y * BM;
    const int n0 = blockIdx.x * BN;
    const int tid = threadIdx.x;

    const int ldRow = tid >> 1;          // 0..127
    const int ldCol = (tid & 1) * 4;     // 0 or 4
    const int bRow  = tid >> 5;          // 0..7
    const int bCol  = (tid & 31) * 4;    // 0..124

    const int tx = tid & 15;
    const int ty = tid >> 4;

    float acc[TM][TN] = {};

    for (int k0 = 0; k0 < K; k0 += BK) {
        // ---- load A tile (transposed into smem) ----
        const float* Ap; int ac; int al;
        if (NSRC == 1) { Ap = Abase; ac = k0; al = lda; }
        else {
            const int src = k0 >> 9;     // 512-wide chunks
            Ap = (src == 0) ? A0 : ((src == 1) ? A1 : A2);
            ac = k0 & 511; al = 512;
        }
        float4 av = *reinterpret_cast<const float4*>(Ap + (size_t)(m0 + ldRow) * al + ac + ldCol);
        As[ldCol + 0][ldRow] = av.x;
        As[ldCol + 1][ldRow] = av.y;
        As[ldCol + 2][ldRow] = av.z;
        As[ldCol + 3][ldRow] = av.w;

        // ---- load B tile ----
        if (!TB) {
            float4 bv = *reinterpret_cast<const float4*>(Bbase + (size_t)(k0 + bRow) * ldb + n0 + bCol);
            *reinterpret_cast<float4*>(&Bs[bRow][bCol]) = bv;
        } else {
            float4 bv = *reinterpret_cast<const float4*>(Bbase + (size_t)(n0 + ldRow) * ldb + k0 + ldCol);
            Bs[ldCol + 0][ldRow] = bv.x;
            Bs[ldCol + 1][ldRow] = bv.y;
            Bs[ldCol + 2][ldRow] = bv.z;
            Bs[ldCol + 3][ldRow] = bv.w;
        }
        __syncthreads();

        #pragma unroll
        for (int kk = 0; kk < BK; kk++) {
            float ar[TM], br[TN];
            #pragma unroll
            for (int i = 0; i < TM; i++) ar[i] = As[kk][ty * TM + i];
            #pragma unroll
            for (int j = 0; j < TN; j++) br[j] = Bs[kk][tx * TN + j];
            #pragma unroll
            for (int i = 0; i < TM; i++)
                #pragma unroll
                for (int j = 0; j < TN; j++)
                    acc[i][j] = fmaf(ar[i], br[j], acc[i][j]);
        }
        __syncthreads();
    }

    // ---- epilogue ----
    float bcol[TN];
    #pragma unroll
    for (int j = 0; j < TN; j++) bcol[j] = bias ? bias[n0 + tx * TN + j] : 0.f;

    #pragma unroll
    for (int i = 0; i < TM; i++) {
        const int m = m0 + ty * TM + i;
        float out[TN];
        if (EPI == 0) {
            #pragma unroll
            for (int j = 0; j < TN; j++) out[j] = acc[i][j] * alpha + bcol[j];
        } else if (EPI == 1) {
            const float rs = extra[m];
            #pragma unroll
            for (int j = 0; j < TN; j++) out[j] = acc[i][j] * rs + bcol[j];
        } else if (EPI == 2) {
            const float* g = extra + (size_t)(m >> 10) * ldgate + n0 + tx * TN;
            #pragma unroll
            for (int j = 0; j < TN; j++) out[j] = (acc[i][j] + bcol[j]) * g[j];
        } else { // EPI == 3
            const float* g = extra + (size_t)m * ldc + n0 + tx * TN;
            #pragma unroll
            for (int j = 0; j < TN; j++) out[j] = (acc[i][j] + bcol[j]) * g[j];
        }
        float4* cp = reinterpret_cast<float4*>(Cbase + (size_t)m * ldc + n0 + tx * TN);
        cp[0] = make_float4(out[0], out[1], out[2], out[3]);
        cp[1] = make_float4(out[4], out[5], out[6], out[7]);
    }
}

// ---------------- small helper kernels ----------------

// inverse L2 norm of each image row (folded into initKB epilogue)
__global__ void rownorm_kernel(const float* __restrict__ img, float* __restrict__ invn)
{
    const int m = blockIdx.x;
    const float* r = img + (size_t)m * DFEAT;
    const int tid = threadIdx.x;
    float s = 0.f;
    for (int k = tid; k < DFEAT; k += 256) { float x = r[k]; s = fmaf(x, x, s); }
    __shared__ float red[256];
    red[tid] = s; __syncthreads();
    for (int o = 128; o > 0; o >>= 1) { if (tid < o) red[tid] += red[tid + o]; __syncthreads(); }
    if (tid == 0) invn[m] = 1.f / fmaxf(sqrtf(red[0]), 1e-12f);
}

__global__ void ctx_init_kernel(const float* __restrict__ initMem, float* __restrict__ xctx)
{
    const size_t i = (size_t)blockIdx.x * blockDim.x + threadIdx.x;
    xctx[i] = initMem[i & (CTX - 1)];
}

// [32,512] = in[32,512] @ W[512,512] + b  (optional ELU)
template<bool ELU>
__global__ void small_linear_kernel(const float* __restrict__ in, const float* __restrict__ W,
                                    const float* __restrict__ bias, float* __restrict__ out)
{
    const int b = blockIdx.x;
    const int tid = threadIdx.x;
    __shared__ float x[CMD];
    for (int d = tid; d < CMD; d += 256) x[d] = in[b * CMD + d];
    __syncthreads();
    for (int j = tid; j < CMD; j += 256) {
        float acc = 0.f;
        #pragma unroll 4
        for (int k = 0; k < CMD; k++) acc = fmaf(x[k], W[(size_t)k * CMD + j], acc);
        acc += bias[j];
        if (ELU) acc = (acc > 0.f) ? acc : expm1f(acc);
        out[b * CMD + j] = acc;
    }
}

// textual command: raw = (q_cmd * lstm) @ c2l_w + c2l_b ; masked softmax ; cmd = att @ lstm
__global__ void text_cmd_kernel(const float* __restrict__ qcmd, const float* __restrict__ lstm,
                                const float* __restrict__ c2l_w, const float* __restrict__ c2l_b,
                                const int* __restrict__ qlen, float* __restrict__ cmd)
{
    const int b = blockIdx.x;
    const int tid = threadIdx.x;
    __shared__ float e[CMD];
    __shared__ float att[LQL];
    for (int d = tid; d < CMD; d += 256) e[d] = qcmd[b * CMD + d] * c2l_w[d];
    __syncthreads();
    if (tid < LQL) {
        const float* L = lstm + ((size_t)b * LQL + tid) * CMD;
        float acc = 0.f;
        for (int d = 0; d < CMD; d++) acc = fmaf(L[d], e[d], acc);
        acc += c2l_b[0];
        att[tid] = (tid >= qlen[b]) ? NEGV : acc;
    }
    __syncthreads();
    if (tid == 0) {
        float mx = -3.4e38f;
        for (int l = 0; l < LQL; l++) mx = fmaxf(mx, att[l]);
        float sum = 0.f;
        for (int l = 0; l < LQL; l++) { att[l] = expf(att[l] - mx); sum += att[l]; }
        const float inv = 1.f / sum;
        for (int l = 0; l < LQL; l++) att[l] *= inv;
    }
    __syncthreads();
    for (int d = tid; d < CMD; d += 256) {
        float acc = 0.f;
        #pragma unroll 4
        for (int l = 0; l < LQL; l++) acc = fmaf(att[l], lstm[((size_t)b * LQL + l) * CMD + d], acc);
        cmd[b * CMD + d] = acc;
    }
}

// masked row softmax over the [B,N,N] score tensor (in place)
__global__ void attn_softmax_kernel(float* __restrict__ score, const int* __restrict__ entity_num)
{
    const int row = blockIdx.x;        // 0 .. B*N-1
    const int b = row >> 10;
    const int n = row & 1023;
    const int en = entity_num[b];
    float* s = score + (size_t)row * NENT;
    const bool rmask = (n >= en);
    const int tid = threadIdx.x;

    float v[4];
    float mx = -3.4e38f;
    #pragma unroll
    for (int j = 0; j < 4; j++) {
        const int m = tid + j * 256;
        float x = s[m];
        x = (rmask || m >= en) ? NEGV : x;
        v[j] = x;
        mx = fmaxf(mx, x);
    }
    __shared__ float red[256];
    red[tid] = mx; __syncthreads();
    for (int o = 128; o > 0; o >>= 1) { if (tid < o) red[tid] = fmaxf(red[tid], red[tid + o]); __syncthreads(); }
    mx = red[0];
    __syncthreads();

    float sum = 0.f;
    #pragma unroll
    for (int j = 0; j < 4; j++) { v[j] = expf(v[j] - mx); sum += v[j]; }
    red[tid] = sum; __syncthreads();
    for (int o = 128; o > 0; o >>= 1) { if (tid < o) red[tid] += red[tid + o]; __syncthreads(); }
    const float inv = 1.f / red[0];

    #pragma unroll
    for (int j = 0; j < 4; j++) s[tid + j * 256] = v[j] * inv;
}

// ---------------- launch ----------------
template<typename T> static float* symaddr(T& sym) {
    void* p = nullptr;
    cudaGetSymbolAddress(&p, sym);
    return (float*)p;
}

extern "C" void kernel_launch(void* const* d_in, const int* in_sizes, int n_in,
                              void* d_out, int out_size)
{
    const float* images    = (const float*)d_in[0];
    const float* q_enc     = (const float*)d_in[1];
    const float* lstm      = (const float*)d_in[2];
    const int*   q_length  = (const int*)  d_in[3];
    const int*   ent_num   = (const int*)  d_in[4];
    const float* initKB_w  = (const float*)d_in[5];
    const float* initKB_b  = (const float*)d_in[6];
    const float* initMem   = (const float*)d_in[7];
    const float* qInput_w  = (const float*)d_in[8];
    const float* qInput_b  = (const float*)d_in[9];
    const float* qInput2_w = (const float*)d_in[10];
    const float* qInput2_b = (const float*)d_in[11];
    const float* c2l_w     = (const float*)d_in[12];
    const float* c2l_b     = (const float*)d_in[13];
    const float* pxl_w     = (const float*)d_in[14];
    const float* pxl_b     = (const float*)d_in[15];
    const float* pxc_w     = (const float*)d_in[16];
    const float* pxc_b     = (const float*)d_in[17];
    const float* qry_w     = (const float*)d_in[18];
    const float* qry_b     = (const float*)d_in[19];
    const float* key_w     = (const float*)d_in[20];
    const float* key_b     = (const float*)d_in[21];
    const float* val_w     = (const float*)d_in[22];
    const float* val_b     = (const float*)d_in[23];
    const float* pk_w      = (const float*)d_in[24];
    const float* pk_b      = (const float*)d_in[25];
    const float* pv_w      = (const float*)d_in[26];
    const float* pv_b      = (const float*)d_in[27];
    const float* mu_w      = (const float*)d_in[28];
    const float* mu_b      = (const float*)d_in[29];
    const float* ck_w      = (const float*)d_in[30];
    const float* ck_b      = (const float*)d_in[31];

    float* invn    = symaddr(g_invnorm);
    float* xloc    = symaddr(g_xloc);
    float* xctx[2] = { symaddr(g_xctx0), symaddr(g_xctx1) };
    float* projloc = symaddr(g_projloc);
    float* pp      = symaddr(g_pp);
    float* q       = symaddr(g_q);
    float* k       = symaddr(g_k);
    float* v       = symaddr(g_v);
    float* msg     = symaddr(g_msg);
    float* score   = symaddr(g_score);
    float* qbase   = symaddr(g_qbase);
    float* qcmd    = symaddr(g_qcmd);
    float* cmd     = symaddr(g_cmd);
    float* pkg     = symaddr(g_pkg);
    float* pvg     = symaddr(g_pvg);

    const float scale = 0.044194173824159216f;   // 1/sqrt(512)
    const dim3 gridMain(CTX / BN, MROWS / BM, 1);          // (4, 256)
    const dim3 gridScore(NENT / BN, NENT / BM, BB);        // (8, 8, 32)
    const dim3 gridMsg(CTX / BN, NENT / BM, BB);           // (4, 8, 32)

    // ---- setup ----
    rownorm_kernel<<<MROWS, 256>>>(images, invn);
    ctx_init_kernel<<<(MROWS * CTX) / 256, 256>>>(initMem, xctx[0]);
    small_linear_kernel<true><<<BB, 256>>>(q_enc, qInput_w, qInput_b, qbase);

    // x_loc = normalize(images) @ initKB_w + b    (norm folded into epilogue)
    gemm_kernel<1, false, 1><<<gridMain, 256>>>(
        images, nullptr, nullptr, initKB_w, initKB_b, invn, xloc,
        DFEAT, DFEAT, CTX, CTX, 0, 0, 0, 0, 1.f);

    int cur = 0;
    for (int t = 0; t < TT; t++) {
        // textual command
        small_linear_kernel<false><<<BB, 256>>>(qbase, qInput2_w + (size_t)t * CMD * CMD,
                                                qInput2_b + (size_t)t * CMD, qcmd);
        text_cmd_kernel<<<BB, 256>>>(qcmd, lstm, c2l_w, c2l_b, q_length, cmd);
        small_linear_kernel<false><<<BB, 256>>>(cmd, pk_w, pk_b, pkg);
        small_linear_kernel<false><<<BB, 256>>>(cmd, pv_w, pv_b, pvg);

        // proj_loc = x_loc @ pxl + b
        gemm_kernel<1, false, 0><<<gridMain, 256>>>(
            xloc, nullptr, nullptr, pxl_w, pxl_b, nullptr, projloc,
            CTX, CTX, CTX, CTX, 0, 0, 0, 0, 1.f);
        // pp = (x_ctx @ pxc + b) * proj_loc
        gemm_kernel<1, false, 3><<<gridMain, 256>>>(
            xctx[cur], nullptr, nullptr, pxc_w, pxc_b, projloc, pp,
            CTX, CTX, CTX, CTX, 0, 0, 0, 0, 1.f);

        // q/k/v over virtual concat [x_loc | x_ctx | pp]  (K = 1536)
        gemm_kernel<3, false, 0><<<gridMain, 256>>>(
            xloc, xctx[cur], pp, qry_w, qry_b, nullptr, q,
            3 * CTX, 0, CTX, CTX, 0, 0, 0, 0, 1.f);
        gemm_kernel<3, false, 2><<<gridMain, 256>>>(
            xloc, xctx[cur], pp, key_w, key_b, pkg, k,
            3 * CTX, 0, CTX, CTX, CTX, 0, 0, 0, 1.f);
        gemm_kernel<3, false, 2><<<gridMain, 256>>>(
            xloc, xctx[cur], pp, val_w, val_b, pvg, v,
            3 * CTX, 0, CTX, CTX, CTX, 0, 0, 0, 1.f);

        // score[b] = scale * q[b] @ k[b]^T   (batched NT)
        gemm_kernel<1, true, 0><<<gridScore, 256>>>(
            q, nullptr, nullptr, k, nullptr, nullptr, score,
            CTX, CTX, CTX, NENT, 0,
            (size_t)NENT * CTX, (size_t)NENT * CTX, (size_t)NENT * NENT, scale);

        attn_softmax_kernel<<<MROWS, 256>>>(score, ent_num);

        // message[b] = prob[b] @ v[b]   (batched NN)
        gemm_kernel<1, false, 0><<<gridMsg, 256>>>(
            score, nullptr, nullptr, v, nullptr, nullptr, msg,
            NENT, NENT, CTX, CTX, 0,
            (size_t)NENT * NENT, (size_t)NENT * CTX, (size_t)NENT * CTX, 1.f);

        // x_ctx' = [x_ctx | message] @ mu + b
        gemm_kernel<2, false, 0><<<gridMain, 256>>>(
            xctx[cur], msg, nullptr, mu_w, mu_b, nullptr, xctx[cur ^ 1],
            2 * CTX, 0, CTX, CTX, 0, 0, 0, 0, 1.f);
        cur ^= 1;
    }

    // out = [x_loc | x_ctx] @ ck + b
    gemm_kernel<2, false, 0><<<gridMain, 256>>>(
        xloc, xctx[cur], nullptr, ck_w, ck_b, nullptr, (float*)d_out,
        2 * CTX, 0, CTX, CTX, 0, 0, 0, 0, 1.f);
}

// round 4
// speedup vs baseline: 2.7045x; 2.7045x over previous
#include <cuda_runtime.h>
#include <math.h>
#include <stdint.h>

#define BB     32
#define NENT   1024
#define LQL    128
#define DFEAT  2112
#define CTX    512
#define CMD    512
#define TT     4
#define MROWS  (BB*NENT)
#define NEGV   (-1e30f)

// ---- mma.sync GEMM tiling ----
#define BMm 128
#define BNm 128
#define BKm 16
#define SST 136          // smem row stride in floats (8 mod 32 -> bank spread)

// ---- scratch ----
__device__ float g_imgr   [(size_t)MROWS*DFEAT];
__device__ float g_invnorm[MROWS];
__device__ float g_xloc   [(size_t)MROWS*CTX];
__device__ float g_xctx0  [(size_t)MROWS*CTX];
__device__ float g_xctx1  [(size_t)MROWS*CTX];
__device__ float g_projloc[(size_t)MROWS*CTX];
__device__ float g_pp     [(size_t)MROWS*CTX];
__device__ float g_q      [(size_t)MROWS*CTX];
__device__ float g_k      [(size_t)MROWS*CTX];
__device__ float g_v      [(size_t)MROWS*CTX];
__device__ float g_vT     [(size_t)MROWS*CTX];
__device__ float g_msg    [(size_t)MROWS*CTX];
__device__ float g_score  [(size_t)BB*NENT*NENT];
__device__ float g_qbase  [BB*CMD];
__device__ float g_qcmd   [BB*CMD];
__device__ float g_cmd    [BB*CMD];
__device__ float g_pkg    [BB*CTX];
__device__ float g_pvg    [BB*CTX];
__device__ float g_wT_ikb[(size_t)CTX*DFEAT];
__device__ float g_wT_pxl[(size_t)CTX*CTX];
__device__ float g_wT_pxc[(size_t)CTX*CTX];
__device__ float g_wT_qry[(size_t)CTX*3*CTX];
__device__ float g_wT_key[(size_t)CTX*3*CTX];
__device__ float g_wT_val[(size_t)CTX*3*CTX];
__device__ float g_wT_mu [(size_t)CTX*2*CTX];
__device__ float g_wT_ck [(size_t)CTX*2*CTX];

__device__ __forceinline__ float rna_tf32(float f) {
    uint32_t r; asm("cvt.rna.tf32.f32 %0, %1;" : "=r"(r) : "f"(f));
    return __uint_as_float(r);
}

__device__ __forceinline__ void mma_m16n8k8(float* d,
    uint32_t a0, uint32_t a1, uint32_t a2, uint32_t a3,
    uint32_t b0, uint32_t b1)
{
    asm volatile(
        "mma.sync.aligned.m16n8k8.row.col.f32.tf32.tf32.f32 "
        "{%0,%1,%2,%3}, {%4,%5,%6,%7}, {%8,%9}, {%0,%1,%2,%3};"
        : "+f"(d[0]), "+f"(d[1]), "+f"(d[2]), "+f"(d[3])
        : "r"(a0), "r"(a1), "r"(a2), "r"(a3), "r"(b0), "r"(b1));
}

// ---------------- tensor-core GEMM via mma.sync (tf32) ----------------
// C[M,N] = epi( A @ B^T ); A row-major [M,K] (virtual concat of up to 3
// CTX-wide buffers), B K-major [N,K]. Operands pre-rounded to tf32 by producers.
// EPI 0: acc*alpha + bias[n]
// EPI 1: acc*extra[m] + bias[n]
// EPI 2: (acc+bias[n]) * extra[(m>>10)*CTX + n]
// EPI 3: (acc+bias[n]) * extra[m*ldc + n]
template<int NSRC, int EPI, bool RND>
__global__ __launch_bounds__(256, 2)
void gemm_mma(const float* __restrict__ A0, const float* __restrict__ A1,
              const float* __restrict__ A2, const float* __restrict__ Bt,
              const float* __restrict__ bias, const float* __restrict__ extra,
              float* __restrict__ C,
              int K, int lda, int ldb, int ldc,
              size_t sA, size_t sB, size_t sC, float alpha)
{
    __shared__ float As[2][BKm * SST];
    __shared__ float Bs[2][BKm * SST];

    const int tid = threadIdx.x;
    const int z = blockIdx.z;
    const int m0 = blockIdx.y * BMm;
    const int n0 = blockIdx.x * BNm;
    const float* Abase = A0 + (size_t)z * sA;
    const float* Bbase = Bt + (size_t)z * sB;
    float* Cbase = C + (size_t)z * sC;

    const int wid = tid >> 5, lane = tid & 31;
    const int wm = (wid & 3) * 32;        // warp M offset in block
    const int wn = (wid >> 2) * 64;       // warp N offset in block
    const int gr = lane >> 2;             // group row 0..7
    const int gc = lane & 3;              // group col 0..3

    // producer thread coords: 2 float4 per tile (rows prow, prow+64)
    const int prow = tid >> 2;            // 0..63
    const int pc4 = (tid & 3) * 4;        // k offset of float4

    float acc[2][8][4] = {};

    const int NCC = K / BKm;

    // ---- helpers ----
    auto stsSwz = [&](float* S, int row, float4 v) {
        const float* pv = reinterpret_cast<const float*>(&v);
        #pragma unroll
        for (int i = 0; i < 4; ++i) {
            const int kk = pc4 + i;
            const int x = ((kk >> 2) & 3) << 3;
            S[kk * SST + (row ^ x)] = pv[i];
        }
    };
    auto fetchA = [&](int k0, float4& v0, float4& v1) {
        const float* Ap; int al, ak;
        if (NSRC == 1) { Ap = Abase; al = lda; ak = k0; }
        else {
            const int src = k0 >> 9;
            Ap = (src == 0) ? A0 : ((src == 1) ? A1 : A2);
            al = CTX; ak = k0 & (CTX - 1);
        }
        v0 = *reinterpret_cast<const float4*>(Ap + (size_t)(m0 + prow)      * al + ak + pc4);
        v1 = *reinterpret_cast<const float4*>(Ap + (size_t)(m0 + prow + 64) * al + ak + pc4);
    };
    auto fetchB = [&](int k0, float4& v0, float4& v1) {
        v0 = *reinterpret_cast<const float4*>(Bbase + (size_t)(n0 + prow)      * ldb + k0 + pc4);
        v1 = *reinterpret_cast<const float4*>(Bbase + (size_t)(n0 + prow + 64) * ldb + k0 + pc4);
    };
    auto compute = [&](const float* SA, const float* SB) {
        #pragma unroll
        for (int kk = 0; kk < BKm; kk += 8) {
            const int X1 = ((kk >> 2) & 3) << 3;
            const int X2 = (((kk + 4) >> 2) & 3) << 3;
            uint32_t b[8][2];
            #pragma unroll
            for (int nt = 0; nt < 8; ++nt) {
                const int n = wn + nt * 8 + gr;
                b[nt][0] = __float_as_uint(SB[(kk + gc)     * SST + (n ^ X1)]);
                b[nt][1] = __float_as_uint(SB[(kk + 4 + gc) * SST + (n ^ X2)]);
            }
            #pragma unroll
            for (int mt = 0; mt < 2; ++mt) {
                const int m = wm + mt * 16 + gr;
                const uint32_t a0 = __float_as_uint(SA[(kk + gc)     * SST + ( m      ^ X1)]);
                const uint32_t a1 = __float_as_uint(SA[(kk + gc)     * SST + ((m + 8) ^ X1)]);
                const uint32_t a2 = __float_as_uint(SA[(kk + 4 + gc) * SST + ( m      ^ X2)]);
                const uint32_t a3 = __float_as_uint(SA[(kk + 4 + gc) * SST + ((m + 8) ^ X2)]);
                #pragma unroll
                for (int nt = 0; nt < 8; ++nt)
                    mma_m16n8k8(acc[mt][nt], a0, a1, a2, a3, b[nt][0], b[nt][1]);
            }
        }
    };

    // ---- mainloop (double-buffered) ----
    {
        float4 a0, a1, b0, b1;
        fetchA(0, a0, a1); fetchB(0, b0, b1);
        stsSwz(As[0], prow, a0); stsSwz(As[0], prow + 64, a1);
        stsSwz(Bs[0], prow, b0); stsSwz(Bs[0], prow + 64, b1);
    }
    __syncthreads();
    for (int c = 0; c < NCC; ++c) {
        float4 a0, a1, b0, b1;
        const bool pf = (c + 1 < NCC);
        if (pf) { fetchA((c + 1) * BKm, a0, a1); fetchB((c + 1) * BKm, b0, b1); }
        compute(As[c & 1], Bs[c & 1]);
        if (pf) {
            const int nb = (c + 1) & 1;
            stsSwz(As[nb], prow, a0); stsSwz(As[nb], prow + 64, a1);
            stsSwz(Bs[nb], prow, b0); stsSwz(Bs[nb], prow + 64, b1);
        }
        __syncthreads();
    }

    // ---- epilogue: direct per-lane float2 stores ----
    #pragma unroll
    for (int mt = 0; mt < 2; ++mt) {
        #pragma unroll
        for (int half = 0; half < 2; ++half) {
            const int m = m0 + wm + mt * 16 + gr + half * 8;
            const float rs = (EPI == 1) ? extra[m] : 0.f;
            #pragma unroll
            for (int nt = 0; nt < 8; ++nt) {
                const int n = n0 + wn + nt * 8 + gc * 2;
                float v0 = acc[mt][nt][half * 2 + 0];
                float v1 = acc[mt][nt][half * 2 + 1];
                const float bb0 = bias ? bias[n]     : 0.f;
                const float bb1 = bias ? bias[n + 1] : 0.f;
                if (EPI == 0)      { v0 = v0 * alpha + bb0;  v1 = v1 * alpha + bb1; }
                else if (EPI == 1) { v0 = v0 * rs + bb0;     v1 = v1 * rs + bb1; }
                else if (EPI == 2) {
                    const float* g = extra + (size_t)(m >> 10) * CTX + n;
                    v0 = (v0 + bb0) * g[0];
                    v1 = (v1 + bb1) * g[1];
                } else {
                    const float* g = extra + (size_t)m * ldc + n;
                    v0 = (v0 + bb0) * g[0];
                    v1 = (v1 + bb1) * g[1];
                }
                if (RND) { v0 = rna_tf32(v0); v1 = rna_tf32(v1); }
                *reinterpret_cast<float2*>(Cbase + (size_t)m * ldc + n) = make_float2(v0, v1);
            }
        }
    }
}

// ---- transpose (+tf32 round): out[C,R] = rnd(in[R,C]^T), batched ----
__global__ void transpose_kernel(const float* __restrict__ in, float* __restrict__ out,
                                 int R, int C, size_t sIn, size_t sOut)
{
    __shared__ float tile[32][33];
    const int z = blockIdx.z;
    in  += (size_t)z * sIn;
    out += (size_t)z * sOut;
    const int r0 = blockIdx.y * 32, c0 = blockIdx.x * 32;
    #pragma unroll
    for (int i = threadIdx.y; i < 32; i += 8)
        tile[i][threadIdx.x] = rna_tf32(in[(size_t)(r0 + i) * C + c0 + threadIdx.x]);
    __syncthreads();
    #pragma unroll
    for (int i = threadIdx.y; i < 32; i += 8)
        out[(size_t)(c0 + i) * R + r0 + threadIdx.x] = tile[threadIdx.x][i];
}

// ---- round images into scratch (tf32) ----
__global__ void round_copy_kernel(const float* __restrict__ in, float* __restrict__ out, size_t n4)
{
    const size_t i = (size_t)blockIdx.x * blockDim.x + threadIdx.x;
    if (i >= n4) return;
    float4 v = reinterpret_cast<const float4*>(in)[i];
    v.x = rna_tf32(v.x); v.y = rna_tf32(v.y); v.z = rna_tf32(v.z); v.w = rna_tf32(v.w);
    reinterpret_cast<float4*>(out)[i] = v;
}

__global__ void rownorm_kernel(const float* __restrict__ img, float* __restrict__ invn)
{
    const int m = blockIdx.x;
    const float* r = img + (size_t)m * DFEAT;
    const int tid = threadIdx.x;
    float s = 0.f;
    for (int k = tid; k < DFEAT; k += 256) { float x = r[k]; s = fmaf(x, x, s); }
    __shared__ float red[256];
    red[tid] = s; __syncthreads();
    for (int o = 128; o > 0; o >>= 1) { if (tid < o) red[tid] += red[tid + o]; __syncthreads(); }
    if (tid == 0) invn[m] = 1.f / fmaxf(sqrtf(red[0]), 1e-12f);
}

__global__ void ctx_init_kernel(const float* __restrict__ initMem, float* __restrict__ xctx)
{
    const size_t i = (size_t)blockIdx.x * blockDim.x + threadIdx.x;
    xctx[i] = rna_tf32(initMem[i & (CTX - 1)]);
}

template<bool ELU>
__global__ void small_linear_kernel(const float* __restrict__ in, const float* __restrict__ W,
                                    const float* __restrict__ bias, float* __restrict__ out)
{
    const int b = blockIdx.x;
    const int tid = threadIdx.x;
    __shared__ float x[CMD];
    for (int d = tid; d < CMD; d += 256) x[d] = in[b * CMD + d];
    __syncthreads();
    for (int j = tid; j < CMD; j += 256) {
        float acc = 0.f;
        #pragma unroll 4
        for (int k = 0; k < CMD; k++) acc = fmaf(x[k], W[(size_t)k * CMD + j], acc);
        acc += bias[j];
        if (ELU) acc = (acc > 0.f) ? acc : expm1f(acc);
        out[b * CMD + j] = acc;
    }
}

__global__ void text_cmd_kernel(const float* __restrict__ qcmd, const float* __restrict__ lstm,
                                const float* __restrict__ c2l_w, const float* __restrict__ c2l_b,
                                const int* __restrict__ qlen, float* __restrict__ cmd)
{
    const int b = blockIdx.x;
    const int tid = threadIdx.x;
    __shared__ float e[CMD];
    __shared__ float att[LQL];
    for (int d = tid; d < CMD; d += 256) e[d] = qcmd[b * CMD + d] * c2l_w[d];
    __syncthreads();
    if (tid < LQL) {
        const float* L = lstm + ((size_t)b * LQL + tid) * CMD;
        float acc = 0.f;
        for (int d = 0; d < CMD; d++) acc = fmaf(L[d], e[d], acc);
        acc += c2l_b[0];
        att[tid] = (tid >= qlen[b]) ? NEGV : acc;
    }
    __syncthreads();
    if (tid == 0) {
        float mx = -3.4e38f;
        for (int l = 0; l < LQL; l++) mx = fmaxf(mx, att[l]);
        float sum = 0.f;
        for (int l = 0; l < LQL; l++) { att[l] = expf(att[l] - mx); sum += att[l]; }
        const float inv = 1.f / sum;
        for (int l = 0; l < LQL; l++) att[l] *= inv;
    }
    __syncthreads();
    for (int d = tid; d < CMD; d += 256) {
        float acc = 0.f;
        #pragma unroll 4
        for (int l = 0; l < LQL; l++) acc = fmaf(att[l], lstm[((size_t)b * LQL + l) * CMD + d], acc);
        cmd[b * CMD + d] = acc;
    }
}

// masked row softmax (in place); stores prob rounded to tf32 (feeds msg MMA)
__global__ void attn_softmax_kernel(float* __restrict__ score, const int* __restrict__ entity_num)
{
    const int row = blockIdx.x;
    const int b = row >> 10;
    const int n = row & 1023;
    const int en = entity_num[b];
    float* s = score + (size_t)row * NENT;
    const bool rmask = (n >= en);
    const int tid = threadIdx.x;

    float v[4];
    float mx = -3.4e38f;
    #pragma unroll
    for (int j = 0; j < 4; j++) {
        const int m = tid + j * 256;
        float x = s[m];
        x = (rmask || m >= en) ? NEGV : x;
        v[j] = x;
        mx = fmaxf(mx, x);
    }
    __shared__ float red[256];
    red[tid] = mx; __syncthreads();
    for (int o = 128; o > 0; o >>= 1) { if (tid < o) red[tid] = fmaxf(red[tid], red[tid + o]); __syncthreads(); }
    mx = red[0];
    __syncthreads();

    float sum = 0.f;
    #pragma unroll
    for (int j = 0; j < 4; j++) { v[j] = expf(v[j] - mx); sum += v[j]; }
    red[tid] = sum; __syncthreads();
    for (int o = 128; o > 0; o >>= 1) { if (tid < o) red[tid] += red[tid + o]; __syncthreads(); }
    const float inv = 1.f / red[0];

    #pragma unroll
    for (int j = 0; j < 4; j++) s[tid + j * 256] = rna_tf32(v[j] * inv);
}

// ---------------- launch ----------------
template<typename T> static float* symaddr(T& sym) {
    void* p = nullptr;
    cudaGetSymbolAddress(&p, sym);
    return (float*)p;
}

extern "C" void kernel_launch(void* const* d_in, const int* in_sizes, int n_in,
                              void* d_out, int out_size)
{
    const float* images    = (const float*)d_in[0];
    const float* q_enc     = (const float*)d_in[1];
    const float* lstm      = (const float*)d_in[2];
    const int*   q_length  = (const int*)  d_in[3];
    const int*   ent_num   = (const int*)  d_in[4];
    const float* initKB_w  = (const float*)d_in[5];
    const float* initKB_b  = (const float*)d_in[6];
    const float* initMem   = (const float*)d_in[7];
    const float* qInput_w  = (const float*)d_in[8];
    const float* qInput_b  = (const float*)d_in[9];
    const float* qInput2_w = (const float*)d_in[10];
    const float* qInput2_b = (const float*)d_in[11];
    const float* c2l_w     = (const float*)d_in[12];
    const float* c2l_b     = (const float*)d_in[13];
    const float* pxl_w     = (const float*)d_in[14];
    const float* pxl_b     = (const float*)d_in[15];
    const float* pxc_w     = (const float*)d_in[16];
    const float* pxc_b     = (const float*)d_in[17];
    const float* qry_w     = (const float*)d_in[18];
    const float* qry_b     = (const float*)d_in[19];
    const float* key_w     = (const float*)d_in[20];
    const float* key_b     = (const float*)d_in[21];
    const float* val_w     = (const float*)d_in[22];
    const float* val_b     = (const float*)d_in[23];
    const float* pk_w      = (const float*)d_in[24];
    const float* pk_b      = (const float*)d_in[25];
    const float* pv_w      = (const float*)d_in[26];
    const float* pv_b      = (const float*)d_in[27];
    const float* mu_w      = (const float*)d_in[28];
    const float* mu_b      = (const float*)d_in[29];
    const float* ck_w      = (const float*)d_in[30];
    const float* ck_b      = (const float*)d_in[31];

    float* imgr  = symaddr(g_imgr);
    float* invn  = symaddr(g_invnorm);
    float* xloc  = symaddr(g_xloc);
    float* xctxA = symaddr(g_xctx0);
    float* xctxB = symaddr(g_xctx1);
    float* prjl  = symaddr(g_projloc);
    float* pp    = symaddr(g_pp);
    float* q     = symaddr(g_q);
    float* k     = symaddr(g_k);
    float* v     = symaddr(g_v);
    float* vT    = symaddr(g_vT);
    float* msg   = symaddr(g_msg);
    float* score = symaddr(g_score);
    float* qbase = symaddr(g_qbase);
    float* qcmd  = symaddr(g_qcmd);
    float* cmd   = symaddr(g_cmd);
    float* pkg   = symaddr(g_pkg);
    float* pvg   = symaddr(g_pvg);
    float* wIKB  = symaddr(g_wT_ikb);
    float* wPXL  = symaddr(g_wT_pxl);
    float* wPXC  = symaddr(g_wT_pxc);
    float* wQRY  = symaddr(g_wT_qry);
    float* wKEY  = symaddr(g_wT_key);
    float* wVAL  = symaddr(g_wT_val);
    float* wMU   = symaddr(g_wT_mu);
    float* wCK   = symaddr(g_wT_ck);

    const float scale = 0.044194173824159216f;   // 1/sqrt(512)
    const dim3 tdim(32, 8);
    const dim3 gridMain(CTX / BNm, MROWS / BMm, 1);      // (4, 256)
    const dim3 gridScore(NENT / BNm, NENT / BMm, BB);    // (8, 8, 32)
    const dim3 gridMsg(CTX / BNm, NENT / BMm, BB);       // (4, 8, 32)

    // weight transposes [K,N] -> [N,K] (+tf32 round)
    transpose_kernel<<<dim3(CTX/32, DFEAT/32, 1), tdim>>>(initKB_w, wIKB, DFEAT, CTX, 0, 0);
    transpose_kernel<<<dim3(CTX/32, CTX/32, 1),   tdim>>>(pxl_w,    wPXL, CTX,   CTX, 0, 0);
    transpose_kernel<<<dim3(CTX/32, CTX/32, 1),   tdim>>>(pxc_w,    wPXC, CTX,   CTX, 0, 0);
    transpose_kernel<<<dim3(CTX/32, 3*CTX/32, 1), tdim>>>(qry_w,    wQRY, 3*CTX, CTX, 0, 0);
    transpose_kernel<<<dim3(CTX/32, 3*CTX/32, 1), tdim>>>(key_w,    wKEY, 3*CTX, CTX, 0, 0);
    transpose_kernel<<<dim3(CTX/32, 3*CTX/32, 1), tdim>>>(val_w,    wVAL, 3*CTX, CTX, 0, 0);
    transpose_kernel<<<dim3(CTX/32, 2*CTX/32, 1), tdim>>>(mu_w,     wMU,  2*CTX, CTX, 0, 0);
    transpose_kernel<<<dim3(CTX/32, 2*CTX/32, 1), tdim>>>(ck_w,     wCK,  2*CTX, CTX, 0, 0);

    // setup
    {
        const size_t n4 = (size_t)MROWS * DFEAT / 4;
        round_copy_kernel<<<(unsigned)((n4 + 255) / 256), 256>>>(images, imgr, n4);
    }
    rownorm_kernel<<<MROWS, 256>>>(images, invn);
    ctx_init_kernel<<<(MROWS * CTX) / 256, 256>>>(initMem, xctxA);
    small_linear_kernel<true><<<BB, 256>>>(q_enc, qInput_w, qInput_b, qbase);

    // x_loc = normalize(images) @ initKB_w + b (norm as row scale, tf32-rounded out)
    gemm_mma<1,1,true><<<gridMain, 256>>>(
        imgr, nullptr, nullptr, wIKB, initKB_b, invn, xloc,
        DFEAT, DFEAT, DFEAT, CTX, 0, 0, 0, 1.f);

    float* xc = xctxA;
    float* xn = xctxB;
    for (int t = 0; t < TT; t++) {
        small_linear_kernel<false><<<BB, 256>>>(qbase, qInput2_w + (size_t)t * CMD * CMD,
                                                qInput2_b + (size_t)t * CMD, qcmd);
        text_cmd_kernel<<<BB, 256>>>(qcmd, lstm, c2l_w, c2l_b, q_length, cmd);
        small_linear_kernel<false><<<BB, 256>>>(cmd, pk_w, pk_b, pkg);
        small_linear_kernel<false><<<BB, 256>>>(cmd, pv_w, pv_b, pvg);

        // proj_loc = x_loc @ pxl + b (only consumed by pp's EPI3 -> no rounding)
        gemm_mma<1,0,false><<<gridMain, 256>>>(
            xloc, nullptr, nullptr, wPXL, pxl_b, nullptr, prjl,
            CTX, CTX, CTX, CTX, 0, 0, 0, 1.f);
        // pp = (x_ctx @ pxc + b) * proj_loc
        gemm_mma<1,3,true><<<gridMain, 256>>>(
            xc, nullptr, nullptr, wPXC, pxc_b, prjl, pp,
            CTX, CTX, CTX, CTX, 0, 0, 0, 1.f);

        // q/k/v over virtual concat [x_loc | x_ctx | pp]  (K=1536)
        gemm_mma<3,0,true><<<gridMain, 256>>>(
            xloc, xc, pp, wQRY, qry_b, nullptr, q,
            3*CTX, 0, 3*CTX, CTX, 0, 0, 0, 1.f);
        gemm_mma<3,2,true><<<gridMain, 256>>>(
            xloc, xc, pp, wKEY, key_b, pkg, k,
            3*CTX, 0, 3*CTX, CTX, 0, 0, 0, 1.f);
        gemm_mma<3,2,true><<<gridMain, 256>>>(
            xloc, xc, pp, wVAL, val_b, pvg, v,
            3*CTX, 0, 3*CTX, CTX, 0, 0, 0, 1.f);

        // score[b] = scale * q[b] @ k[b]^T  (k already [N,K] per batch)
        gemm_mma<1,0,false><<<gridScore, 256>>>(
            q, nullptr, nullptr, k, nullptr, nullptr, score,
            CTX, CTX, CTX, NENT,
            (size_t)NENT * CTX, (size_t)NENT * CTX, (size_t)NENT * NENT, scale);

        attn_softmax_kernel<<<MROWS, 256>>>(score, ent_num);

        // vT[b] = v[b]^T  ([1024,512] -> [512,1024], tf32-rounded)
        transpose_kernel<<<dim3(CTX/32, NENT/32, BB), tdim>>>(
            v, vT, NENT, CTX, (size_t)NENT * CTX, (size_t)CTX * NENT);

        // message[b] = prob[b] @ v[b]  (B = vT, K-major)
        gemm_mma<1,0,true><<<gridMsg, 256>>>(
            score, nullptr, nullptr, vT, nullptr, nullptr, msg,
            NENT, NENT, NENT, CTX,
            (size_t)NENT * NENT, (size_t)CTX * NENT, (size_t)NENT * CTX, 1.f);

        // x_ctx' = [x_ctx | message] @ mu + b
        gemm_mma<2,0,true><<<gridMain, 256>>>(
            xc, msg, nullptr, wMU, mu_b, nullptr, xn,
            2*CTX, 0, 2*CTX, CTX, 0, 0, 0, 1.f);
        float* tmp = xc; xc = xn; xn = tmp;
    }

    // out = [x_loc | x_ctx] @ ck + b
    gemm_mma<2,0,false><<<gridMain, 256>>>(
        xloc, xc, nullptr, wCK, ck_b, nullptr, (float*)d_out,
        2*CTX, 0, 2*CTX, CTX, 0, 0, 0, 1.f);
}

// round 5
// speedup vs baseline: 3.1503x; 1.1648x over previous
#include <cuda_runtime.h>
#include <math.h>
#include <stdint.h>

#define BB     32
#define NENT   1024
#define LQL    128
#define DFEAT  2112
#define CTX    512
#define CMD    512
#define TT     4
#define MROWS  (BB*NENT)
#define NEGV   (-1e30f)

// ---- mma.sync GEMM tiling ----
#define BMm 128
#define BNm 128
#define BKm 16
#define STAGES 4
#define SROW 20                         // smem row stride (floats); conflict-free
#define STAGE_F (2 * BMm * SROW)        // floats per stage (A + B) = 5120
#define TILE_F  (BMm * SROW)            // 2560
#define SMEM_DYN (STAGES * STAGE_F * 4) // 81920 bytes

// ---- scratch ----
__device__ float g_imgr   [(size_t)MROWS*DFEAT];
__device__ float g_invnorm[MROWS];
__device__ float g_xloc   [(size_t)MROWS*CTX];
__device__ float g_xctx0  [(size_t)MROWS*CTX];
__device__ float g_xctx1  [(size_t)MROWS*CTX];
__device__ float g_projloc[(size_t)MROWS*CTX];
__device__ float g_pp     [(size_t)MROWS*CTX];
__device__ float g_q      [(size_t)MROWS*CTX];
__device__ float g_k      [(size_t)MROWS*CTX];
__device__ float g_v      [(size_t)MROWS*CTX];
__device__ float g_vT     [(size_t)MROWS*CTX];
__device__ float g_msg    [(size_t)MROWS*CTX];
__device__ float g_qL     [(size_t)MROWS*CTX];
__device__ float g_kL     [(size_t)MROWS*CTX];
__device__ float g_vL     [(size_t)MROWS*CTX];
__device__ float g_score  [(size_t)BB*NENT*NENT];
__device__ float g_qbase  [BB*CMD];
__device__ float g_qcmd   [BB*CMD];
__device__ float g_cmd    [BB*CMD];
__device__ float g_pkg    [BB*CTX];
__device__ float g_pvg    [BB*CTX];
__device__ float g_wT_ikb[(size_t)CTX*DFEAT];
__device__ float g_wT_pxl[(size_t)CTX*CTX];
__device__ float g_wT_pxc[(size_t)CTX*CTX];
__device__ float g_wT_qry[(size_t)CTX*3*CTX];
__device__ float g_wT_key[(size_t)CTX*3*CTX];
__device__ float g_wT_val[(size_t)CTX*3*CTX];
__device__ float g_wT_mu [(size_t)CTX*2*CTX];
__device__ float g_wT_ck [(size_t)CTX*2*CTX];

__device__ __forceinline__ float rna_tf32(float f) {
    uint32_t r; asm("cvt.rna.tf32.f32 %0, %1;" : "=r"(r) : "f"(f));
    return __uint_as_float(r);
}
__device__ __forceinline__ uint32_t smem_u32(const void* p) {
    uint32_t a;
    asm("{ .reg .u64 t; cvta.to.shared.u64 t, %1; cvt.u32.u64 %0, t; }" : "=r"(a) : "l"(p));
    return a;
}
__device__ __forceinline__ void cp_async16(uint32_t saddr, const void* gptr) {
    asm volatile("cp.async.ca.shared.global [%0], [%1], 16;" :: "r"(saddr), "l"(gptr));
}
#define CP_COMMIT() asm volatile("cp.async.commit_group;" ::: "memory")
#define CP_WAIT2()  asm volatile("cp.async.wait_group 2;" ::: "memory")

__device__ __forceinline__ void mma_m16n8k8(float* d,
    uint32_t a0, uint32_t a1, uint32_t a2, uint32_t a3,
    uint32_t b0, uint32_t b1)
{
    asm volatile(
        "mma.sync.aligned.m16n8k8.row.col.f32.tf32.tf32.f32 "
        "{%0,%1,%2,%3}, {%4,%5,%6,%7}, {%8,%9}, {%0,%1,%2,%3};"
        : "+f"(d[0]), "+f"(d[1]), "+f"(d[2]), "+f"(d[3])
        : "r"(a0), "r"(a1), "r"(a2), "r"(a3), "r"(b0), "r"(b1));
}

// ---------------- tensor-core GEMM via mma.sync (tf32) ----------------
// C[M,N] = epi( A @ B^T [+ addC] ); A row-major [M,K] (virtual concat of up to
// 3 CTX-wide buffers), B K-major [N,K]. 4-stage cp.async pipeline.
// EPI 0: acc*alpha + bias[n]
// EPI 1: acc*extra[m] + bias[n]
// EPI 2: (acc+bias[n]) * extra[(m>>10)*CTX + n]
// EPI 3: (acc+bias[n]) * extra[m*ldc + n]
// ADD: acc += addC[m*ldc+n] before EPI.  RND: round result to tf32.
template<int NSRC, int EPI, bool RND, bool ADD>
__global__ __launch_bounds__(256, 2)
void gemm_mma(const float* __restrict__ A0, const float* __restrict__ A1,
              const float* __restrict__ A2, const float* __restrict__ Bt,
              const float* __restrict__ bias, const float* __restrict__ extra,
              const float* __restrict__ addC, float* __restrict__ C,
              int K, int lda, int ldb, int ldc,
              size_t sA, size_t sB, size_t sC, float alpha)
{
    extern __shared__ float smem[];
    const uint32_t sbase = smem_u32(smem);

    const int tid = threadIdx.x;
    const int z = blockIdx.z;
    const int m0 = blockIdx.y * BMm;
    const int n0 = blockIdx.x * BNm;
    const float* Abase = A0 + (size_t)z * sA;
    const float* Bbase = Bt + (size_t)z * sB;
    float* Cbase = C + (size_t)z * sC;

    const int wid = tid >> 5, lane = tid & 31;
    const int wm = (wid & 3) * 32;
    const int wn = (wid >> 2) * 64;
    const int gr = lane >> 2;
    const int gc = lane & 3;

    // producer coords: each thread copies 2 float4 per tile
    const int prow0 = tid >> 2;                 // 0..63
    const int pkq   = (tid & 3) * 4;            // k offset of float4

    float acc[2][8][4] = {};
    const int NCC = K / BKm;

    auto loadChunk = [&](int c, int st) {
        const int k0 = c * BKm;
        const float* Ap; int al, ak;
        if (NSRC == 1) { Ap = Abase; al = lda; ak = k0; }
        else {
            const int src = k0 >> 9;
            Ap = (src == 0) ? A0 : ((src == 1) ? A1 : A2);
            al = CTX; ak = k0 & (CTX - 1);
        }
        const uint32_t sa = sbase + (uint32_t)(st * STAGE_F) * 4;
        const uint32_t sb = sa + (uint32_t)TILE_F * 4;
        #pragma unroll
        for (int t = 0; t < 2; ++t) {
            const int row = prow0 + t * 64;
            cp_async16(sa + (uint32_t)(row * SROW + pkq) * 4,
                       Ap + (size_t)(m0 + row) * al + ak + pkq);
            cp_async16(sb + (uint32_t)(row * SROW + pkq) * 4,
                       Bbase + (size_t)(n0 + row) * ldb + k0 + pkq);
        }
        CP_COMMIT();
    };

    auto compute = [&](int st) {
        const float* SA = smem + st * STAGE_F;
        const float* SB = SA + TILE_F;
        #pragma unroll
        for (int kk = 0; kk < BKm; kk += 8) {
            uint32_t b[8][2];
            #pragma unroll
            for (int nt = 0; nt < 8; ++nt) {
                const int n = wn + nt * 8 + gr;
                b[nt][0] = __float_as_uint(SB[n * SROW + kk + gc]);
                b[nt][1] = __float_as_uint(SB[n * SROW + kk + 4 + gc]);
            }
            #pragma unroll
            for (int mt = 0; mt < 2; ++mt) {
                const int m = wm + mt * 16 + gr;
                const uint32_t a0 = __float_as_uint(SA[ m      * SROW + kk + gc]);
                const uint32_t a1 = __float_as_uint(SA[(m + 8) * SROW + kk + gc]);
                const uint32_t a2 = __float_as_uint(SA[ m      * SROW + kk + 4 + gc]);
                const uint32_t a3 = __float_as_uint(SA[(m + 8) * SROW + kk + 4 + gc]);
                #pragma unroll
                for (int nt = 0; nt < 8; ++nt)
                    mma_m16n8k8(acc[mt][nt], a0, a1, a2, a3, b[nt][0], b[nt][1]);
            }
        }
    };

    // prologue: fill STAGES-1 stages
    #pragma unroll
    for (int s = 0; s < STAGES - 1; ++s) {
        if (s < NCC) loadChunk(s, s);
        else CP_COMMIT();
    }
    for (int c = 0; c < NCC; ++c) {
        CP_WAIT2();                       // chunk c's copies complete
        __syncthreads();
        const int nc = c + STAGES - 1;
        if (nc < NCC) loadChunk(nc, nc & (STAGES - 1));
        else CP_COMMIT();
        compute(c & (STAGES - 1));
    }

    // ---- epilogue: direct per-lane float2 stores ----
    #pragma unroll
    for (int mt = 0; mt < 2; ++mt) {
        #pragma unroll
        for (int half = 0; half < 2; ++half) {
            const int m = m0 + wm + mt * 16 + gr + half * 8;
            const float rs = (EPI == 1) ? extra[m] : 0.f;
            #pragma unroll
            for (int nt = 0; nt < 8; ++nt) {
                const int n = n0 + wn + nt * 8 + gc * 2;
                float v0 = acc[mt][nt][half * 2 + 0];
                float v1 = acc[mt][nt][half * 2 + 1];
                if (ADD) {
                    const float2 ad = *reinterpret_cast<const float2*>(addC + (size_t)m * ldc + n);
                    v0 += ad.x; v1 += ad.y;
                }
                const float bb0 = bias ? bias[n]     : 0.f;
                const float bb1 = bias ? bias[n + 1] : 0.f;
                if (EPI == 0)      { v0 = v0 * alpha + bb0;  v1 = v1 * alpha + bb1; }
                else if (EPI == 1) { v0 = v0 * rs + bb0;     v1 = v1 * rs + bb1; }
                else if (EPI == 2) {
                    const float* g = extra + (size_t)(m >> 10) * CTX + n;
                    v0 = (v0 + bb0) * g[0];
                    v1 = (v1 + bb1) * g[1];
                } else {
                    const float* g = extra + (size_t)m * ldc + n;
                    v0 = (v0 + bb0) * g[0];
                    v1 = (v1 + bb1) * g[1];
                }
                if (RND) { v0 = rna_tf32(v0); v1 = rna_tf32(v1); }
                *reinterpret_cast<float2*>(Cbase + (size_t)m * ldc + n) = make_float2(v0, v1);
            }
        }
    }
}

// ---- transpose (+tf32 round): out[C,R] = rnd(in[R,C]^T), batched ----
__global__ void transpose_kernel(const float* __restrict__ in, float* __restrict__ out,
                                 int R, int C, size_t sIn, size_t sOut)
{
    __shared__ float tile[32][33];
    const int z = blockIdx.z;
    in  += (size_t)z * sIn;
    out += (size_t)z * sOut;
    const int r0 = blockIdx.y * 32, c0 = blockIdx.x * 32;
    #pragma unroll
    for (int i = threadIdx.y; i < 32; i += 8)
        tile[i][threadIdx.x] = rna_tf32(in[(size_t)(r0 + i) * C + c0 + threadIdx.x]);
    __syncthreads();
    #pragma unroll
    for (int i = threadIdx.y; i < 32; i += 8)
        out[(size_t)(c0 + i) * R + r0 + threadIdx.x] = tile[threadIdx.x][i];
}

__global__ void round_copy_kernel(const float* __restrict__ in, float* __restrict__ out, size_t n4)
{
    const size_t i = (size_t)blockIdx.x * blockDim.x + threadIdx.x;
    if (i >= n4) return;
    float4 v = reinterpret_cast<const float4*>(in)[i];
    v.x = rna_tf32(v.x); v.y = rna_tf32(v.y); v.z = rna_tf32(v.z); v.w = rna_tf32(v.w);
    reinterpret_cast<float4*>(out)[i] = v;
}

__global__ void rownorm_kernel(const float* __restrict__ img, float* __restrict__ invn)
{
    const int m = blockIdx.x;
    const float* r = img + (size_t)m * DFEAT;
    const int tid = threadIdx.x;
    float s = 0.f;
    for (int k = tid; k < DFEAT; k += 256) { float x = r[k]; s = fmaf(x, x, s); }
    __shared__ float red[256];
    red[tid] = s; __syncthreads();
    for (int o = 128; o > 0; o >>= 1) { if (tid < o) red[tid] += red[tid + o]; __syncthreads(); }
    if (tid == 0) invn[m] = 1.f / fmaxf(sqrtf(red[0]), 1e-12f);
}

__global__ void ctx_init_kernel(const float* __restrict__ initMem, float* __restrict__ xctx)
{
    const size_t i = (size_t)blockIdx.x * blockDim.x + threadIdx.x;
    xctx[i] = rna_tf32(initMem[i & (CTX - 1)]);
}

template<bool ELU>
__global__ void small_linear_kernel(const float* __restrict__ in, const float* __restrict__ W,
                                    const float* __restrict__ bias, float* __restrict__ out)
{
    const int b = blockIdx.x;
    const int tid = threadIdx.x;
    __shared__ float x[CMD];
    for (int d = tid; d < CMD; d += 256) x[d] = in[b * CMD + d];
    __syncthreads();
    for (int j = tid; j < CMD; j += 256) {
        float acc = 0.f;
        #pragma unroll 4
        for (int k = 0; k < CMD; k++) acc = fmaf(x[k], W[(size_t)k * CMD + j], acc);
        acc += bias[j];
        if (ELU) acc = (acc > 0.f) ? acc : expm1f(acc);
        out[b * CMD + j] = acc;
    }
}

__global__ void text_cmd_kernel(const float* __restrict__ qcmd, const float* __restrict__ lstm,
                                const float* __restrict__ c2l_w, const float* __restrict__ c2l_b,
                                const int* __restrict__ qlen, float* __restrict__ cmd)
{
    const int b = blockIdx.x;
    const int tid = threadIdx.x;
    __shared__ float e[CMD];
    __shared__ float att[LQL];
    for (int d = tid; d < CMD; d += 256) e[d] = qcmd[b * CMD + d] * c2l_w[d];
    __syncthreads();
    if (tid < LQL) {
        const float* L = lstm + ((size_t)b * LQL + tid) * CMD;
        float acc = 0.f;
        for (int d = 0; d < CMD; d++) acc = fmaf(L[d], e[d], acc);
        acc += c2l_b[0];
        att[tid] = (tid >= qlen[b]) ? NEGV : acc;
    }
    __syncthreads();
    if (tid == 0) {
        float mx = -3.4e38f;
        for (int l = 0; l < LQL; l++) mx = fmaxf(mx, att[l]);
        float sum = 0.f;
        for (int l = 0; l < LQL; l++) { att[l] = expf(att[l] - mx); sum += att[l]; }
        const float inv = 1.f / sum;
        for (int l = 0; l < LQL; l++) att[l] *= inv;
    }
    __syncthreads();
    for (int d = tid; d < CMD; d += 256) {
        float acc = 0.f;
        #pragma unroll 4
        for (int l = 0; l < LQL; l++) acc = fmaf(att[l], lstm[((size_t)b * LQL + l) * CMD + d], acc);
        cmd[b * CMD + d] = acc;
    }
}

__global__ void attn_softmax_kernel(float* __restrict__ score, const int* __restrict__ entity_num)
{
    const int row = blockIdx.x;
    const int b = row >> 10;
    const int n = row & 1023;
    const int en = entity_num[b];
    float* s = score + (size_t)row * NENT;
    const bool rmask = (n >= en);
    const int tid = threadIdx.x;

    float v[4];
    float mx = -3.4e38f;
    #pragma unroll
    for (int j = 0; j < 4; j++) {
        const int m = tid + j * 256;
        float x = s[m];
        x = (rmask || m >= en) ? NEGV : x;
        v[j] = x;
        mx = fmaxf(mx, x);
    }
    __shared__ float red[256];
    red[tid] = mx; __syncthreads();
    for (int o = 128; o > 0; o >>= 1) { if (tid < o) red[tid] = fmaxf(red[tid], red[tid + o]); __syncthreads(); }
    mx = red[0];
    __syncthreads();

    float sum = 0.f;
    #pragma unroll
    for (int j = 0; j < 4; j++) { v[j] = expf(v[j] - mx); sum += v[j]; }
    red[tid] = sum; __syncthreads();
    for (int o = 128; o > 0; o >>= 1) { if (tid < o) red[tid] += red[tid + o]; __syncthreads(); }
    const float inv = 1.f / red[0];

    #pragma unroll
    for (int j = 0; j < 4; j++) s[tid + j * 256] = rna_tf32(v[j] * inv);
}

// ---------------- launch ----------------
template<typename T> static float* symaddr(T& sym) {
    void* p = nullptr;
    cudaGetSymbolAddress(&p, sym);
    return (float*)p;
}

extern "C" void kernel_launch(void* const* d_in, const int* in_sizes, int n_in,
                              void* d_out, int out_size)
{
    const float* images    = (const float*)d_in[0];
    const float* q_enc     = (const float*)d_in[1];
    const float* lstm      = (const float*)d_in[2];
    const int*   q_length  = (const int*)  d_in[3];
    const int*   ent_num   = (const int*)  d_in[4];
    const float* initKB_w  = (const float*)d_in[5];
    const float* initKB_b  = (const float*)d_in[6];
    const float* initMem   = (const float*)d_in[7];
    const float* qInput_w  = (const float*)d_in[8];
    const float* qInput_b  = (const float*)d_in[9];
    const float* qInput2_w = (const float*)d_in[10];
    const float* qInput2_b = (const float*)d_in[11];
    const float* c2l_w     = (const float*)d_in[12];
    const float* c2l_b     = (const float*)d_in[13];
    const float* pxl_w     = (const float*)d_in[14];
    const float* pxl_b     = (const float*)d_in[15];
    const float* pxc_w     = (const float*)d_in[16];
    const float* pxc_b     = (const float*)d_in[17];
    const float* qry_w     = (const float*)d_in[18];
    const float* qry_b     = (const float*)d_in[19];
    const float* key_w     = (const float*)d_in[20];
    const float* key_b     = (const float*)d_in[21];
    const float* val_w     = (const float*)d_in[22];
    const float* val_b     = (const float*)d_in[23];
    const float* pk_w      = (const float*)d_in[24];
    const float* pk_b      = (const float*)d_in[25];
    const float* pv_w      = (const float*)d_in[26];
    const float* pv_b      = (const float*)d_in[27];
    const float* mu_w      = (const float*)d_in[28];
    const float* mu_b      = (const float*)d_in[29];
    const float* ck_w      = (const float*)d_in[30];
    const float* ck_b      = (const float*)d_in[31];

    float* imgr  = symaddr(g_imgr);
    float* invn  = symaddr(g_invnorm);
    float* xloc  = symaddr(g_xloc);
    float* xctxA = symaddr(g_xctx0);
    float* xctxB = symaddr(g_xctx1);
    float* prjl  = symaddr(g_projloc);
    float* pp    = symaddr(g_pp);
    float* q     = symaddr(g_q);
    float* k     = symaddr(g_k);
    float* v     = symaddr(g_v);
    float* vT    = symaddr(g_vT);
    float* msg   = symaddr(g_msg);
    float* qL    = symaddr(g_qL);
    float* kL    = symaddr(g_kL);
    float* vL    = symaddr(g_vL);
    float* score = symaddr(g_score);
    float* qbase = symaddr(g_qbase);
    float* qcmd  = symaddr(g_qcmd);
    float* cmd   = symaddr(g_cmd);
    float* pkg   = symaddr(g_pkg);
    float* pvg   = symaddr(g_pvg);
    float* wIKB  = symaddr(g_wT_ikb);
    float* wPXL  = symaddr(g_wT_pxl);
    float* wPXC  = symaddr(g_wT_pxc);
    float* wQRY  = symaddr(g_wT_qry);
    float* wKEY  = symaddr(g_wT_key);
    float* wVAL  = symaddr(g_wT_val);
    float* wMU   = symaddr(g_wT_mu);
    float* wCK   = symaddr(g_wT_ck);

    // opt-in to >48KB dynamic smem for every instantiation we launch
    cudaFuncSetAttribute(gemm_mma<1,0,false,false>, cudaFuncAttributeMaxDynamicSharedMemorySize, SMEM_DYN);
    cudaFuncSetAttribute(gemm_mma<1,1,true ,false>, cudaFuncAttributeMaxDynamicSharedMemorySize, SMEM_DYN);
    cudaFuncSetAttribute(gemm_mma<1,3,true ,false>, cudaFuncAttributeMaxDynamicSharedMemorySize, SMEM_DYN);
    cudaFuncSetAttribute(gemm_mma<1,0,true ,false>, cudaFuncAttributeMaxDynamicSharedMemorySize, SMEM_DYN);
    cudaFuncSetAttribute(gemm_mma<2,0,true ,true >, cudaFuncAttributeMaxDynamicSharedMemorySize, SMEM_DYN);
    cudaFuncSetAttribute(gemm_mma<2,2,true ,true >, cudaFuncAttributeMaxDynamicSharedMemorySize, SMEM_DYN);
    cudaFuncSetAttribute(gemm_mma<2,0,true ,false>, cudaFuncAttributeMaxDynamicSharedMemorySize, SMEM_DYN);
    cudaFuncSetAttribute(gemm_mma<2,0,false,false>, cudaFuncAttributeMaxDynamicSharedMemorySize, SMEM_DYN);

    const float scale = 0.044194173824159216f;   // 1/sqrt(512)
    const dim3 tdim(32, 8);
    const dim3 gridMain(CTX / BNm, MROWS / BMm, 1);      // (4, 256)
    const dim3 gridScore(NENT / BNm, NENT / BMm, BB);    // (8, 8, 32)
    const dim3 gridMsg(CTX / BNm, NENT / BMm, BB);       // (4, 8, 32)

    // weight transposes [K,N] -> [N,K] (+tf32 round)
    transpose_kernel<<<dim3(CTX/32, DFEAT/32, 1), tdim>>>(initKB_w, wIKB, DFEAT, CTX, 0, 0);
    transpose_kernel<<<dim3(CTX/32, CTX/32, 1),   tdim>>>(pxl_w,    wPXL, CTX,   CTX, 0, 0);
    transpose_kernel<<<dim3(CTX/32, CTX/32, 1),   tdim>>>(pxc_w,    wPXC, CTX,   CTX, 0, 0);
    transpose_kernel<<<dim3(CTX/32, 3*CTX/32, 1), tdim>>>(qry_w,    wQRY, 3*CTX, CTX, 0, 0);
    transpose_kernel<<<dim3(CTX/32, 3*CTX/32, 1), tdim>>>(key_w,    wKEY, 3*CTX, CTX, 0, 0);
    transpose_kernel<<<dim3(CTX/32, 3*CTX/32, 1), tdim>>>(val_w,    wVAL, 3*CTX, CTX, 0, 0);
    transpose_kernel<<<dim3(CTX/32, 2*CTX/32, 1), tdim>>>(mu_w,     wMU,  2*CTX, CTX, 0, 0);
    transpose_kernel<<<dim3(CTX/32, 2*CTX/32, 1), tdim>>>(ck_w,     wCK,  2*CTX, CTX, 0, 0);

    // setup
    {
        const size_t n4 = (size_t)MROWS * DFEAT / 4;
        round_copy_kernel<<<(unsigned)((n4 + 255) / 256), 256>>>(images, imgr, n4);
    }
    rownorm_kernel<<<MROWS, 256>>>(images, invn);
    ctx_init_kernel<<<(MROWS * CTX) / 256, 256>>>(initMem, xctxA);
    small_linear_kernel<true><<<BB, 256>>>(q_enc, qInput_w, qInput_b, qbase);

    // x_loc = normalize(images) @ initKB_w + b (norm as row scale, tf32-rounded out)
    gemm_mma<1,1,true,false><<<gridMain, 256, SMEM_DYN>>>(
        imgr, nullptr, nullptr, wIKB, initKB_b, invn, nullptr, xloc,
        DFEAT, DFEAT, DFEAT, CTX, 0, 0, 0, 1.f);

    // ---- iteration-invariant hoists ----
    // proj_loc = x_loc @ pxl + b (consumed only as elementwise gate)
    gemm_mma<1,0,false,false><<<gridMain, 256, SMEM_DYN>>>(
        xloc, nullptr, nullptr, wPXL, pxl_b, nullptr, nullptr, prjl,
        CTX, CTX, CTX, CTX, 0, 0, 0, 1.f);
    // partial q/k/v over the constant x_loc third (K rows 0..511 of W)
    gemm_mma<1,0,false,false><<<gridMain, 256, SMEM_DYN>>>(
        xloc, nullptr, nullptr, wQRY, nullptr, nullptr, nullptr, qL,
        CTX, CTX, 3*CTX, CTX, 0, 0, 0, 1.f);
    gemm_mma<1,0,false,false><<<gridMain, 256, SMEM_DYN>>>(
        xloc, nullptr, nullptr, wKEY, nullptr, nullptr, nullptr, kL,
        CTX, CTX, 3*CTX, CTX, 0, 0, 0, 1.f);
    gemm_mma<1,0,false,false><<<gridMain, 256, SMEM_DYN>>>(
        xloc, nullptr, nullptr, wVAL, nullptr, nullptr, nullptr, vL,
        CTX, CTX, 3*CTX, CTX, 0, 0, 0, 1.f);

    float* xc = xctxA;
    float* xn = xctxB;
    for (int t = 0; t < TT; t++) {
        small_linear_kernel<false><<<BB, 256>>>(qbase, qInput2_w + (size_t)t * CMD * CMD,
                                                qInput2_b + (size_t)t * CMD, qcmd);
        text_cmd_kernel<<<BB, 256>>>(qcmd, lstm, c2l_w, c2l_b, q_length, cmd);
        small_linear_kernel<false><<<BB, 256>>>(cmd, pk_w, pk_b, pkg);
        small_linear_kernel<false><<<BB, 256>>>(cmd, pv_w, pv_b, pvg);

        // pp = (x_ctx @ pxc + b) * proj_loc
        gemm_mma<1,3,true,false><<<gridMain, 256, SMEM_DYN>>>(
            xc, nullptr, nullptr, wPXC, pxc_b, prjl, nullptr, pp,
            CTX, CTX, CTX, CTX, 0, 0, 0, 1.f);

        // q/k/v: K=1024 over [x_ctx | pp] + precomputed x_loc partial
        // (W rows 512..1535, i.e. column offset 512 in the K-major [N,1536] matrix)
        gemm_mma<2,0,true,true><<<gridMain, 256, SMEM_DYN>>>(
            xc, pp, nullptr, wQRY + CTX, qry_b, nullptr, qL, q,
            2*CTX, 0, 3*CTX, CTX, 0, 0, 0, 1.f);
        gemm_mma<2,2,true,true><<<gridMain, 256, SMEM_DYN>>>(
            xc, pp, nullptr, wKEY + CTX, key_b, pkg, kL, k,
            2*CTX, 0, 3*CTX, CTX, 0, 0, 0, 1.f);
        gemm_mma<2,2,true,true><<<gridMain, 256, SMEM_DYN>>>(
            xc, pp, nullptr, wVAL + CTX, val_b, pvg, vL, v,
            2*CTX, 0, 3*CTX, CTX, 0, 0, 0, 1.f);

        // score[b] = scale * q[b] @ k[b]^T
        gemm_mma<1,0,false,false><<<gridScore, 256, SMEM_DYN>>>(
            q, nullptr, nullptr, k, nullptr, nullptr, nullptr, score,
            CTX, CTX, CTX, NENT,
            (size_t)NENT * CTX, (size_t)NENT * CTX, (size_t)NENT * NENT, scale);

        attn_softmax_kernel<<<MROWS, 256>>>(score, ent_num);

        // vT[b] = v[b]^T (tf32-rounded)
        transpose_kernel<<<dim3(CTX/32, NENT/32, BB), tdim>>>(
            v, vT, NENT, CTX, (size_t)NENT * CTX, (size_t)CTX * NENT);

        // message[b] = prob[b] @ v[b]
        gemm_mma<1,0,true,false><<<gridMsg, 256, SMEM_DYN>>>(
            score, nullptr, nullptr, vT, nullptr, nullptr, nullptr, msg,
            NENT, NENT, NENT, CTX,
            (size_t)NENT * NENT, (size_t)CTX * NENT, (size_t)NENT * CTX, 1.f);

        // x_ctx' = [x_ctx | message] @ mu + b
        gemm_mma<2,0,true,false><<<gridMain, 256, SMEM_DYN>>>(
            xc, msg, nullptr, wMU, mu_b, nullptr, nullptr, xn,
            2*CTX, 0, 2*CTX, CTX, 0, 0, 0, 1.f);
        float* tmp = xc; xc = xn; xn = tmp;
    }

    // out = [x_loc | x_ctx] @ ck + b
    gemm_mma<2,0,false,false><<<gridMain, 256, SMEM_DYN>>>(
        xloc, xc, nullptr, wCK, ck_b, nullptr, nullptr, (float*)d_out,
        2*CTX, 0, 2*CTX, CTX, 0, 0, 0, 1.f);
}

// round 6
// speedup vs baseline: 3.3373x; 1.0594x over previous
#include <cuda_runtime.h>
#include <math.h>
#include <stdint.h>

#define BB     32
#define NENT   1024
#define LQL    128
#define DFEAT  2112
#define CTX    512
#define CMD    512
#define TT     4
#define MROWS  (BB*NENT)
#define NEGV   (-1e30f)

// ---- mma.sync GEMM tiling ----
#define BMm 128
#define BNm 128
#define BKm 16
#define STAGES 4
#define SROW 20                         // smem row stride (floats); conflict-free
#define STAGE_F (2 * BMm * SROW)        // floats per stage (A + B) = 5120
#define TILE_F  (BMm * SROW)            // 2560
#define SMEM_DYN (STAGES * STAGE_F * 4) // 81920 bytes

// ---- scratch ----
__device__ float g_imgr   [(size_t)MROWS*DFEAT];
__device__ float g_invnorm[MROWS];
__device__ float g_xloc   [(size_t)MROWS*CTX];
__device__ float g_xctx0  [(size_t)MROWS*CTX];
__device__ float g_xctx1  [(size_t)MROWS*CTX];
__device__ float g_projloc[(size_t)MROWS*CTX];
__device__ float g_pp     [(size_t)MROWS*CTX];
__device__ float g_q      [(size_t)MROWS*CTX];
__device__ float g_k      [(size_t)MROWS*CTX];
__device__ float g_v      [(size_t)MROWS*CTX];
__device__ float g_vT     [(size_t)MROWS*CTX];
__device__ float g_msg    [(size_t)MROWS*CTX];
__device__ float g_qL     [(size_t)MROWS*CTX];
__device__ float g_kL     [(size_t)MROWS*CTX];
__device__ float g_vL     [(size_t)MROWS*CTX];
__device__ float g_score  [(size_t)BB*NENT*NENT];
__device__ float g_qbase  [BB*CMD];
__device__ float g_qcmd   [BB*CMD];
__device__ float g_cmd    [BB*CMD];
__device__ float g_pkg    [BB*CTX];
__device__ float g_pvg    [BB*CTX];
__device__ float g_wT_ikb[(size_t)CTX*DFEAT];
__device__ float g_wT_pxl[(size_t)CTX*CTX];
__device__ float g_wT_pxc[(size_t)CTX*CTX];
__device__ float g_wT_qry[(size_t)CTX*3*CTX];
__device__ float g_wT_key[(size_t)CTX*3*CTX];
__device__ float g_wT_val[(size_t)CTX*3*CTX];
__device__ float g_wT_mu [(size_t)CTX*2*CTX];
__device__ float g_wT_ck [(size_t)CTX*2*CTX];

__device__ __forceinline__ float rna_tf32(float f) {
    uint32_t r; asm("cvt.rna.tf32.f32 %0, %1;" : "=r"(r) : "f"(f));
    return __uint_as_float(r);
}
__device__ __forceinline__ uint32_t smem_u32(const void* p) {
    uint32_t a;
    asm("{ .reg .u64 t; cvta.to.shared.u64 t, %1; cvt.u32.u64 %0, t; }" : "=r"(a) : "l"(p));
    return a;
}
__device__ __forceinline__ void cp_async16(uint32_t saddr, const void* gptr) {
    asm volatile("cp.async.ca.shared.global [%0], [%1], 16;" :: "r"(saddr), "l"(gptr));
}
#define CP_COMMIT() asm volatile("cp.async.commit_group;" ::: "memory")
#define CP_WAIT2()  asm volatile("cp.async.wait_group 2;" ::: "memory")

__device__ __forceinline__ void mma_m16n8k8(float* d,
    uint32_t a0, uint32_t a1, uint32_t a2, uint32_t a3,
    uint32_t b0, uint32_t b1)
{
    asm volatile(
        "mma.sync.aligned.m16n8k8.row.col.f32.tf32.tf32.f32 "
        "{%0,%1,%2,%3}, {%4,%5,%6,%7}, {%8,%9}, {%0,%1,%2,%3};"
        : "+f"(d[0]), "+f"(d[1]), "+f"(d[2]), "+f"(d[3])
        : "r"(a0), "r"(a1), "r"(a2), "r"(a3), "r"(b0), "r"(b1));
}

// ---------------- tensor-core GEMM via mma.sync (tf32) ----------------
// C[M,N] = epi( A @ B^T [+ addC] ); A row-major [M,K] (virtual concat of up to
// 3 CTX-wide buffers), B K-major [N,K]. 4-stage cp.async pipeline.
// EPI 0: acc*alpha + bias[n]
// EPI 1: acc*extra[m] + bias[n]
// EPI 2: (acc+bias[n]) * extra[(m>>10)*CTX + n]
// EPI 3: (acc+bias[n]) * extra[m*ldc + n]
// ADD: acc += addC[m*ldc+n] before EPI.  RND: round result to tf32.
// MASK 0: none. 1 (score): skip tile if m0>=en || n0>=en.
//      2 (message): skip tile if m0>=en; truncate K at ceil(en/BKm)*BKm.
template<int NSRC, int EPI, bool RND, bool ADD, int MASK>
__global__ __launch_bounds__(256, 2)
void gemm_mma(const float* __restrict__ A0, const float* __restrict__ A1,
              const float* __restrict__ A2, const float* __restrict__ Bt,
              const float* __restrict__ bias, const float* __restrict__ extra,
              const float* __restrict__ addC, const int* __restrict__ ennum,
              float* __restrict__ C,
              int K, int lda, int ldb, int ldc,
              size_t sA, size_t sB, size_t sC, float alpha)
{
    extern __shared__ float smem[];
    const uint32_t sbase = smem_u32(smem);

    const int tid = threadIdx.x;
    const int z = blockIdx.z;
    const int m0 = blockIdx.y * BMm;
    const int n0 = blockIdx.x * BNm;

    int Keff = K;
    if (MASK != 0) {
        const int en = ennum[z];
        if (m0 >= en) return;                       // block-uniform exit
        if (MASK == 1 && n0 >= en) return;
        if (MASK == 2) { const int kc = ((en + BKm - 1) / BKm) * BKm; Keff = kc < K ? kc : K; }
    }

    const float* Abase = A0 + (size_t)z * sA;
    const float* Bbase = Bt + (size_t)z * sB;
    float* Cbase = C + (size_t)z * sC;

    const int wid = tid >> 5, lane = tid & 31;
    const int wm = (wid & 3) * 32;
    const int wn = (wid >> 2) * 64;
    const int gr = lane >> 2;
    const int gc = lane & 3;

    const int prow0 = tid >> 2;                 // 0..63
    const int pkq   = (tid & 3) * 4;            // k offset of float4

    float acc[2][8][4] = {};
    const int NCC = Keff / BKm;

    auto loadChunk = [&](int c, int st) {
        const int k0 = c * BKm;
        const float* Ap; int al, ak;
        if (NSRC == 1) { Ap = Abase; al = lda; ak = k0; }
        else {
            const int src = k0 >> 9;
            Ap = (src == 0) ? A0 : ((src == 1) ? A1 : A2);
            al = CTX; ak = k0 & (CTX - 1);
        }
        const uint32_t sa = sbase + (uint32_t)(st * STAGE_F) * 4;
        const uint32_t sb = sa + (uint32_t)TILE_F * 4;
        #pragma unroll
        for (int t = 0; t < 2; ++t) {
            const int row = prow0 + t * 64;
            cp_async16(sa + (uint32_t)(row * SROW + pkq) * 4,
                       Ap + (size_t)(m0 + row) * al + ak + pkq);
            cp_async16(sb + (uint32_t)(row * SROW + pkq) * 4,
                       Bbase + (size_t)(n0 + row) * ldb + k0 + pkq);
        }
        CP_COMMIT();
    };

    auto compute = [&](int st) {
        const float* SA = smem + st * STAGE_F;
        const float* SB = SA + TILE_F;
        #pragma unroll
        for (int kk = 0; kk < BKm; kk += 8) {
            uint32_t b[8][2];
            #pragma unroll
            for (int nt = 0; nt < 8; ++nt) {
                const int n = wn + nt * 8 + gr;
                b[nt][0] = __float_as_uint(SB[n * SROW + kk + gc]);
                b[nt][1] = __float_as_uint(SB[n * SROW + kk + 4 + gc]);
            }
            #pragma unroll
            for (int mt = 0; mt < 2; ++mt) {
                const int m = wm + mt * 16 + gr;
                const uint32_t a0 = __float_as_uint(SA[ m      * SROW + kk + gc]);
                const uint32_t a1 = __float_as_uint(SA[(m + 8) * SROW + kk + gc]);
                const uint32_t a2 = __float_as_uint(SA[ m      * SROW + kk + 4 + gc]);
                const uint32_t a3 = __float_as_uint(SA[(m + 8) * SROW + kk + 4 + gc]);
                #pragma unroll
                for (int nt = 0; nt < 8; ++nt)
                    mma_m16n8k8(acc[mt][nt], a0, a1, a2, a3, b[nt][0], b[nt][1]);
            }
        }
    };

    #pragma unroll
    for (int s = 0; s < STAGES - 1; ++s) {
        if (s < NCC) loadChunk(s, s);
        else CP_COMMIT();
    }
    for (int c = 0; c < NCC; ++c) {
        CP_WAIT2();
        __syncthreads();
        const int nc = c + STAGES - 1;
        if (nc < NCC) loadChunk(nc, nc & (STAGES - 1));
        else CP_COMMIT();
        compute(c & (STAGES - 1));
    }

    // ---- epilogue ----
    #pragma unroll
    for (int mt = 0; mt < 2; ++mt) {
        #pragma unroll
        for (int half = 0; half < 2; ++half) {
            const int m = m0 + wm + mt * 16 + gr + half * 8;
            const float rs = (EPI == 1) ? extra[m] : 0.f;
            #pragma unroll
            for (int nt = 0; nt < 8; ++nt) {
                const int n = n0 + wn + nt * 8 + gc * 2;
                float v0 = acc[mt][nt][half * 2 + 0];
                float v1 = acc[mt][nt][half * 2 + 1];
                if (ADD) {
                    const float2 ad = *reinterpret_cast<const float2*>(addC + (size_t)m * ldc + n);
                    v0 += ad.x; v1 += ad.y;
                }
                const float bb0 = bias ? bias[n]     : 0.f;
                const float bb1 = bias ? bias[n + 1] : 0.f;
                if (EPI == 0)      { v0 = v0 * alpha + bb0;  v1 = v1 * alpha + bb1; }
                else if (EPI == 1) { v0 = v0 * rs + bb0;     v1 = v1 * rs + bb1; }
                else if (EPI == 2) {
                    const float* g = extra + (size_t)(m >> 10) * CTX + n;
                    v0 = (v0 + bb0) * g[0];
                    v1 = (v1 + bb1) * g[1];
                } else {
                    const float* g = extra + (size_t)m * ldc + n;
                    v0 = (v0 + bb0) * g[0];
                    v1 = (v1 + bb1) * g[1];
                }
                if (RND) { v0 = rna_tf32(v0); v1 = rna_tf32(v1); }
                *reinterpret_cast<float2*>(Cbase + (size_t)m * ldc + n) = make_float2(v0, v1);
            }
        }
    }
}

// ---- masked-row message fill: msg[b, m>=en, :] = mean over rows of v[b] ----
__global__ void msg_fill_kernel(const float* __restrict__ v, const int* __restrict__ ennum,
                                float* __restrict__ msg)
{
    const int b = blockIdx.y;
    const int d = blockIdx.x * 256 + threadIdx.x;   // column 0..511
    const int en = ennum[b];
    if (en >= NENT) return;
    const float* vb = v + (size_t)b * NENT * CTX + d;
    float s = 0.f;
    #pragma unroll 4
    for (int kk = 0; kk < NENT; ++kk) s += vb[(size_t)kk * CTX];
    const float mean = rna_tf32(s * (1.f / NENT));
    float* mb = msg + (size_t)b * NENT * CTX + d;
    for (int m = en; m < NENT; ++m) mb[(size_t)m * CTX] = mean;
}

// ---- transpose (+tf32 round): out[C,R] = rnd(in[R,C]^T), batched ----
__global__ void transpose_kernel(const float* __restrict__ in, float* __restrict__ out,
                                 int R, int C, size_t sIn, size_t sOut)
{
    __shared__ float tile[32][33];
    const int z = blockIdx.z;
    in  += (size_t)z * sIn;
    out += (size_t)z * sOut;
    const int r0 = blockIdx.y * 32, c0 = blockIdx.x * 32;
    #pragma unroll
    for (int i = threadIdx.y; i < 32; i += 8)
        tile[i][threadIdx.x] = rna_tf32(in[(size_t)(r0 + i) * C + c0 + threadIdx.x]);
    __syncthreads();
    #pragma unroll
    for (int i = threadIdx.y; i < 32; i += 8)
        out[(size_t)(c0 + i) * R + r0 + threadIdx.x] = tile[threadIdx.x][i];
}

__global__ void round_copy_kernel(const float* __restrict__ in, float* __restrict__ out, size_t n4)
{
    const size_t i = (size_t)blockIdx.x * blockDim.x + threadIdx.x;
    if (i >= n4) return;
    float4 v = reinterpret_cast<const float4*>(in)[i];
    v.x = rna_tf32(v.x); v.y = rna_tf32(v.y); v.z = rna_tf32(v.z); v.w = rna_tf32(v.w);
    reinterpret_cast<float4*>(out)[i] = v;
}

__global__ void rownorm_kernel(const float* __restrict__ img, float* __restrict__ invn)
{
    const int m = blockIdx.x;
    const float* r = img + (size_t)m * DFEAT;
    const int tid = threadIdx.x;
    float s = 0.f;
    for (int k = tid; k < DFEAT; k += 256) { float x = r[k]; s = fmaf(x, x, s); }
    __shared__ float red[256];
    red[tid] = s; __syncthreads();
    for (int o = 128; o > 0; o >>= 1) { if (tid < o) red[tid] += red[tid + o]; __syncthreads(); }
    if (tid == 0) invn[m] = 1.f / fmaxf(sqrtf(red[0]), 1e-12f);
}

__global__ void ctx_init_kernel(const float* __restrict__ initMem, float* __restrict__ xctx)
{
    const size_t i = (size_t)blockIdx.x * blockDim.x + threadIdx.x;
    xctx[i] = rna_tf32(initMem[i & (CTX - 1)]);
}

template<bool ELU>
__global__ void small_linear_kernel(const float* __restrict__ in, const float* __restrict__ W,
                                    const float* __restrict__ bias, float* __restrict__ out)
{
    const int b = blockIdx.x;
    const int tid = threadIdx.x;
    __shared__ float x[CMD];
    for (int d = tid; d < CMD; d += 256) x[d] = in[b * CMD + d];
    __syncthreads();
    for (int j = tid; j < CMD; j += 256) {
        float acc = 0.f;
        #pragma unroll 4
        for (int k = 0; k < CMD; k++) acc = fmaf(x[k], W[(size_t)k * CMD + j], acc);
        acc += bias[j];
        if (ELU) acc = (acc > 0.f) ? acc : expm1f(acc);
        out[b * CMD + j] = acc;
    }
}

__global__ void text_cmd_kernel(const float* __restrict__ qcmd, const float* __restrict__ lstm,
                                const float* __restrict__ c2l_w, const float* __restrict__ c2l_b,
                                const int* __restrict__ qlen, float* __restrict__ cmd)
{
    const int b = blockIdx.x;
    const int tid = threadIdx.x;
    __shared__ float e[CMD];
    __shared__ float att[LQL];
    for (int d = tid; d < CMD; d += 256) e[d] = qcmd[b * CMD + d] * c2l_w[d];
    __syncthreads();
    if (tid < LQL) {
        const float* L = lstm + ((size_t)b * LQL + tid) * CMD;
        float acc = 0.f;
        for (int d = 0; d < CMD; d++) acc = fmaf(L[d], e[d], acc);
        acc += c2l_b[0];
        att[tid] = (tid >= qlen[b]) ? NEGV : acc;
    }
    __syncthreads();
    if (tid == 0) {
        float mx = -3.4e38f;
        for (int l = 0; l < LQL; l++) mx = fmaxf(mx, att[l]);
        float sum = 0.f;
        for (int l = 0; l < LQL; l++) { att[l] = expf(att[l] - mx); sum += att[l]; }
        const float inv = 1.f / sum;
        for (int l = 0; l < LQL; l++) att[l] *= inv;
    }
    __syncthreads();
    for (int d = tid; d < CMD; d += 256) {
        float acc = 0.f;
        #pragma unroll 4
        for (int l = 0; l < LQL; l++) acc = fmaf(att[l], lstm[((size_t)b * LQL + l) * CMD + d], acc);
        cmd[b * CMD + d] = acc;
    }
}

// masked row softmax (in place); skips fully-masked rows (msg_fill handles them)
__global__ void attn_softmax_kernel(float* __restrict__ score, const int* __restrict__ entity_num)
{
    const int row = blockIdx.x;
    const int b = row >> 10;
    const int n = row & 1023;
    const int en = entity_num[b];
    if (n >= en) return;                 // masked row: never read downstream
    float* s = score + (size_t)row * NENT;
    const int tid = threadIdx.x;

    float v[4];
    float mx = -3.4e38f;
    #pragma unroll
    for (int j = 0; j < 4; j++) {
        const int m = tid + j * 256;
        float x = s[m];
        x = (m >= en) ? NEGV : x;
        v[j] = x;
        mx = fmaxf(mx, x);
    }
    __shared__ float red[256];
    red[tid] = mx; __syncthreads();
    for (int o = 128; o > 0; o >>= 1) { if (tid < o) red[tid] = fmaxf(red[tid], red[tid + o]); __syncthreads(); }
    mx = red[0];
    __syncthreads();

    float sum = 0.f;
    #pragma unroll
    for (int j = 0; j < 4; j++) { v[j] = expf(v[j] - mx); sum += v[j]; }
    red[tid] = sum; __syncthreads();
    for (int o = 128; o > 0; o >>= 1) { if (tid < o) red[tid] += red[tid + o]; __syncthreads(); }
    const float inv = 1.f / red[0];

    #pragma unroll
    for (int j = 0; j < 4; j++) s[tid + j * 256] = rna_tf32(v[j] * inv);
}

// ---------------- launch ----------------
template<typename T> static float* symaddr(T& sym) {
    void* p = nullptr;
    cudaGetSymbolAddress(&p, sym);
    return (float*)p;
}

extern "C" void kernel_launch(void* const* d_in, const int* in_sizes, int n_in,
                              void* d_out, int out_size)
{
    const float* images    = (const float*)d_in[0];
    const float* q_enc     = (const float*)d_in[1];
    const float* lstm      = (const float*)d_in[2];
    const int*   q_length  = (const int*)  d_in[3];
    const int*   ent_num   = (const int*)  d_in[4];
    const float* initKB_w  = (const float*)d_in[5];
    const float* initKB_b  = (const float*)d_in[6];
    const float* initMem   = (const float*)d_in[7];
    const float* qInput_w  = (const float*)d_in[8];
    const float* qInput_b  = (const float*)d_in[9];
    const float* qInput2_w = (const float*)d_in[10];
    const float* qInput2_b = (const float*)d_in[11];
    const float* c2l_w     = (const float*)d_in[12];
    const float* c2l_b     = (const float*)d_in[13];
    const float* pxl_w     = (const float*)d_in[14];
    const float* pxl_b     = (const float*)d_in[15];
    const float* pxc_w     = (const float*)d_in[16];
    const float* pxc_b     = (const float*)d_in[17];
    const float* qry_w     = (const float*)d_in[18];
    const float* qry_b     = (const float*)d_in[19];
    const float* key_w     = (const float*)d_in[20];
    const float* key_b     = (const float*)d_in[21];
    const float* val_w     = (const float*)d_in[22];
    const float* val_b     = (const float*)d_in[23];
    const float* pk_w      = (const float*)d_in[24];
    const float* pk_b      = (const float*)d_in[25];
    const float* pv_w      = (const float*)d_in[26];
    const float* pv_b      = (const float*)d_in[27];
    const float* mu_w      = (const float*)d_in[28];
    const float* mu_b      = (const float*)d_in[29];
    const float* ck_w      = (const float*)d_in[30];
    const float* ck_b      = (const float*)d_in[31];

    float* imgr  = symaddr(g_imgr);
    float* invn  = symaddr(g_invnorm);
    float* xloc  = symaddr(g_xloc);
    float* xctxA = symaddr(g_xctx0);
    float* xctxB = symaddr(g_xctx1);
    float* prjl  = symaddr(g_projloc);
    float* pp    = symaddr(g_pp);
    float* q     = symaddr(g_q);
    float* k     = symaddr(g_k);
    float* v     = symaddr(g_v);
    float* vT    = symaddr(g_vT);
    float* msg   = symaddr(g_msg);
    float* qL    = symaddr(g_qL);
    float* kL    = symaddr(g_kL);
    float* vL    = symaddr(g_vL);
    float* score = symaddr(g_score);
    float* qbase = symaddr(g_qbase);
    float* qcmd  = symaddr(g_qcmd);
    float* cmd   = symaddr(g_cmd);
    float* pkg   = symaddr(g_pkg);
    float* pvg   = symaddr(g_pvg);
    float* wIKB  = symaddr(g_wT_ikb);
    float* wPXL  = symaddr(g_wT_pxl);
    float* wPXC  = symaddr(g_wT_pxc);
    float* wQRY  = symaddr(g_wT_qry);
    float* wKEY  = symaddr(g_wT_key);
    float* wVAL  = symaddr(g_wT_val);
    float* wMU   = symaddr(g_wT_mu);
    float* wCK   = symaddr(g_wT_ck);

    cudaFuncSetAttribute(gemm_mma<1,0,false,false,0>, cudaFuncAttributeMaxDynamicSharedMemorySize, SMEM_DYN);
    cudaFuncSetAttribute(gemm_mma<1,1,true ,false,0>, cudaFuncAttributeMaxDynamicSharedMemorySize, SMEM_DYN);
    cudaFuncSetAttribute(gemm_mma<1,3,true ,false,0>, cudaFuncAttributeMaxDynamicSharedMemorySize, SMEM_DYN);
    cudaFuncSetAttribute(gemm_mma<1,0,false,false,1>, cudaFuncAttributeMaxDynamicSharedMemorySize, SMEM_DYN);
    cudaFuncSetAttribute(gemm_mma<1,0,true ,false,2>, cudaFuncAttributeMaxDynamicSharedMemorySize, SMEM_DYN);
    cudaFuncSetAttribute(gemm_mma<2,0,true ,true ,0>, cudaFuncAttributeMaxDynamicSharedMemorySize, SMEM_DYN);
    cudaFuncSetAttribute(gemm_mma<2,2,true ,true ,0>, cudaFuncAttributeMaxDynamicSharedMemorySize, SMEM_DYN);
    cudaFuncSetAttribute(gemm_mma<2,0,true ,false,0>, cudaFuncAttributeMaxDynamicSharedMemorySize, SMEM_DYN);
    cudaFuncSetAttribute(gemm_mma<2,0,false,false,0>, cudaFuncAttributeMaxDynamicSharedMemorySize, SMEM_DYN);

    const float scale = 0.044194173824159216f;   // 1/sqrt(512)
    const dim3 tdim(32, 8);
    const dim3 gridMain(CTX / BNm, MROWS / BMm, 1);      // (4, 256)
    const dim3 gridScore(NENT / BNm, NENT / BMm, BB);    // (8, 8, 32)
    const dim3 gridMsg(CTX / BNm, NENT / BMm, BB);       // (4, 8, 32)

    // weight transposes [K,N] -> [N,K] (+tf32 round)
    transpose_kernel<<<dim3(CTX/32, DFEAT/32, 1), tdim>>>(initKB_w, wIKB, DFEAT, CTX, 0, 0);
    transpose_kernel<<<dim3(CTX/32, CTX/32, 1),   tdim>>>(pxl_w,    wPXL, CTX,   CTX, 0, 0);
    transpose_kernel<<<dim3(CTX/32, CTX/32, 1),   tdim>>>(pxc_w,    wPXC, CTX,   CTX, 0, 0);
    transpose_kernel<<<dim3(CTX/32, 3*CTX/32, 1), tdim>>>(qry_w,    wQRY, 3*CTX, CTX, 0, 0);
    transpose_kernel<<<dim3(CTX/32, 3*CTX/32, 1), tdim>>>(key_w,    wKEY, 3*CTX, CTX, 0, 0);
    transpose_kernel<<<dim3(CTX/32, 3*CTX/32, 1), tdim>>>(val_w,    wVAL, 3*CTX, CTX, 0, 0);
    transpose_kernel<<<dim3(CTX/32, 2*CTX/32, 1), tdim>>>(mu_w,     wMU,  2*CTX, CTX, 0, 0);
    transpose_kernel<<<dim3(CTX/32, 2*CTX/32, 1), tdim>>>(ck_w,     wCK,  2*CTX, CTX, 0, 0);

    // setup
    {
        const size_t n4 = (size_t)MROWS * DFEAT / 4;
        round_copy_kernel<<<(unsigned)((n4 + 255) / 256), 256>>>(images, imgr, n4);
    }
    rownorm_kernel<<<MROWS, 256>>>(images, invn);
    ctx_init_kernel<<<(MROWS * CTX) / 256, 256>>>(initMem, xctxA);
    small_linear_kernel<true><<<BB, 256>>>(q_enc, qInput_w, qInput_b, qbase);

    // x_loc = normalize(images) @ initKB_w + b
    gemm_mma<1,1,true,false,0><<<gridMain, 256, SMEM_DYN>>>(
        imgr, nullptr, nullptr, wIKB, initKB_b, invn, nullptr, nullptr, xloc,
        DFEAT, DFEAT, DFEAT, CTX, 0, 0, 0, 1.f);

    // ---- iteration-invariant hoists ----
    gemm_mma<1,0,false,false,0><<<gridMain, 256, SMEM_DYN>>>(
        xloc, nullptr, nullptr, wPXL, pxl_b, nullptr, nullptr, nullptr, prjl,
        CTX, CTX, CTX, CTX, 0, 0, 0, 1.f);
    gemm_mma<1,0,false,false,0><<<gridMain, 256, SMEM_DYN>>>(
        xloc, nullptr, nullptr, wQRY, nullptr, nullptr, nullptr, nullptr, qL,
        CTX, CTX, 3*CTX, CTX, 0, 0, 0, 1.f);
    gemm_mma<1,0,false,false,0><<<gridMain, 256, SMEM_DYN>>>(
        xloc, nullptr, nullptr, wKEY, nullptr, nullptr, nullptr, nullptr, kL,
        CTX, CTX, 3*CTX, CTX, 0, 0, 0, 1.f);
    gemm_mma<1,0,false,false,0><<<gridMain, 256, SMEM_DYN>>>(
        xloc, nullptr, nullptr, wVAL, nullptr, nullptr, nullptr, nullptr, vL,
        CTX, CTX, 3*CTX, CTX, 0, 0, 0, 1.f);

    float* xc = xctxA;
    float* xn = xctxB;
    for (int t = 0; t < TT; t++) {
        small_linear_kernel<false><<<BB, 256>>>(qbase, qInput2_w + (size_t)t * CMD * CMD,
                                                qInput2_b + (size_t)t * CMD, qcmd);
        text_cmd_kernel<<<BB, 256>>>(qcmd, lstm, c2l_w, c2l_b, q_length, cmd);
        small_linear_kernel<false><<<BB, 256>>>(cmd, pk_w, pk_b, pkg);
        small_linear_kernel<false><<<BB, 256>>>(cmd, pv_w, pv_b, pvg);

        // pp = (x_ctx @ pxc + b) * proj_loc
        gemm_mma<1,3,true,false,0><<<gridMain, 256, SMEM_DYN>>>(
            xc, nullptr, nullptr, wPXC, pxc_b, prjl, nullptr, nullptr, pp,
            CTX, CTX, CTX, CTX, 0, 0, 0, 1.f);

        // q/k/v: K=1024 over [x_ctx | pp] + hoisted x_loc partial
        gemm_mma<2,0,true,true,0><<<gridMain, 256, SMEM_DYN>>>(
            xc, pp, nullptr, wQRY + CTX, qry_b, nullptr, qL, nullptr, q,
            2*CTX, 0, 3*CTX, CTX, 0, 0, 0, 1.f);
        gemm_mma<2,2,true,true,0><<<gridMain, 256, SMEM_DYN>>>(
            xc, pp, nullptr, wKEY + CTX, key_b, pkg, kL, nullptr, k,
            2*CTX, 0, 3*CTX, CTX, 0, 0, 0, 1.f);
        gemm_mma<2,2,true,true,0><<<gridMain, 256, SMEM_DYN>>>(
            xc, pp, nullptr, wVAL + CTX, val_b, pvg, vL, nullptr, v,
            2*CTX, 0, 3*CTX, CTX, 0, 0, 0, 1.f);

        // score[b] = scale * q[b] @ k[b]^T  — only live (m,n) tiles
        gemm_mma<1,0,false,false,1><<<gridScore, 256, SMEM_DYN>>>(
            q, nullptr, nullptr, k, nullptr, nullptr, nullptr, ent_num, score,
            CTX, CTX, CTX, NENT,
            (size_t)NENT * CTX, (size_t)NENT * CTX, (size_t)NENT * NENT, scale);

        attn_softmax_kernel<<<MROWS, 256>>>(score, ent_num);

        // vT[b] = v[b]^T (tf32-rounded)
        transpose_kernel<<<dim3(CTX/32, NENT/32, BB), tdim>>>(
            v, vT, NENT, CTX, (size_t)NENT * CTX, (size_t)CTX * NENT);

        // message[b] = prob[b] @ v[b] — live rows only, K truncated at en
        gemm_mma<1,0,true,false,2><<<gridMsg, 256, SMEM_DYN>>>(
            score, nullptr, nullptr, vT, nullptr, nullptr, nullptr, ent_num, msg,
            NENT, NENT, NENT, CTX,
            (size_t)NENT * NENT, (size_t)CTX * NENT, (size_t)NENT * CTX, 1.f);
        // masked rows: message = column mean of v[b]
        msg_fill_kernel<<<dim3(CTX / 256, BB), 256>>>(v, ent_num, msg);

        // x_ctx' = [x_ctx | message] @ mu + b
        gemm_mma<2,0,true,false,0><<<gridMain, 256, SMEM_DYN>>>(
            xc, msg, nullptr, wMU, mu_b, nullptr, nullptr, nullptr, xn,
            2*CTX, 0, 2*CTX, CTX, 0, 0, 0, 1.f);
        float* tmp = xc; xc = xn; xn = tmp;
    }

    // out = [x_loc | x_ctx] @ ck + b
    gemm_mma<2,0,false,false,0><<<gridMain, 256, SMEM_DYN>>>(
        xloc, xc, nullptr, wCK, ck_b, nullptr, nullptr, nullptr, (float*)d_out,
        2*CTX, 0, 2*CTX, CTX, 0, 0, 0, 1.f);
}

// round 7
// speedup vs baseline: 3.9730x; 1.1905x over previous
#include <cuda_runtime.h>
#include <math.h>
#include <stdint.h>

#define BB     32
#define NENT   1024
#define LQL    128
#define DFEAT  2112
#define CTX    512
#define CMD    512
#define TT     4
#define MROWS  (BB*NENT)
#define NEGV   (-1e30f)

// ---- mma.sync GEMM tiling ----
#define BMm 128
#define BNm 128
#define BKm 16
#define STAGES 4
#define SROW 20                         // smem row stride (floats); conflict-free
#define STAGE_F (2 * BMm * SROW)        // floats per stage (A + B) = 5120
#define TILE_F  (BMm * SROW)            // 2560
#define SMEM_DYN (STAGES * STAGE_F * 4) // 81920 bytes

// ---- scratch ----
__device__ float g_imgr   [(size_t)MROWS*DFEAT];
__device__ float g_invnorm[MROWS];
__device__ float g_xloc   [(size_t)MROWS*CTX];
__device__ float g_xctx0  [(size_t)MROWS*CTX];
__device__ float g_xctx1  [(size_t)MROWS*CTX];
__device__ float g_projloc[(size_t)MROWS*CTX];
__device__ float g_pp     [(size_t)MROWS*CTX];
__device__ float g_q      [(size_t)MROWS*CTX];
__device__ float g_k      [(size_t)MROWS*CTX];
__device__ float g_v      [(size_t)MROWS*CTX];
__device__ float g_vT     [(size_t)MROWS*CTX];
__device__ float g_msg    [(size_t)MROWS*CTX];
__device__ float g_qL     [(size_t)MROWS*CTX];
__device__ float g_kL     [(size_t)MROWS*CTX];
__device__ float g_vL     [(size_t)MROWS*CTX];
__device__ float g_score  [(size_t)BB*NENT*NENT];
__device__ float g_qbase  [BB*CMD];
__device__ float g_qcmd   [BB*CMD];
__device__ float g_cmd    [BB*CMD];
__device__ float g_pkg    [BB*CTX];
__device__ float g_pvg    [BB*CTX];
__device__ float g_wT_ikb[(size_t)CTX*DFEAT];
__device__ float g_wT_pxl[(size_t)CTX*CTX];
__device__ float g_wT_pxc[(size_t)CTX*CTX];
__device__ float g_wT_qry[(size_t)CTX*3*CTX];
__device__ float g_wT_key[(size_t)CTX*3*CTX];
__device__ float g_wT_val[(size_t)CTX*3*CTX];
__device__ float g_wT_mu [(size_t)CTX*2*CTX];
__device__ float g_wT_ck [(size_t)CTX*2*CTX];

__device__ __forceinline__ float rna_tf32(float f) {
    uint32_t r; asm("cvt.rna.tf32.f32 %0, %1;" : "=r"(r) : "f"(f));
    return __uint_as_float(r);
}
__device__ __forceinline__ uint32_t smem_u32(const void* p) {
    uint32_t a;
    asm("{ .reg .u64 t; cvta.to.shared.u64 t, %1; cvt.u32.u64 %0, t; }" : "=r"(a) : "l"(p));
    return a;
}
__device__ __forceinline__ void cp_async16(uint32_t saddr, const void* gptr) {
    asm volatile("cp.async.cg.shared.global [%0], [%1], 16;" :: "r"(saddr), "l"(gptr));
}
#define CP_COMMIT() asm volatile("cp.async.commit_group;" ::: "memory")
#define CP_WAIT2()  asm volatile("cp.async.wait_group 2;" ::: "memory")

__device__ __forceinline__ void ldsm_x4(uint32_t addr, uint32_t& r0, uint32_t& r1,
                                        uint32_t& r2, uint32_t& r3)
{
    asm volatile("ldmatrix.sync.aligned.m8n8.x4.shared.b16 {%0,%1,%2,%3}, [%4];"
                 : "=r"(r0), "=r"(r1), "=r"(r2), "=r"(r3) : "r"(addr));
}

__device__ __forceinline__ void mma_m16n8k8(float* d,
    uint32_t a0, uint32_t a1, uint32_t a2, uint32_t a3,
    uint32_t b0, uint32_t b1)
{
    asm volatile(
        "mma.sync.aligned.m16n8k8.row.col.f32.tf32.tf32.f32 "
        "{%0,%1,%2,%3}, {%4,%5,%6,%7}, {%8,%9}, {%0,%1,%2,%3};"
        : "+f"(d[0]), "+f"(d[1]), "+f"(d[2]), "+f"(d[3])
        : "r"(a0), "r"(a1), "r"(a2), "r"(a3), "r"(b0), "r"(b1));
}

// ---------------- tensor-core GEMM via mma.sync (tf32) ----------------
// C[M,N] = epi( A @ B^T [+ addC] ); A row-major [M,K] (virtual concat of up to
// 3 CTX-wide buffers), B K-major [N,K]. 4-stage cp.async + ldmatrix fragments.
// EPI 0: acc*alpha + bias[n]
// EPI 1: acc*extra[m] + bias[n]
// EPI 2: (acc+bias[n]) * extra[(m>>10)*CTX + n]
// EPI 3: (acc+bias[n]) * extra[m*ldc + n]
// ADD: acc += addC[m*ldc+n] before EPI.  RND: round result to tf32.
// MASK 0: none. 1 (score): skip tile if m0>=en || n0>=en.
//      2 (message): skip tile if m0>=en; truncate K at ceil(en/BKm)*BKm.
template<int NSRC, int EPI, bool RND, bool ADD, int MASK>
__global__ __launch_bounds__(256, 2)
void gemm_mma(const float* __restrict__ A0, const float* __restrict__ A1,
              const float* __restrict__ A2, const float* __restrict__ Bt,
              const float* __restrict__ bias, const float* __restrict__ extra,
              const float* __restrict__ addC, const int* __restrict__ ennum,
              float* __restrict__ C,
              int K, int lda, int ldb, int ldc,
              size_t sA, size_t sB, size_t sC, float alpha)
{
    extern __shared__ float smem[];
    const uint32_t sbase = smem_u32(smem);

    const int tid = threadIdx.x;
    const int z = blockIdx.z;
    const int m0 = blockIdx.y * BMm;
    const int n0 = blockIdx.x * BNm;

    int Keff = K;
    if (MASK != 0) {
        const int en = ennum[z];
        if (m0 >= en) return;
        if (MASK == 1 && n0 >= en) return;
        if (MASK == 2) { const int kc = ((en + BKm - 1) / BKm) * BKm; Keff = kc < K ? kc : K; }
    }

    const float* Abase = A0 + (size_t)z * sA;
    const float* Bbase = Bt + (size_t)z * sB;
    float* Cbase = C + (size_t)z * sC;

    const int wid = tid >> 5, lane = tid & 31;
    const int wm = (wid & 3) * 32;
    const int wn = (wid >> 2) * 64;
    const int gr = lane >> 2;
    const int gc = lane & 3;

    // ldmatrix lane mapping
    const int lr = lane & 7, lg = lane >> 3;
    const int arow  = wm + lr + (lg & 1) * 8;     // + mt*16
    const int akoff = (lg >> 1) * 4;              // + kk
    const int brow  = wn + lr + (lg >> 1) * 8;    // + ntp*16
    const int bkoff = (lg & 1) * 4;               // + kk

    const int prow0 = tid >> 2;
    const int pkq   = (tid & 3) * 4;

    float acc[2][8][4] = {};
    const int NCC = Keff / BKm;

    auto loadChunk = [&](int c, int st) {
        const int k0 = c * BKm;
        const float* Ap; int al, ak;
        if (NSRC == 1) { Ap = Abase; al = lda; ak = k0; }
        else {
            const int src = k0 >> 9;
            Ap = (src == 0) ? A0 : ((src == 1) ? A1 : A2);
            al = CTX; ak = k0 & (CTX - 1);
        }
        const uint32_t sa = sbase + (uint32_t)(st * STAGE_F) * 4;
        const uint32_t sb = sa + (uint32_t)TILE_F * 4;
        #pragma unroll
        for (int t = 0; t < 2; ++t) {
            const int row = prow0 + t * 64;
            cp_async16(sa + (uint32_t)(row * SROW + pkq) * 4,
                       Ap + (size_t)(m0 + row) * al + ak + pkq);
            cp_async16(sb + (uint32_t)(row * SROW + pkq) * 4,
                       Bbase + (size_t)(n0 + row) * ldb + k0 + pkq);
        }
        CP_COMMIT();
    };

    auto compute = [&](int st) {
        const uint32_t SAu = sbase + (uint32_t)(st * STAGE_F) * 4;
        const uint32_t SBu = SAu + (uint32_t)TILE_F * 4;
        #pragma unroll
        for (int kk = 0; kk < BKm; kk += 8) {
            uint32_t b[8][2];
            #pragma unroll
            for (int ntp = 0; ntp < 4; ++ntp) {
                const uint32_t addr = SBu +
                    (uint32_t)(((brow + ntp * 16) * SROW) + kk + bkoff) * 4;
                ldsm_x4(addr, b[2*ntp][0], b[2*ntp][1], b[2*ntp+1][0], b[2*ntp+1][1]);
            }
            #pragma unroll
            for (int mt = 0; mt < 2; ++mt) {
                uint32_t a0, a1, a2, a3;
                const uint32_t addr = SAu +
                    (uint32_t)(((arow + mt * 16) * SROW) + kk + akoff) * 4;
                ldsm_x4(addr, a0, a1, a2, a3);
                #pragma unroll
                for (int nt = 0; nt < 8; ++nt)
                    mma_m16n8k8(acc[mt][nt], a0, a1, a2, a3, b[nt][0], b[nt][1]);
            }
        }
    };

    #pragma unroll
    for (int s = 0; s < STAGES - 1; ++s) {
        if (s < NCC) loadChunk(s, s);
        else CP_COMMIT();
    }
    for (int c = 0; c < NCC; ++c) {
        CP_WAIT2();
        __syncthreads();
        const int nc = c + STAGES - 1;
        if (nc < NCC) loadChunk(nc, nc & (STAGES - 1));
        else CP_COMMIT();
        compute(c & (STAGES - 1));
    }

    // ---- epilogue ----
    #pragma unroll
    for (int mt = 0; mt < 2; ++mt) {
        #pragma unroll
        for (int half = 0; half < 2; ++half) {
            const int m = m0 + wm + mt * 16 + gr + half * 8;
            const float rs = (EPI == 1) ? extra[m] : 0.f;
            #pragma unroll
            for (int nt = 0; nt < 8; ++nt) {
                const int n = n0 + wn + nt * 8 + gc * 2;
                float v0 = acc[mt][nt][half * 2 + 0];
                float v1 = acc[mt][nt][half * 2 + 1];
                if (ADD) {
                    const float2 ad = *reinterpret_cast<const float2*>(addC + (size_t)m * ldc + n);
                    v0 += ad.x; v1 += ad.y;
                }
                const float bb0 = bias ? bias[n]     : 0.f;
                const float bb1 = bias ? bias[n + 1] : 0.f;
                if (EPI == 0)      { v0 = v0 * alpha + bb0;  v1 = v1 * alpha + bb1; }
                else if (EPI == 1) { v0 = v0 * rs + bb0;     v1 = v1 * rs + bb1; }
                else if (EPI == 2) {
                    const float* g = extra + (size_t)(m >> 10) * CTX + n;
                    v0 = (v0 + bb0) * g[0];
                    v1 = (v1 + bb1) * g[1];
                } else {
                    const float* g = extra + (size_t)m * ldc + n;
                    v0 = (v0 + bb0) * g[0];
                    v1 = (v1 + bb1) * g[1];
                }
                if (RND) { v0 = rna_tf32(v0); v1 = rna_tf32(v1); }
                *reinterpret_cast<float2*>(Cbase + (size_t)m * ldc + n) = make_float2(v0, v1);
            }
        }
    }
}

// ---- masked-row message fill: msg[b, m>=en, :] = mean over rows of v[b] ----
__global__ void msg_fill_kernel(const float* __restrict__ v, const int* __restrict__ ennum,
                                float* __restrict__ msg)
{
    const int b = blockIdx.y;
    const int d = blockIdx.x * 256 + threadIdx.x;
    const int en = ennum[b];
    if (en >= NENT) return;
    const float* vb = v + (size_t)b * NENT * CTX + d;
    float s = 0.f;
    #pragma unroll 4
    for (int kk = 0; kk < NENT; ++kk) s += vb[(size_t)kk * CTX];
    const float mean = rna_tf32(s * (1.f / NENT));
    float* mb = msg + (size_t)b * NENT * CTX + d;
    for (int m = en; m < NENT; ++m) mb[(size_t)m * CTX] = mean;
}

// ---- transpose (+tf32 round): out[C,R] = rnd(in[R,C]^T), batched ----
__global__ void transpose_kernel(const float* __restrict__ in, float* __restrict__ out,
                                 int R, int C, size_t sIn, size_t sOut)
{
    __shared__ float tile[32][33];
    const int z = blockIdx.z;
    in  += (size_t)z * sIn;
    out += (size_t)z * sOut;
    const int r0 = blockIdx.y * 32, c0 = blockIdx.x * 32;
    #pragma unroll
    for (int i = threadIdx.y; i < 32; i += 8)
        tile[i][threadIdx.x] = rna_tf32(in[(size_t)(r0 + i) * C + c0 + threadIdx.x]);
    __syncthreads();
    #pragma unroll
    for (int i = threadIdx.y; i < 32; i += 8)
        out[(size_t)(c0 + i) * R + r0 + threadIdx.x] = tile[threadIdx.x][i];
}

// ---- fused: row inv-norm (fp32) + tf32-rounded copy of images ----
__global__ void rownorm_round_kernel(const float* __restrict__ img, float* __restrict__ invn,
                                     float* __restrict__ imgr)
{
    const int m = blockIdx.x;
    const float4* r4 = reinterpret_cast<const float4*>(img + (size_t)m * DFEAT);
    float4* o4 = reinterpret_cast<float4*>(imgr + (size_t)m * DFEAT);
    const int tid = threadIdx.x;
    float s = 0.f;
    for (int i = tid; i < DFEAT / 4; i += 256) {
        float4 u = r4[i];
        s = fmaf(u.x, u.x, s); s = fmaf(u.y, u.y, s);
        s = fmaf(u.z, u.z, s); s = fmaf(u.w, u.w, s);
        u.x = rna_tf32(u.x); u.y = rna_tf32(u.y);
        u.z = rna_tf32(u.z); u.w = rna_tf32(u.w);
        o4[i] = u;
    }
    __shared__ float red[256];
    red[tid] = s; __syncthreads();
    for (int o = 128; o > 0; o >>= 1) { if (tid < o) red[tid] += red[tid + o]; __syncthreads(); }
    if (tid == 0) invn[m] = 1.f / fmaxf(sqrtf(red[0]), 1e-12f);
}

__global__ void ctx_init_kernel(const float* __restrict__ initMem, float* __restrict__ xctx)
{
    const size_t i = (size_t)blockIdx.x * blockDim.x + threadIdx.x;
    xctx[i] = rna_tf32(initMem[i & (CTX - 1)]);
}

template<bool ELU>
__global__ void small_linear_kernel(const float* __restrict__ in, const float* __restrict__ W,
                                    const float* __restrict__ bias, float* __restrict__ out)
{
    const int b = blockIdx.x;
    const int tid = threadIdx.x;
    __shared__ float x[CMD];
    for (int d = tid; d < CMD; d += 256) x[d] = in[b * CMD + d];
    __syncthreads();
    for (int j = tid; j < CMD; j += 256) {
        float acc = 0.f;
        #pragma unroll 4
        for (int k = 0; k < CMD; k++) acc = fmaf(x[k], W[(size_t)k * CMD + j], acc);
        acc += bias[j];
        if (ELU) acc = (acc > 0.f) ? acc : expm1f(acc);
        out[b * CMD + j] = acc;
    }
}

__global__ void text_cmd_kernel(const float* __restrict__ qcmd, const float* __restrict__ lstm,
                                const float* __restrict__ c2l_w, const float* __restrict__ c2l_b,
                                const int* __restrict__ qlen, float* __restrict__ cmd)
{
    const int b = blockIdx.x;
    const int tid = threadIdx.x;
    __shared__ float e[CMD];
    __shared__ float att[LQL];
    for (int d = tid; d < CMD; d += 256) e[d] = qcmd[b * CMD + d] * c2l_w[d];
    __syncthreads();
    if (tid < LQL) {
        const float* L = lstm + ((size_t)b * LQL + tid) * CMD;
        float acc = 0.f;
        for (int d = 0; d < CMD; d++) acc = fmaf(L[d], e[d], acc);
        acc += c2l_b[0];
        att[tid] = (tid >= qlen[b]) ? NEGV : acc;
    }
    __syncthreads();
    if (tid == 0) {
        float mx = -3.4e38f;
        for (int l = 0; l < LQL; l++) mx = fmaxf(mx, att[l]);
        float sum = 0.f;
        for (int l = 0; l < LQL; l++) { att[l] = expf(att[l] - mx); sum += att[l]; }
        const float inv = 1.f / sum;
        for (int l = 0; l < LQL; l++) att[l] *= inv;
    }
    __syncthreads();
    for (int d = tid; d < CMD; d += 256) {
        float acc = 0.f;
        #pragma unroll 4
        for (int l = 0; l < LQL; l++) acc = fmaf(att[l], lstm[((size_t)b * LQL + l) * CMD + d], acc);
        cmd[b * CMD + d] = acc;
    }
}

// masked row softmax (in place); skips fully-masked rows (msg_fill handles them)
__global__ void attn_softmax_kernel(float* __restrict__ score, const int* __restrict__ entity_num)
{
    const int row = blockIdx.x;
    const int b = row >> 10;
    const int n = row & 1023;
    const int en = entity_num[b];
    if (n >= en) return;
    float* s = score + (size_t)row * NENT;
    const int tid = threadIdx.x;

    float v[4];
    float mx = -3.4e38f;
    #pragma unroll
    for (int j = 0; j < 4; j++) {
        const int m = tid + j * 256;
        float x = s[m];
        x = (m >= en) ? NEGV : x;
        v[j] = x;
        mx = fmaxf(mx, x);
    }
    __shared__ float red[256];
    red[tid] = mx; __syncthreads();
    for (int o = 128; o > 0; o >>= 1) { if (tid < o) red[tid] = fmaxf(red[tid], red[tid + o]); __syncthreads(); }
    mx = red[0];
    __syncthreads();

    float sum = 0.f;
    #pragma unroll
    for (int j = 0; j < 4; j++) { v[j] = expf(v[j] - mx); sum += v[j]; }
    red[tid] = sum; __syncthreads();
    for (int o = 128; o > 0; o >>= 1) { if (tid < o) red[tid] += red[tid + o]; __syncthreads(); }
    const float inv = 1.f / red[0];

    #pragma unroll
    for (int j = 0; j < 4; j++) s[tid + j * 256] = rna_tf32(v[j] * inv);
}

// ---------------- launch ----------------
template<typename T> static float* symaddr(T& sym) {
    void* p = nullptr;
    cudaGetSymbolAddress(&p, sym);
    return (float*)p;
}

extern "C" void kernel_launch(void* const* d_in, const int* in_sizes, int n_in,
                              void* d_out, int out_size)
{
    const float* images    = (const float*)d_in[0];
    const float* q_enc     = (const float*)d_in[1];
    const float* lstm      = (const float*)d_in[2];
    const int*   q_length  = (const int*)  d_in[3];
    const int*   ent_num   = (const int*)  d_in[4];
    const float* initKB_w  = (const float*)d_in[5];
    const float* initKB_b  = (const float*)d_in[6];
    const float* initMem   = (const float*)d_in[7];
    const float* qInput_w  = (const float*)d_in[8];
    const float* qInput_b  = (const float*)d_in[9];
    const float* qInput2_w = (const float*)d_in[10];
    const float* qInput2_b = (const float*)d_in[11];
    const float* c2l_w     = (const float*)d_in[12];
    const float* c2l_b     = (const float*)d_in[13];
    const float* pxl_w     = (const float*)d_in[14];
    const float* pxl_b     = (const float*)d_in[15];
    const float* pxc_w     = (const float*)d_in[16];
    const float* pxc_b     = (const float*)d_in[17];
    const float* qry_w     = (const float*)d_in[18];
    const float* qry_b     = (const float*)d_in[19];
    const float* key_w     = (const float*)d_in[20];
    const float* key_b     = (const float*)d_in[21];
    const float* val_w     = (const float*)d_in[22];
    const float* val_b     = (const float*)d_in[23];
    const float* pk_w      = (const float*)d_in[24];
    const float* pk_b      = (const float*)d_in[25];
    const float* pv_w      = (const float*)d_in[26];
    const float* pv_b      = (const float*)d_in[27];
    const float* mu_w      = (const float*)d_in[28];
    const float* mu_b      = (const float*)d_in[29];
    const float* ck_w      = (const float*)d_in[30];
    const float* ck_b      = (const float*)d_in[31];

    float* imgr  = symaddr(g_imgr);
    float* invn  = symaddr(g_invnorm);
    float* xloc  = symaddr(g_xloc);
    float* xctxA = symaddr(g_xctx0);
    float* xctxB = symaddr(g_xctx1);
    float* prjl  = symaddr(g_projloc);
    float* pp    = symaddr(g_pp);
    float* q     = symaddr(g_q);
    float* k     = symaddr(g_k);
    float* v     = symaddr(g_v);
    float* vT    = symaddr(g_vT);
    float* msg   = symaddr(g_msg);
    float* qL    = symaddr(g_qL);
    float* kL    = symaddr(g_kL);
    float* vL    = symaddr(g_vL);
    float* score = symaddr(g_score);
    float* qbase = symaddr(g_qbase);
    float* qcmd  = symaddr(g_qcmd);
    float* cmd   = symaddr(g_cmd);
    float* pkg   = symaddr(g_pkg);
    float* pvg   = symaddr(g_pvg);
    float* wIKB  = symaddr(g_wT_ikb);
    float* wPXL  = symaddr(g_wT_pxl);
    float* wPXC  = symaddr(g_wT_pxc);
    float* wQRY  = symaddr(g_wT_qry);
    float* wKEY  = symaddr(g_wT_key);
    float* wVAL  = symaddr(g_wT_val);
    float* wMU   = symaddr(g_wT_mu);
    float* wCK   = symaddr(g_wT_ck);

    cudaFuncSetAttribute(gemm_mma<1,0,false,false,0>, cudaFuncAttributeMaxDynamicSharedMemorySize, SMEM_DYN);
    cudaFuncSetAttribute(gemm_mma<1,1,true ,false,0>, cudaFuncAttributeMaxDynamicSharedMemorySize, SMEM_DYN);
    cudaFuncSetAttribute(gemm_mma<1,3,true ,false,0>, cudaFuncAttributeMaxDynamicSharedMemorySize, SMEM_DYN);
    cudaFuncSetAttribute(gemm_mma<1,0,false,false,1>, cudaFuncAttributeMaxDynamicSharedMemorySize, SMEM_DYN);
    cudaFuncSetAttribute(gemm_mma<1,0,true ,false,2>, cudaFuncAttributeMaxDynamicSharedMemorySize, SMEM_DYN);
    cudaFuncSetAttribute(gemm_mma<2,0,true ,true ,0>, cudaFuncAttributeMaxDynamicSharedMemorySize, SMEM_DYN);
    cudaFuncSetAttribute(gemm_mma<2,2,true ,true ,0>, cudaFuncAttributeMaxDynamicSharedMemorySize, SMEM_DYN);
    cudaFuncSetAttribute(gemm_mma<2,0,true ,false,0>, cudaFuncAttributeMaxDynamicSharedMemorySize, SMEM_DYN);
    cudaFuncSetAttribute(gemm_mma<2,0,false,false,0>, cudaFuncAttributeMaxDynamicSharedMemorySize, SMEM_DYN);

    const float scale = 0.044194173824159216f;   // 1/sqrt(512)
    const dim3 tdim(32, 8);
    const dim3 gridMain(CTX / BNm, MROWS / BMm, 1);      // (4, 256)
    const dim3 gridScore(NENT / BNm, NENT / BMm, BB);    // (8, 8, 32)
    const dim3 gridMsg(CTX / BNm, NENT / BMm, BB);       // (4, 8, 32)

    // --- launch order arranged so ncu (-s 5 -c 1) captures the initKB GEMM ---
    transpose_kernel<<<dim3(CTX/32, DFEAT/32, 1), tdim>>>(initKB_w, wIKB, DFEAT, CTX, 0, 0);  // 0
    rownorm_round_kernel<<<MROWS, 256>>>(images, invn, imgr);                                 // 1
    ctx_init_kernel<<<(MROWS * CTX) / 256, 256>>>(initMem, xctxA);                            // 2
    small_linear_kernel<true><<<BB, 256>>>(q_enc, qInput_w, qInput_b, qbase);                 // 3
    transpose_kernel<<<dim3(CTX/32, CTX/32, 1), tdim>>>(pxl_w, wPXL, CTX, CTX, 0, 0);         // 4
    // 5: x_loc = normalize(images) @ initKB_w + b   <-- ncu target
    gemm_mma<1,1,true,false,0><<<gridMain, 256, SMEM_DYN>>>(
        imgr, nullptr, nullptr, wIKB, initKB_b, invn, nullptr, nullptr, xloc,
        DFEAT, DFEAT, DFEAT, CTX, 0, 0, 0, 1.f);

    // remaining weight transposes
    transpose_kernel<<<dim3(CTX/32, CTX/32, 1),   tdim>>>(pxc_w, wPXC, CTX,   CTX, 0, 0);
    transpose_kernel<<<dim3(CTX/32, 3*CTX/32, 1), tdim>>>(qry_w, wQRY, 3*CTX, CTX, 0, 0);
    transpose_kernel<<<dim3(CTX/32, 3*CTX/32, 1), tdim>>>(key_w, wKEY, 3*CTX, CTX, 0, 0);
    transpose_kernel<<<dim3(CTX/32, 3*CTX/32, 1), tdim>>>(val_w, wVAL, 3*CTX, CTX, 0, 0);
    transpose_kernel<<<dim3(CTX/32, 2*CTX/32, 1), tdim>>>(mu_w,  wMU,  2*CTX, CTX, 0, 0);
    transpose_kernel<<<dim3(CTX/32, 2*CTX/32, 1), tdim>>>(ck_w,  wCK,  2*CTX, CTX, 0, 0);

    // ---- iteration-invariant hoists ----
    gemm_mma<1,0,false,false,0><<<gridMain, 256, SMEM_DYN>>>(
        xloc, nullptr, nullptr, wPXL, pxl_b, nullptr, nullptr, nullptr, prjl,
        CTX, CTX, CTX, CTX, 0, 0, 0, 1.f);
    gemm_mma<1,0,false,false,0><<<gridMain, 256, SMEM_DYN>>>(
        xloc, nullptr, nullptr, wQRY, nullptr, nullptr, nullptr, nullptr, qL,
        CTX, CTX, 3*CTX, CTX, 0, 0, 0, 1.f);
    gemm_mma<1,0,false,false,0><<<gridMain, 256, SMEM_DYN>>>(
        xloc, nullptr, nullptr, wKEY, nullptr, nullptr, nullptr, nullptr, kL,
        CTX, CTX, 3*CTX, CTX, 0, 0, 0, 1.f);
    gemm_mma<1,0,false,false,0><<<gridMain, 256, SMEM_DYN>>>(
        xloc, nullptr, nullptr, wVAL, nullptr, nullptr, nullptr, nullptr, vL,
        CTX, CTX, 3*CTX, CTX, 0, 0, 0, 1.f);

    float* xc = xctxA;
    float* xn = xctxB;
    for (int t = 0; t < TT; t++) {
        small_linear_kernel<false><<<BB, 256>>>(qbase, qInput2_w + (size_t)t * CMD * CMD,
                                                qInput2_b + (size_t)t * CMD, qcmd);
        text_cmd_kernel<<<BB, 256>>>(qcmd, lstm, c2l_w, c2l_b, q_length, cmd);
        small_linear_kernel<false><<<BB, 256>>>(cmd, pk_w, pk_b, pkg);
        small_linear_kernel<false><<<BB, 256>>>(cmd, pv_w, pv_b, pvg);

        // pp = (x_ctx @ pxc + b) * proj_loc
        gemm_mma<1,3,true,false,0><<<gridMain, 256, SMEM_DYN>>>(
            xc, nullptr, nullptr, wPXC, pxc_b, prjl, nullptr, nullptr, pp,
            CTX, CTX, CTX, CTX, 0, 0, 0, 1.f);

        // q/k/v: K=1024 over [x_ctx | pp] + hoisted x_loc partial
        gemm_mma<2,0,true,true,0><<<gridMain, 256, SMEM_DYN>>>(
            xc, pp, nullptr, wQRY + CTX, qry_b, nullptr, qL, nullptr, q,
            2*CTX, 0, 3*CTX, CTX, 0, 0, 0, 1.f);
        gemm_mma<2,2,true,true,0><<<gridMain, 256, SMEM_DYN>>>(
            xc, pp, nullptr, wKEY + CTX, key_b, pkg, kL, nullptr, k,
            2*CTX, 0, 3*CTX, CTX, 0, 0, 0, 1.f);
        gemm_mma<2,2,true,true,0><<<gridMain, 256, SMEM_DYN>>>(
            xc, pp, nullptr, wVAL + CTX, val_b, pvg, vL, nullptr, v,
            2*CTX, 0, 3*CTX, CTX, 0, 0, 0, 1.f);

        // score[b] = scale * q[b] @ k[b]^T  — only live (m,n) tiles
        gemm_mma<1,0,false,false,1><<<gridScore, 256, SMEM_DYN>>>(
            q, nullptr, nullptr, k, nullptr, nullptr, nullptr, ent_num, score,
            CTX, CTX, CTX, NENT,
            (size_t)NENT * CTX, (size_t)NENT * CTX, (size_t)NENT * NENT, scale);

        attn_softmax_kernel<<<MROWS, 256>>>(score, ent_num);

        // vT[b] = v[b]^T (tf32-rounded)
        transpose_kernel<<<dim3(CTX/32, NENT/32, BB), tdim>>>(
            v, vT, NENT, CTX, (size_t)NENT * CTX, (size_t)CTX * NENT);

        // message[b] = prob[b] @ v[b] — live rows only, K truncated at en
        gemm_mma<1,0,true,false,2><<<gridMsg, 256, SMEM_DYN>>>(
            score, nullptr, nullptr, vT, nullptr, nullptr, nullptr, ent_num, msg,
            NENT, NENT, NENT, CTX,
            (size_t)NENT * NENT, (size_t)CTX * NENT, (size_t)NENT * CTX, 1.f);
        msg_fill_kernel<<<dim3(CTX / 256, BB), 256>>>(v, ent_num, msg);

        // x_ctx' = [x_ctx | message] @ mu + b
        gemm_mma<2,0,true,false,0><<<gridMain, 256, SMEM_DYN>>>(
            xc, msg, nullptr, wMU, mu_b, nullptr, nullptr, nullptr, xn,
            2*CTX, 0, 2*CTX, CTX, 0, 0, 0, 1.f);
        float* tmp = xc; xc = xn; xn = tmp;
    }

    // out = [x_loc | x_ctx] @ ck + b
    gemm_mma<2,0,false,false,0><<<gridMain, 256, SMEM_DYN>>>(
        xloc, xc, nullptr, wCK, ck_b, nullptr, nullptr, nullptr, (float*)d_out,
        2*CTX, 0, 2*CTX, CTX, 0, 0, 0, 1.f);
}

// round 8
// speedup vs baseline: 4.9116x; 1.2362x over previous
#include <cuda_runtime.h>
#include <math.h>
#include <stdint.h>

#define BB     32
#define NENT   1024
#define LQL    128
#define DFEAT  2112
#define CTX    512
#define CMD    512
#define TT     4
#define MROWS  (BB*NENT)
#define NEGV   (-1e30f)

// ---- mma.sync GEMM tiling ----
#define BMm 128
#define BNm 128
#define BKm 16
#define STAGES 4
#define SROW 20
#define STAGE_F (2 * BMm * SROW)
#define TILE_F  (BMm * SROW)
#define SMEM_DYN (STAGES * STAGE_F * 4)

// ---- scratch ----
__device__ float g_imgr   [(size_t)MROWS*DFEAT];
__device__ float g_invnorm[MROWS];
__device__ float g_xloc   [(size_t)MROWS*CTX];
__device__ float g_xctx0  [(size_t)MROWS*CTX];
__device__ float g_xctx1  [(size_t)MROWS*CTX];
__device__ float g_projloc[(size_t)MROWS*CTX];
__device__ float g_pp     [(size_t)MROWS*CTX];
__device__ float g_q      [(size_t)MROWS*CTX];
__device__ float g_k      [(size_t)MROWS*CTX];
__device__ float g_v      [(size_t)MROWS*CTX];
__device__ float g_vT     [(size_t)MROWS*CTX];
__device__ float g_msg    [(size_t)MROWS*CTX];
__device__ float g_qL     [(size_t)MROWS*CTX];
__device__ float g_kL     [(size_t)MROWS*CTX];
__device__ float g_vL     [(size_t)MROWS*CTX];
__device__ float g_score  [(size_t)BB*NENT*NENT];
__device__ float g_qbase  [BB*CMD];
__device__ float g_qcmd   [BB*CMD];
__device__ float g_cmd    [BB*CMD];
__device__ float g_pkg    [BB*CTX];
__device__ float g_pvg    [BB*CTX];
__device__ float g_wT_ikb[(size_t)CTX*DFEAT];
__device__ float g_wT_pxl[(size_t)CTX*CTX];
__device__ float g_wT_pxc[(size_t)CTX*CTX];
__device__ float g_wT_qry[(size_t)CTX*3*CTX];
__device__ float g_wT_key[(size_t)CTX*3*CTX];
__device__ float g_wT_val[(size_t)CTX*3*CTX];
__device__ float g_wT_mu [(size_t)CTX*2*CTX];
__device__ float g_wT_ck [(size_t)CTX*2*CTX];
// small-linear weights, transposed, NOT tf32-rounded (fp32 path)
__device__ float g_wT_qin [(size_t)CMD*CMD];
__device__ float g_wT_qin2[(size_t)TT*CMD*CMD];
__device__ float g_wT_pk  [(size_t)CMD*CTX];
__device__ float g_wT_pv  [(size_t)CMD*CTX];

__device__ __forceinline__ float rna_tf32(float f) {
    uint32_t r; asm("cvt.rna.tf32.f32 %0, %1;" : "=r"(r) : "f"(f));
    return __uint_as_float(r);
}
__device__ __forceinline__ uint32_t smem_u32(const void* p) {
    uint32_t a;
    asm("{ .reg .u64 t; cvta.to.shared.u64 t, %1; cvt.u32.u64 %0, t; }" : "=r"(a) : "l"(p));
    return a;
}
__device__ __forceinline__ void cp_async16(uint32_t saddr, const void* gptr) {
    asm volatile("cp.async.cg.shared.global [%0], [%1], 16;" :: "r"(saddr), "l"(gptr));
}
#define CP_COMMIT() asm volatile("cp.async.commit_group;" ::: "memory")
#define CP_WAIT2()  asm volatile("cp.async.wait_group 2;" ::: "memory")

__device__ __forceinline__ void ldsm_x4(uint32_t addr, uint32_t& r0, uint32_t& r1,
                                        uint32_t& r2, uint32_t& r3)
{
    asm volatile("ldmatrix.sync.aligned.m8n8.x4.shared.b16 {%0,%1,%2,%3}, [%4];"
                 : "=r"(r0), "=r"(r1), "=r"(r2), "=r"(r3) : "r"(addr));
}

__device__ __forceinline__ void mma_m16n8k8(float* d,
    uint32_t a0, uint32_t a1, uint32_t a2, uint32_t a3,
    uint32_t b0, uint32_t b1)
{
    asm volatile(
        "mma.sync.aligned.m16n8k8.row.col.f32.tf32.tf32.f32 "
        "{%0,%1,%2,%3}, {%4,%5,%6,%7}, {%8,%9}, {%0,%1,%2,%3};"
        : "+f"(d[0]), "+f"(d[1]), "+f"(d[2]), "+f"(d[3])
        : "r"(a0), "r"(a1), "r"(a2), "r"(a3), "r"(b0), "r"(b1));
}

// ---------------- tensor-core GEMM via mma.sync (tf32) ----------------
template<int NSRC, int EPI, bool RND, bool ADD, int MASK>
__global__ __launch_bounds__(256, 2)
void gemm_mma(const float* __restrict__ A0, const float* __restrict__ A1,
              const float* __restrict__ A2, const float* __restrict__ Bt,
              const float* __restrict__ bias, const float* __restrict__ extra,
              const float* __restrict__ addC, const int* __restrict__ ennum,
              float* __restrict__ C,
              int K, int lda, int ldb, int ldc,
              size_t sA, size_t sB, size_t sC, float alpha)
{
    extern __shared__ float smem[];
    const uint32_t sbase = smem_u32(smem);

    const int tid = threadIdx.x;
    const int z = blockIdx.z;
    const int m0 = blockIdx.y * BMm;
    const int n0 = blockIdx.x * BNm;

    int Keff = K;
    if (MASK != 0) {
        const int en = ennum[z];
        if (m0 >= en) return;
        if (MASK == 1 && n0 >= en) return;
        if (MASK == 2) { const int kc = ((en + BKm - 1) / BKm) * BKm; Keff = kc < K ? kc : K; }
    }

    const float* Abase = A0 + (size_t)z * sA;
    const float* Bbase = Bt + (size_t)z * sB;
    float* Cbase = C + (size_t)z * sC;

    const int wid = tid >> 5, lane = tid & 31;
    const int wm = (wid & 3) * 32;
    const int wn = (wid >> 2) * 64;
    const int gr = lane >> 2;
    const int gc = lane & 3;

    const int lr = lane & 7, lg = lane >> 3;
    const int arow  = wm + lr + (lg & 1) * 8;
    const int akoff = (lg >> 1) * 4;
    const int brow  = wn + lr + (lg >> 1) * 8;
    const int bkoff = (lg & 1) * 4;

    const int prow0 = tid >> 2;
    const int pkq   = (tid & 3) * 4;

    float acc[2][8][4] = {};
    const int NCC = Keff / BKm;

    auto loadChunk = [&](int c, int st) {
        const int k0 = c * BKm;
        const float* Ap; int al, ak;
        if (NSRC == 1) { Ap = Abase; al = lda; ak = k0; }
        else {
            const int src = k0 >> 9;
            Ap = (src == 0) ? A0 : ((src == 1) ? A1 : A2);
            al = CTX; ak = k0 & (CTX - 1);
        }
        const uint32_t sa = sbase + (uint32_t)(st * STAGE_F) * 4;
        const uint32_t sb = sa + (uint32_t)TILE_F * 4;
        #pragma unroll
        for (int t = 0; t < 2; ++t) {
            const int row = prow0 + t * 64;
            cp_async16(sa + (uint32_t)(row * SROW + pkq) * 4,
                       Ap + (size_t)(m0 + row) * al + ak + pkq);
            cp_async16(sb + (uint32_t)(row * SROW + pkq) * 4,
                       Bbase + (size_t)(n0 + row) * ldb + k0 + pkq);
        }
        CP_COMMIT();
    };

    auto compute = [&](int st) {
        const uint32_t SAu = sbase + (uint32_t)(st * STAGE_F) * 4;
        const uint32_t SBu = SAu + (uint32_t)TILE_F * 4;
        #pragma unroll
        for (int kk = 0; kk < BKm; kk += 8) {
            uint32_t b[8][2];
            #pragma unroll
            for (int ntp = 0; ntp < 4; ++ntp) {
                const uint32_t addr = SBu +
                    (uint32_t)(((brow + ntp * 16) * SROW) + kk + bkoff) * 4;
                ldsm_x4(addr, b[2*ntp][0], b[2*ntp][1], b[2*ntp+1][0], b[2*ntp+1][1]);
            }
            #pragma unroll
            for (int mt = 0; mt < 2; ++mt) {
                uint32_t a0, a1, a2, a3;
                const uint32_t addr = SAu +
                    (uint32_t)(((arow + mt * 16) * SROW) + kk + akoff) * 4;
                ldsm_x4(addr, a0, a1, a2, a3);
                #pragma unroll
                for (int nt = 0; nt < 8; ++nt)
                    mma_m16n8k8(acc[mt][nt], a0, a1, a2, a3, b[nt][0], b[nt][1]);
            }
        }
    };

    #pragma unroll
    for (int s = 0; s < STAGES - 1; ++s) {
        if (s < NCC) loadChunk(s, s);
        else CP_COMMIT();
    }
    for (int c = 0; c < NCC; ++c) {
        CP_WAIT2();
        __syncthreads();
        const int nc = c + STAGES - 1;
        if (nc < NCC) loadChunk(nc, nc & (STAGES - 1));
        else CP_COMMIT();
        compute(c & (STAGES - 1));
    }

    #pragma unroll
    for (int mt = 0; mt < 2; ++mt) {
        #pragma unroll
        for (int half = 0; half < 2; ++half) {
            const int m = m0 + wm + mt * 16 + gr + half * 8;
            const float rs = (EPI == 1) ? extra[m] : 0.f;
            #pragma unroll
            for (int nt = 0; nt < 8; ++nt) {
                const int n = n0 + wn + nt * 8 + gc * 2;
                float v0 = acc[mt][nt][half * 2 + 0];
                float v1 = acc[mt][nt][half * 2 + 1];
                if (ADD) {
                    const float2 ad = *reinterpret_cast<const float2*>(addC + (size_t)m * ldc + n);
                    v0 += ad.x; v1 += ad.y;
                }
                const float bb0 = bias ? bias[n]     : 0.f;
                const float bb1 = bias ? bias[n + 1] : 0.f;
                if (EPI == 0)      { v0 = v0 * alpha + bb0;  v1 = v1 * alpha + bb1; }
                else if (EPI == 1) { v0 = v0 * rs + bb0;     v1 = v1 * rs + bb1; }
                else if (EPI == 2) {
                    const float* g = extra + (size_t)(m >> 10) * CTX + n;
                    v0 = (v0 + bb0) * g[0];
                    v1 = (v1 + bb1) * g[1];
                } else {
                    const float* g = extra + (size_t)m * ldc + n;
                    v0 = (v0 + bb0) * g[0];
                    v1 = (v1 + bb1) * g[1];
                }
                if (RND) { v0 = rna_tf32(v0); v1 = rna_tf32(v1); }
                *reinterpret_cast<float2*>(Cbase + (size_t)m * ldc + n) = make_float2(v0, v1);
            }
        }
    }
}

// ---- masked-row message fill ----
__global__ void msg_fill_kernel(const float* __restrict__ v, const int* __restrict__ ennum,
                                float* __restrict__ msg)
{
    const int b = blockIdx.y;
    const int d = blockIdx.x * 256 + threadIdx.x;
    const int en = ennum[b];
    if (en >= NENT) return;
    const float* vb = v + (size_t)b * NENT * CTX + d;
    float s = 0.f;
    #pragma unroll 4
    for (int kk = 0; kk < NENT; ++kk) s += vb[(size_t)kk * CTX];
    const float mean = rna_tf32(s * (1.f / NENT));
    float* mb = msg + (size_t)b * NENT * CTX + d;
    for (int m = en; m < NENT; ++m) mb[(size_t)m * CTX] = mean;
}

// ---- transpose, optional tf32 round ----
template<bool RND>
__global__ void transpose_kernel(const float* __restrict__ in, float* __restrict__ out,
                                 int R, int C, size_t sIn, size_t sOut)
{
    __shared__ float tile[32][33];
    const int z = blockIdx.z;
    in  += (size_t)z * sIn;
    out += (size_t)z * sOut;
    const int r0 = blockIdx.y * 32, c0 = blockIdx.x * 32;
    #pragma unroll
    for (int i = threadIdx.y; i < 32; i += 8) {
        float x = in[(size_t)(r0 + i) * C + c0 + threadIdx.x];
        tile[i][threadIdx.x] = RND ? rna_tf32(x) : x;
    }
    __syncthreads();
    #pragma unroll
    for (int i = threadIdx.y; i < 32; i += 8)
        out[(size_t)(c0 + i) * R + r0 + threadIdx.x] = tile[threadIdx.x][i];
}

// ---- fused row inv-norm + tf32-rounded copy ----
__global__ void rownorm_round_kernel(const float* __restrict__ img, float* __restrict__ invn,
                                     float* __restrict__ imgr)
{
    const int m = blockIdx.x;
    const float4* r4 = reinterpret_cast<const float4*>(img + (size_t)m * DFEAT);
    float4* o4 = reinterpret_cast<float4*>(imgr + (size_t)m * DFEAT);
    const int tid = threadIdx.x;
    float s = 0.f;
    for (int i = tid; i < DFEAT / 4; i += 256) {
        float4 u = r4[i];
        s = fmaf(u.x, u.x, s); s = fmaf(u.y, u.y, s);
        s = fmaf(u.z, u.z, s); s = fmaf(u.w, u.w, s);
        u.x = rna_tf32(u.x); u.y = rna_tf32(u.y);
        u.z = rna_tf32(u.z); u.w = rna_tf32(u.w);
        o4[i] = u;
    }
    __shared__ float red[256];
    red[tid] = s; __syncthreads();
    for (int o = 128; o > 0; o >>= 1) { if (tid < o) red[tid] += red[tid + o]; __syncthreads(); }
    if (tid == 0) invn[m] = 1.f / fmaxf(sqrtf(red[0]), 1e-12f);
}

__global__ void ctx_init_kernel(const float* __restrict__ initMem, float* __restrict__ xctx)
{
    const size_t i = (size_t)blockIdx.x * blockDim.x + threadIdx.x;
    xctx[i] = rna_tf32(initMem[i & (CTX - 1)]);
}

// ---- fast batch-32 linear: out[b][j] = dot(in[b], wT[j]) + bias[j] ----
// wT is [DOUT, CMD] row-major (k contiguous), fp32 (NOT rounded).
// grid: (DOUT/32, BB), block 256 (8 warps, 4 outputs each)
template<bool ELU>
__global__ void small_linear_fast(const float* __restrict__ in, const float* __restrict__ wT,
                                  const float* __restrict__ bias, float* __restrict__ out)
{
    const int b = blockIdx.y;
    const int jb = blockIdx.x * 32;
    const int tid = threadIdx.x;
    const int wid = tid >> 5, lane = tid & 31;
    __shared__ float x[CMD];
    for (int d = tid; d < CMD; d += 256) x[d] = in[b * CMD + d];
    __syncthreads();
    #pragma unroll
    for (int jj = 0; jj < 4; ++jj) {
        const int j = jb + wid * 4 + jj;
        const float* w = wT + (size_t)j * CMD;
        float acc = 0.f;
        #pragma unroll
        for (int i = 0; i < CMD / 32; ++i)
            acc = fmaf(x[lane + 32 * i], w[lane + 32 * i], acc);
        #pragma unroll
        for (int o = 16; o > 0; o >>= 1)
            acc += __shfl_down_sync(0xFFFFFFFFu, acc, o);
        if (lane == 0) {
            acc += bias[j];
            if (ELU) acc = (acc > 0.f) ? acc : expm1f(acc);
            out[b * CMD + j] = acc;
        }
    }
}

// ---- fast textual command: 1024-thread block per batch ----
__global__ __launch_bounds__(1024)
void text_cmd_fast(const float* __restrict__ qcmd, const float* __restrict__ lstm,
                   const float* __restrict__ c2l_w, const float* __restrict__ c2l_b,
                   const int* __restrict__ qlen, float* __restrict__ cmd)
{
    const int b = blockIdx.x;
    const int tid = threadIdx.x;
    const int wid = tid >> 5, lane = tid & 31;
    __shared__ float e[CMD];
    __shared__ float att[LQL];
    __shared__ float red[128];
    __shared__ float smx, ssum;

    if (tid < CMD) e[tid] = qcmd[b * CMD + tid] * c2l_w[tid];
    __syncthreads();

    // warp-per-l attention logits (32 warps x 4 l's)
    const int en = qlen[b];
    #pragma unroll
    for (int li = 0; li < 4; ++li) {
        const int l = wid + li * 32;
        const float* L = lstm + ((size_t)b * LQL + l) * CMD;
        float acc = 0.f;
        #pragma unroll
        for (int i = 0; i < CMD / 32; ++i)
            acc = fmaf(L[lane + 32 * i], e[lane + 32 * i], acc);
        #pragma unroll
        for (int o = 16; o > 0; o >>= 1)
            acc += __shfl_down_sync(0xFFFFFFFFu, acc, o);
        if (lane == 0) att[l] = (l >= en) ? NEGV : (acc + c2l_b[0]);
    }
    __syncthreads();

    // softmax over 128
    if (tid < 128) red[tid] = att[tid];
    __syncthreads();
    for (int o = 64; o > 0; o >>= 1) {
        if (tid < o) red[tid] = fmaxf(red[tid], red[tid + o]);
        __syncthreads();
    }
    if (tid == 0) smx = red[0];
    __syncthreads();
    float ev = 0.f;
    if (tid < 128) { ev = expf(att[tid] - smx); red[tid] = ev; }
    __syncthreads();
    for (int o = 64; o > 0; o >>= 1) {
        if (tid < o) red[tid] += red[tid + o];
        __syncthreads();
    }
    if (tid == 0) ssum = red[0];
    __syncthreads();
    if (tid < 128) att[tid] = ev / ssum;
    __syncthreads();

    // cmd[d] = sum_l att[l] * lstm[b][l][d]
    if (tid < CMD) {
        float acc = 0.f;
        const float* L = lstm + (size_t)b * LQL * CMD + tid;
        #pragma unroll 4
        for (int l = 0; l < LQL; ++l)
            acc = fmaf(att[l], L[(size_t)l * CMD], acc);
        cmd[b * CMD + tid] = acc;
    }
}

// masked row softmax (in place)
__global__ void attn_softmax_kernel(float* __restrict__ score, const int* __restrict__ entity_num)
{
    const int row = blockIdx.x;
    const int b = row >> 10;
    const int n = row & 1023;
    const int en = entity_num[b];
    if (n >= en) return;
    float* s = score + (size_t)row * NENT;
    const int tid = threadIdx.x;

    float v[4];
    float mx = -3.4e38f;
    #pragma unroll
    for (int j = 0; j < 4; j++) {
        const int m = tid + j * 256;
        float x = s[m];
        x = (m >= en) ? NEGV : x;
        v[j] = x;
        mx = fmaxf(mx, x);
    }
    __shared__ float red[256];
    red[tid] = mx; __syncthreads();
    for (int o = 128; o > 0; o >>= 1) { if (tid < o) red[tid] = fmaxf(red[tid], red[tid + o]); __syncthreads(); }
    mx = red[0];
    __syncthreads();

    float sum = 0.f;
    #pragma unroll
    for (int j = 0; j < 4; j++) { v[j] = expf(v[j] - mx); sum += v[j]; }
    red[tid] = sum; __syncthreads();
    for (int o = 128; o > 0; o >>= 1) { if (tid < o) red[tid] += red[tid + o]; __syncthreads(); }
    const float inv = 1.f / red[0];

    #pragma unroll
    for (int j = 0; j < 4; j++) s[tid + j * 256] = rna_tf32(v[j] * inv);
}

// ---------------- launch ----------------
template<typename T> static float* symaddr(T& sym) {
    void* p = nullptr;
    cudaGetSymbolAddress(&p, sym);
    return (float*)p;
}

extern "C" void kernel_launch(void* const* d_in, const int* in_sizes, int n_in,
                              void* d_out, int out_size)
{
    const float* images    = (const float*)d_in[0];
    const float* q_enc     = (const float*)d_in[1];
    const float* lstm      = (const float*)d_in[2];
    const int*   q_length  = (const int*)  d_in[3];
    const int*   ent_num   = (const int*)  d_in[4];
    const float* initKB_w  = (const float*)d_in[5];
    const float* initKB_b  = (const float*)d_in[6];
    const float* initMem   = (const float*)d_in[7];
    const float* qInput_w  = (const float*)d_in[8];
    const float* qInput_b  = (const float*)d_in[9];
    const float* qInput2_w = (const float*)d_in[10];
    const float* qInput2_b = (const float*)d_in[11];
    const float* c2l_w     = (const float*)d_in[12];
    const float* c2l_b     = (const float*)d_in[13];
    const float* pxl_w     = (const float*)d_in[14];
    const float* pxl_b     = (const float*)d_in[15];
    const float* pxc_w     = (const float*)d_in[16];
    const float* pxc_b     = (const float*)d_in[17];
    const float* qry_w     = (const float*)d_in[18];
    const float* qry_b     = (const float*)d_in[19];
    const float* key_w     = (const float*)d_in[20];
    const float* key_b     = (const float*)d_in[21];
    const float* val_w     = (const float*)d_in[22];
    const float* val_b     = (const float*)d_in[23];
    const float* pk_w      = (const float*)d_in[24];
    const float* pk_b      = (const float*)d_in[25];
    const float* pv_w      = (const float*)d_in[26];
    const float* pv_b      = (const float*)d_in[27];
    const float* mu_w      = (const float*)d_in[28];
    const float* mu_b      = (const float*)d_in[29];
    const float* ck_w      = (const float*)d_in[30];
    const float* ck_b      = (const float*)d_in[31];

    float* imgr  = symaddr(g_imgr);
    float* invn  = symaddr(g_invnorm);
    float* xloc  = symaddr(g_xloc);
    float* xctxA = symaddr(g_xctx0);
    float* xctxB = symaddr(g_xctx1);
    float* prjl  = symaddr(g_projloc);
    float* pp    = symaddr(g_pp);
    float* q     = symaddr(g_q);
    float* k     = symaddr(g_k);
    float* v     = symaddr(g_v);
    float* vT    = symaddr(g_vT);
    float* msg   = symaddr(g_msg);
    float* qL    = symaddr(g_qL);
    float* kL    = symaddr(g_kL);
    float* vL    = symaddr(g_vL);
    float* score = symaddr(g_score);
    float* qbase = symaddr(g_qbase);
    float* qcmd  = symaddr(g_qcmd);
    float* cmd   = symaddr(g_cmd);
    float* pkg   = symaddr(g_pkg);
    float* pvg   = symaddr(g_pvg);
    float* wIKB  = symaddr(g_wT_ikb);
    float* wPXL  = symaddr(g_wT_pxl);
    float* wPXC  = symaddr(g_wT_pxc);
    float* wQRY  = symaddr(g_wT_qry);
    float* wKEY  = symaddr(g_wT_key);
    float* wVAL  = symaddr(g_wT_val);
    float* wMU   = symaddr(g_wT_mu);
    float* wCK   = symaddr(g_wT_ck);
    float* wQIN  = symaddr(g_wT_qin);
    float* wQIN2 = symaddr(g_wT_qin2);
    float* wPK   = symaddr(g_wT_pk);
    float* wPV   = symaddr(g_wT_pv);

    cudaFuncSetAttribute(gemm_mma<1,0,false,false,0>, cudaFuncAttributeMaxDynamicSharedMemorySize, SMEM_DYN);
    cudaFuncSetAttribute(gemm_mma<1,1,true ,false,0>, cudaFuncAttributeMaxDynamicSharedMemorySize, SMEM_DYN);
    cudaFuncSetAttribute(gemm_mma<1,3,true ,false,0>, cudaFuncAttributeMaxDynamicSharedMemorySize, SMEM_DYN);
    cudaFuncSetAttribute(gemm_mma<1,0,false,false,1>, cudaFuncAttributeMaxDynamicSharedMemorySize, SMEM_DYN);
    cudaFuncSetAttribute(gemm_mma<1,0,true ,false,2>, cudaFuncAttributeMaxDynamicSharedMemorySize, SMEM_DYN);
    cudaFuncSetAttribute(gemm_mma<2,0,true ,true ,0>, cudaFuncAttributeMaxDynamicSharedMemorySize, SMEM_DYN);
    cudaFuncSetAttribute(gemm_mma<2,2,true ,true ,0>, cudaFuncAttributeMaxDynamicSharedMemorySize, SMEM_DYN);
    cudaFuncSetAttribute(gemm_mma<2,0,true ,false,0>, cudaFuncAttributeMaxDynamicSharedMemorySize, SMEM_DYN);
    cudaFuncSetAttribute(gemm_mma<2,0,false,false,0>, cudaFuncAttributeMaxDynamicSharedMemorySize, SMEM_DYN);

    const float scale = 0.044194173824159216f;   // 1/sqrt(512)
    const dim3 tdim(32, 8);
    const dim3 gridMain(CTX / BNm, MROWS / BMm, 1);
    const dim3 gridScore(NENT / BNm, NENT / BMm, BB);
    const dim3 gridMsg(CTX / BNm, NENT / BMm, BB);
    const dim3 gridSL(CMD / 32, BB);

    // --- launch order arranged so ncu (-s 5 -c 1) lands on the initKB GEMM ---
    transpose_kernel<true ><<<dim3(CTX/32, DFEAT/32, 1), tdim>>>(initKB_w, wIKB, DFEAT, CTX, 0, 0); // 0
    rownorm_round_kernel<<<MROWS, 256>>>(images, invn, imgr);                                        // 1
    ctx_init_kernel<<<(MROWS * CTX) / 256, 256>>>(initMem, xctxA);                                   // 2
    transpose_kernel<false><<<dim3(CMD/32, CMD/32, 1), tdim>>>(qInput_w, wQIN, CMD, CMD, 0, 0);      // 3
    small_linear_fast<true><<<gridSL, 256>>>(q_enc, wQIN, qInput_b, qbase);                          // 4
    // 5: x_loc = normalize(images) @ initKB_w + b  <-- ncu target
    gemm_mma<1,1,true,false,0><<<gridMain, 256, SMEM_DYN>>>(
        imgr, nullptr, nullptr, wIKB, initKB_b, invn, nullptr, nullptr, xloc,
        DFEAT, DFEAT, DFEAT, CTX, 0, 0, 0, 1.f);

    // remaining weight transposes (tf32-rounded, feed MMA)
    transpose_kernel<true><<<dim3(CTX/32, CTX/32, 1),   tdim>>>(pxl_w, wPXL, CTX,   CTX, 0, 0);
    transpose_kernel<true><<<dim3(CTX/32, CTX/32, 1),   tdim>>>(pxc_w, wPXC, CTX,   CTX, 0, 0);
    transpose_kernel<true><<<dim3(CTX/32, 3*CTX/32, 1), tdim>>>(qry_w, wQRY, 3*CTX, CTX, 0, 0);
    transpose_kernel<true><<<dim3(CTX/32, 3*CTX/32, 1), tdim>>>(key_w, wKEY, 3*CTX, CTX, 0, 0);
    transpose_kernel<true><<<dim3(CTX/32, 3*CTX/32, 1), tdim>>>(val_w, wVAL, 3*CTX, CTX, 0, 0);
    transpose_kernel<true><<<dim3(CTX/32, 2*CTX/32, 1), tdim>>>(mu_w,  wMU,  2*CTX, CTX, 0, 0);
    transpose_kernel<true><<<dim3(CTX/32, 2*CTX/32, 1), tdim>>>(ck_w,  wCK,  2*CTX, CTX, 0, 0);
    // small-linear weights (fp32, not rounded); qInput2 batched over t
    transpose_kernel<false><<<dim3(CMD/32, CMD/32, TT), tdim>>>(qInput2_w, wQIN2, CMD, CMD,
                                                                (size_t)CMD*CMD, (size_t)CMD*CMD);
    transpose_kernel<false><<<dim3(CTX/32, CMD/32, 1), tdim>>>(pk_w, wPK, CMD, CTX, 0, 0);
    transpose_kernel<false><<<dim3(CTX/32, CMD/32, 1), tdim>>>(pv_w, wPV, CMD, CTX, 0, 0);

    // ---- iteration-invariant hoists ----
    gemm_mma<1,0,false,false,0><<<gridMain, 256, SMEM_DYN>>>(
        xloc, nullptr, nullptr, wPXL, pxl_b, nullptr, nullptr, nullptr, prjl,
        CTX, CTX, CTX, CTX, 0, 0, 0, 1.f);
    gemm_mma<1,0,false,false,0><<<gridMain, 256, SMEM_DYN>>>(
        xloc, nullptr, nullptr, wQRY, nullptr, nullptr, nullptr, nullptr, qL,
        CTX, CTX, 3*CTX, CTX, 0, 0, 0, 1.f);
    gemm_mma<1,0,false,false,0><<<gridMain, 256, SMEM_DYN>>>(
        xloc, nullptr, nullptr, wKEY, nullptr, nullptr, nullptr, nullptr, kL,
        CTX, CTX, 3*CTX, CTX, 0, 0, 0, 1.f);
    gemm_mma<1,0,false,false,0><<<gridMain, 256, SMEM_DYN>>>(
        xloc, nullptr, nullptr, wVAL, nullptr, nullptr, nullptr, nullptr, vL,
        CTX, CTX, 3*CTX, CTX, 0, 0, 0, 1.f);

    float* xc = xctxA;
    float* xn = xctxB;
    for (int t = 0; t < TT; t++) {
        small_linear_fast<false><<<gridSL, 256>>>(qbase, wQIN2 + (size_t)t * CMD * CMD,
                                                  qInput2_b + (size_t)t * CMD, qcmd);
        text_cmd_fast<<<BB, 1024>>>(qcmd, lstm, c2l_w, c2l_b, q_length, cmd);
        small_linear_fast<false><<<gridSL, 256>>>(cmd, wPK, pk_b, pkg);
        small_linear_fast<false><<<gridSL, 256>>>(cmd, wPV, pv_b, pvg);

        // pp = (x_ctx @ pxc + b) * proj_loc
        gemm_mma<1,3,true,false,0><<<gridMain, 256, SMEM_DYN>>>(
            xc, nullptr, nullptr, wPXC, pxc_b, prjl, nullptr, nullptr, pp,
            CTX, CTX, CTX, CTX, 0, 0, 0, 1.f);

        // q/k/v: K=1024 over [x_ctx | pp] + hoisted x_loc partial
        gemm_mma<2,0,true,true,0><<<gridMain, 256, SMEM_DYN>>>(
            xc, pp, nullptr, wQRY + CTX, qry_b, nullptr, qL, nullptr, q,
            2*CTX, 0, 3*CTX, CTX, 0, 0, 0, 1.f);
        gemm_mma<2,2,true,true,0><<<gridMain, 256, SMEM_DYN>>>(
            xc, pp, nullptr, wKEY + CTX, key_b, pkg, kL, nullptr, k,
            2*CTX, 0, 3*CTX, CTX, 0, 0, 0, 1.f);
        gemm_mma<2,2,true,true,0><<<gridMain, 256, SMEM_DYN>>>(
            xc, pp, nullptr, wVAL + CTX, val_b, pvg, vL, nullptr, v,
            2*CTX, 0, 3*CTX, CTX, 0, 0, 0, 1.f);

        // score[b] = scale * q[b] @ k[b]^T — live tiles only
        gemm_mma<1,0,false,false,1><<<gridScore, 256, SMEM_DYN>>>(
            q, nullptr, nullptr, k, nullptr, nullptr, nullptr, ent_num, score,
            CTX, CTX, CTX, NENT,
            (size_t)NENT * CTX, (size_t)NENT * CTX, (size_t)NENT * NENT, scale);

        attn_softmax_kernel<<<MROWS, 256>>>(score, ent_num);

        // vT[b] = v[b]^T (tf32-rounded)
        transpose_kernel<true><<<dim3(CTX/32, NENT/32, BB), tdim>>>(
            v, vT, NENT, CTX, (size_t)NENT * CTX, (size_t)CTX * NENT);

        // message[b] = prob[b] @ v[b] — live rows, truncated K
        gemm_mma<1,0,true,false,2><<<gridMsg, 256, SMEM_DYN>>>(
            score, nullptr, nullptr, vT, nullptr, nullptr, nullptr, ent_num, msg,
            NENT, NENT, NENT, CTX,
            (size_t)NENT * NENT, (size_t)CTX * NENT, (size_t)NENT * CTX, 1.f);
        msg_fill_kernel<<<dim3(CTX / 256, BB), 256>>>(v, ent_num, msg);

        // x_ctx' = [x_ctx | message] @ mu + b
        gemm_mma<2,0,true,false,0><<<gridMain, 256, SMEM_DYN>>>(
            xc, msg, nullptr, wMU, mu_b, nullptr, nullptr, nullptr, xn,
            2*CTX, 0, 2*CTX, CTX, 0, 0, 0, 1.f);
        float* tmp = xc; xc = xn; xn = tmp;
    }

    // out = [x_loc | x_ctx] @ ck + b
    gemm_mma<2,0,false,false,0><<<gridMain, 256, SMEM_DYN>>>(
        xloc, xc, nullptr, wCK, ck_b, nullptr, nullptr, nullptr, (float*)d_out,
        2*CTX, 0, 2*CTX, CTX, 0, 0, 0, 1.f);
}

// round 9
// speedup vs baseline: 5.4861x; 1.1170x over previous
#include <cuda_runtime.h>
#include <math.h>
#include <stdint.h>

#define BB     32
#define NENT   1024
#define LQL    128
#define DFEAT  2112
#define CTX    512
#define CMD    512
#define TT     4
#define MROWS  (BB*NENT)
#define NEGV   (-1e30f)

// ---- mma.sync GEMM tiling ----
#define BMm 128
#define BNm 128
#define BKm 16
#define STAGES 4
#define SROW 20
#define STAGE_F (2 * BMm * SROW)
#define TILE_F  (BMm * SROW)
#define SMEM_DYN (STAGES * STAGE_F * 4)

// ---- scratch ----
__device__ float g_imgr   [(size_t)MROWS*DFEAT];
__device__ float g_invnorm[MROWS];
__device__ float g_xloc   [(size_t)MROWS*CTX];
__device__ float g_xctx0  [(size_t)MROWS*CTX];
__device__ float g_xctx1  [(size_t)MROWS*CTX];
__device__ float g_projloc[(size_t)MROWS*CTX];
__device__ float g_pp     [(size_t)MROWS*CTX];
__device__ float g_q      [(size_t)MROWS*CTX];
__device__ float g_k      [(size_t)MROWS*CTX];
__device__ float g_v      [(size_t)MROWS*CTX];
__device__ float g_vT     [(size_t)MROWS*CTX];
__device__ float g_msg    [(size_t)MROWS*CTX];
__device__ float g_qL     [(size_t)MROWS*CTX];
__device__ float g_kL     [(size_t)MROWS*CTX];
__device__ float g_vL     [(size_t)MROWS*CTX];
__device__ float g_score  [(size_t)BB*NENT*NENT];
__device__ float g_qbase  [BB*CMD];
__device__ float g_qcmd   [BB*CMD];
__device__ float g_cmd    [BB*CMD];
__device__ float g_pkg    [BB*CTX];
__device__ float g_pvg    [BB*CTX];
__device__ float g_msgm   [BB*CTX];     // per-batch mean(v)
__device__ float g_xcm    [BB*CTX];     // per-batch masked-row x_ctx state
__device__ float g_wT_ikb[(size_t)CTX*DFEAT];
__device__ float g_wT_pxl[(size_t)CTX*CTX];
__device__ float g_wT_pxc[(size_t)CTX*CTX];
__device__ float g_wT_qry[(size_t)CTX*3*CTX];
__device__ float g_wT_key[(size_t)CTX*3*CTX];
__device__ float g_wT_val[(size_t)CTX*3*CTX];
__device__ float g_wT_mu [(size_t)CTX*2*CTX];
__device__ float g_wT_ck [(size_t)CTX*2*CTX];
__device__ float g_wT_qin [(size_t)CMD*CMD];
__device__ float g_wT_qin2[(size_t)TT*CMD*CMD];
__device__ float g_wT_pk  [(size_t)CMD*CTX];
__device__ float g_wT_pv  [(size_t)CMD*CTX];

__device__ __forceinline__ float rna_tf32(float f) {
    uint32_t r; asm("cvt.rna.tf32.f32 %0, %1;" : "=r"(r) : "f"(f));
    return __uint_as_float(r);
}
__device__ __forceinline__ uint32_t smem_u32(const void* p) {
    uint32_t a;
    asm("{ .reg .u64 t; cvta.to.shared.u64 t, %1; cvt.u32.u64 %0, t; }" : "=r"(a) : "l"(p));
    return a;
}
__device__ __forceinline__ void cp_async16(uint32_t saddr, const void* gptr) {
    asm volatile("cp.async.cg.shared.global [%0], [%1], 16;" :: "r"(saddr), "l"(gptr));
}
#define CP_COMMIT() asm volatile("cp.async.commit_group;" ::: "memory")
#define CP_WAIT2()  asm volatile("cp.async.wait_group 2;" ::: "memory")

__device__ __forceinline__ void ldsm_x4(uint32_t addr, uint32_t& r0, uint32_t& r1,
                                        uint32_t& r2, uint32_t& r3)
{
    asm volatile("ldmatrix.sync.aligned.m8n8.x4.shared.b16 {%0,%1,%2,%3}, [%4];"
                 : "=r"(r0), "=r"(r1), "=r"(r2), "=r"(r3) : "r"(addr));
}

__device__ __forceinline__ void mma_m16n8k8(float* d,
    uint32_t a0, uint32_t a1, uint32_t a2, uint32_t a3,
    uint32_t b0, uint32_t b1)
{
    asm volatile(
        "mma.sync.aligned.m16n8k8.row.col.f32.tf32.tf32.f32 "
        "{%0,%1,%2,%3}, {%4,%5,%6,%7}, {%8,%9}, {%0,%1,%2,%3};"
        : "+f"(d[0]), "+f"(d[1]), "+f"(d[2]), "+f"(d[3])
        : "r"(a0), "r"(a1), "r"(a2), "r"(a3), "r"(b0), "r"(b1));
}

// ---------------- tensor-core GEMM via mma.sync (tf32) ----------------
// MASK 0: none
//      1 (score, z=batch): skip tile if m0>=en || n0>=en
//      2 (message, z=batch): skip tile if m0>=en; truncate K at ceil(en/BKm)
//      3 (row-masked, z=1, batch=m0>>10): skip tile if (m0&1023)>=en
template<int NSRC, int EPI, bool RND, bool ADD, int MASK>
__global__ __launch_bounds__(256, 2)
void gemm_mma(const float* __restrict__ A0, const float* __restrict__ A1,
              const float* __restrict__ A2, const float* __restrict__ Bt,
              const float* __restrict__ bias, const float* __restrict__ extra,
              const float* __restrict__ addC, const int* __restrict__ ennum,
              float* __restrict__ C,
              int K, int lda, int ldb, int ldc,
              size_t sA, size_t sB, size_t sC, float alpha)
{
    extern __shared__ float smem[];
    const uint32_t sbase = smem_u32(smem);

    const int tid = threadIdx.x;
    const int z = blockIdx.z;
    const int m0 = blockIdx.y * BMm;
    const int n0 = blockIdx.x * BNm;

    int Keff = K;
    if (MASK == 1 || MASK == 2) {
        const int en = ennum[z];
        if (m0 >= en) return;
        if (MASK == 1 && n0 >= en) return;
        if (MASK == 2) { const int kc = ((en + BKm - 1) / BKm) * BKm; Keff = kc < K ? kc : K; }
    } else if (MASK == 3) {
        const int en = ennum[m0 >> 10];
        if ((m0 & 1023) >= en) return;
    }

    const float* Abase = A0 + (size_t)z * sA;
    const float* Bbase = Bt + (size_t)z * sB;
    float* Cbase = C + (size_t)z * sC;

    const int wid = tid >> 5, lane = tid & 31;
    const int wm = (wid & 3) * 32;
    const int wn = (wid >> 2) * 64;
    const int gr = lane >> 2;
    const int gc = lane & 3;

    const int lr = lane & 7, lg = lane >> 3;
    const int arow  = wm + lr + (lg & 1) * 8;
    const int akoff = (lg >> 1) * 4;
    const int brow  = wn + lr + (lg >> 1) * 8;
    const int bkoff = (lg & 1) * 4;

    const int prow0 = tid >> 2;
    const int pkq   = (tid & 3) * 4;

    float acc[2][8][4] = {};
    const int NCC = Keff / BKm;

    auto loadChunk = [&](int c, int st) {
        const int k0 = c * BKm;
        const float* Ap; int al, ak;
        if (NSRC == 1) { Ap = Abase; al = lda; ak = k0; }
        else {
            const int src = k0 >> 9;
            Ap = (src == 0) ? A0 : ((src == 1) ? A1 : A2);
            al = CTX; ak = k0 & (CTX - 1);
        }
        const uint32_t sa = sbase + (uint32_t)(st * STAGE_F) * 4;
        const uint32_t sb = sa + (uint32_t)TILE_F * 4;
        #pragma unroll
        for (int t = 0; t < 2; ++t) {
            const int row = prow0 + t * 64;
            cp_async16(sa + (uint32_t)(row * SROW + pkq) * 4,
                       Ap + (size_t)(m0 + row) * al + ak + pkq);
            cp_async16(sb + (uint32_t)(row * SROW + pkq) * 4,
                       Bbase + (size_t)(n0 + row) * ldb + k0 + pkq);
        }
        CP_COMMIT();
    };

    auto compute = [&](int st) {
        const uint32_t SAu = sbase + (uint32_t)(st * STAGE_F) * 4;
        const uint32_t SBu = SAu + (uint32_t)TILE_F * 4;
        #pragma unroll
        for (int kk = 0; kk < BKm; kk += 8) {
            uint32_t b[8][2];
            #pragma unroll
            for (int ntp = 0; ntp < 4; ++ntp) {
                const uint32_t addr = SBu +
                    (uint32_t)(((brow + ntp * 16) * SROW) + kk + bkoff) * 4;
                ldsm_x4(addr, b[2*ntp][0], b[2*ntp][1], b[2*ntp+1][0], b[2*ntp+1][1]);
            }
            #pragma unroll
            for (int mt = 0; mt < 2; ++mt) {
                uint32_t a0, a1, a2, a3;
                const uint32_t addr = SAu +
                    (uint32_t)(((arow + mt * 16) * SROW) + kk + akoff) * 4;
                ldsm_x4(addr, a0, a1, a2, a3);
                #pragma unroll
                for (int nt = 0; nt < 8; ++nt)
                    mma_m16n8k8(acc[mt][nt], a0, a1, a2, a3, b[nt][0], b[nt][1]);
            }
        }
    };

    #pragma unroll
    for (int s = 0; s < STAGES - 1; ++s) {
        if (s < NCC) loadChunk(s, s);
        else CP_COMMIT();
    }
    for (int c = 0; c < NCC; ++c) {
        CP_WAIT2();
        __syncthreads();
        const int nc = c + STAGES - 1;
        if (nc < NCC) loadChunk(nc, nc & (STAGES - 1));
        else CP_COMMIT();
        compute(c & (STAGES - 1));
    }

    #pragma unroll
    for (int mt = 0; mt < 2; ++mt) {
        #pragma unroll
        for (int half = 0; half < 2; ++half) {
            const int m = m0 + wm + mt * 16 + gr + half * 8;
            const float rs = (EPI == 1) ? extra[m] : 0.f;
            #pragma unroll
            for (int nt = 0; nt < 8; ++nt) {
                const int n = n0 + wn + nt * 8 + gc * 2;
                float v0 = acc[mt][nt][half * 2 + 0];
                float v1 = acc[mt][nt][half * 2 + 1];
                if (ADD) {
                    const float2 ad = *reinterpret_cast<const float2*>(addC + (size_t)m * ldc + n);
                    v0 += ad.x; v1 += ad.y;
                }
                const float bb0 = bias ? bias[n]     : 0.f;
                const float bb1 = bias ? bias[n + 1] : 0.f;
                if (EPI == 0)      { v0 = v0 * alpha + bb0;  v1 = v1 * alpha + bb1; }
                else if (EPI == 1) { v0 = v0 * rs + bb0;     v1 = v1 * rs + bb1; }
                else if (EPI == 2) {
                    const float* g = extra + (size_t)(m >> 10) * CTX + n;
                    v0 = (v0 + bb0) * g[0];
                    v1 = (v1 + bb1) * g[1];
                } else {
                    const float* g = extra + (size_t)m * ldc + n;
                    v0 = (v0 + bb0) * g[0];
                    v1 = (v1 + bb1) * g[1];
                }
                if (RND) { v0 = rna_tf32(v0); v1 = rna_tf32(v1); }
                *reinterpret_cast<float2*>(Cbase + (size_t)m * ldc + n) = make_float2(v0, v1);
            }
        }
    }
}

// ---- per-batch mean of v rows -> msgm[b][d] ----
__global__ void mean_v_kernel(const float* __restrict__ v, const int* __restrict__ ennum,
                              float* __restrict__ msgm)
{
    const int b = blockIdx.y;
    const int d = blockIdx.x * 256 + threadIdx.x;
    if (ennum[b] >= NENT) return;
    const float* vb = v + (size_t)b * NENT * CTX + d;
    float s = 0.f;
    #pragma unroll 4
    for (int kk = 0; kk < NENT; ++kk) s += vb[(size_t)kk * CTX];
    msgm[b * CTX + d] = rna_tf32(s * (1.f / NENT));
}

// ---- masked-row x_ctx update + broadcast ----
// y = rna([xcm | msgm] @ mu + b); xcm <- y; xn[b, m>=en, :] <- y
__global__ __launch_bounds__(256)
void ctx_bcast_kernel(const float* __restrict__ msgm, const float* __restrict__ wMU,
                      const float* __restrict__ mu_b, const int* __restrict__ ennum,
                      float* __restrict__ xcm, float* __restrict__ xn)
{
    const int b = blockIdx.x;
    const int en = ennum[b];
    if (en >= NENT) return;
    const int tid = threadIdx.x;
    const int wid = tid >> 5, lane = tid & 31;
    __shared__ float x[2 * CTX];
    __shared__ float y[CTX];
    for (int d = tid; d < CTX; d += 256) {
        x[d] = xcm[b * CTX + d];
        x[CTX + d] = msgm[b * CTX + d];
    }
    __syncthreads();
    for (int j = wid; j < CTX; j += 8) {
        const float* w = wMU + (size_t)j * (2 * CTX);
        float acc = 0.f;
        #pragma unroll
        for (int i = 0; i < (2 * CTX) / 32; ++i)
            acc = fmaf(x[lane + 32 * i], w[lane + 32 * i], acc);
        #pragma unroll
        for (int o = 16; o > 0; o >>= 1)
            acc += __shfl_down_sync(0xFFFFFFFFu, acc, o);
        if (lane == 0) y[j] = rna_tf32(acc + mu_b[j]);
    }
    __syncthreads();
    for (int d = tid; d < CTX; d += 256) xcm[b * CTX + d] = y[d];
    float* base = xn + (size_t)b * NENT * CTX;
    for (int m = en; m < NENT; ++m)
        for (int d = tid; d < CTX; d += 256)
            base[(size_t)m * CTX + d] = y[d];
}

// ---- transpose, optional tf32 round ----
template<bool RND>
__global__ void transpose_kernel(const float* __restrict__ in, float* __restrict__ out,
                                 int R, int C, size_t sIn, size_t sOut)
{
    __shared__ float tile[32][33];
    const int z = blockIdx.z;
    in  += (size_t)z * sIn;
    out += (size_t)z * sOut;
    const int r0 = blockIdx.y * 32, c0 = blockIdx.x * 32;
    #pragma unroll
    for (int i = threadIdx.y; i < 32; i += 8) {
        float x = in[(size_t)(r0 + i) * C + c0 + threadIdx.x];
        tile[i][threadIdx.x] = RND ? rna_tf32(x) : x;
    }
    __syncthreads();
    #pragma unroll
    for (int i = threadIdx.y; i < 32; i += 8)
        out[(size_t)(c0 + i) * R + r0 + threadIdx.x] = tile[threadIdx.x][i];
}

// ---- fused row inv-norm + tf32-rounded copy ----
__global__ void rownorm_round_kernel(const float* __restrict__ img, float* __restrict__ invn,
                                     float* __restrict__ imgr)
{
    const int m = blockIdx.x;
    const float4* r4 = reinterpret_cast<const float4*>(img + (size_t)m * DFEAT);
    float4* o4 = reinterpret_cast<float4*>(imgr + (size_t)m * DFEAT);
    const int tid = threadIdx.x;
    float s = 0.f;
    for (int i = tid; i < DFEAT / 4; i += 256) {
        float4 u = r4[i];
        s = fmaf(u.x, u.x, s); s = fmaf(u.y, u.y, s);
        s = fmaf(u.z, u.z, s); s = fmaf(u.w, u.w, s);
        u.x = rna_tf32(u.x); u.y = rna_tf32(u.y);
        u.z = rna_tf32(u.z); u.w = rna_tf32(u.w);
        o4[i] = u;
    }
    __shared__ float red[256];
    red[tid] = s; __syncthreads();
    for (int o = 128; o > 0; o >>= 1) { if (tid < o) red[tid] += red[tid + o]; __syncthreads(); }
    if (tid == 0) invn[m] = 1.f / fmaxf(sqrtf(red[0]), 1e-12f);
}

__global__ void ctx_init_kernel(const float* __restrict__ initMem, float* __restrict__ xctx,
                                float* __restrict__ xcm)
{
    const size_t i = (size_t)blockIdx.x * blockDim.x + threadIdx.x;
    const float val = rna_tf32(initMem[i & (CTX - 1)]);
    xctx[i] = val;
    if (i < BB * CTX) xcm[i] = val;
}

// ---- fast batch-32 linear ----
template<bool ELU>
__global__ void small_linear_fast(const float* __restrict__ in, const float* __restrict__ wT,
                                  const float* __restrict__ bias, float* __restrict__ out)
{
    const int b = blockIdx.y;
    const int jb = blockIdx.x * 32;
    const int tid = threadIdx.x;
    const int wid = tid >> 5, lane = tid & 31;
    __shared__ float x[CMD];
    for (int d = tid; d < CMD; d += 256) x[d] = in[b * CMD + d];
    __syncthreads();
    #pragma unroll
    for (int jj = 0; jj < 4; ++jj) {
        const int j = jb + wid * 4 + jj;
        const float* w = wT + (size_t)j * CMD;
        float acc = 0.f;
        #pragma unroll
        for (int i = 0; i < CMD / 32; ++i)
            acc = fmaf(x[lane + 32 * i], w[lane + 32 * i], acc);
        #pragma unroll
        for (int o = 16; o > 0; o >>= 1)
            acc += __shfl_down_sync(0xFFFFFFFFu, acc, o);
        if (lane == 0) {
            acc += bias[j];
            if (ELU) acc = (acc > 0.f) ? acc : expm1f(acc);
            out[b * CMD + j] = acc;
        }
    }
}

// ---- fast textual command ----
__global__ __launch_bounds__(1024)
void text_cmd_fast(const float* __restrict__ qcmd, const float* __restrict__ lstm,
                   const float* __restrict__ c2l_w, const float* __restrict__ c2l_b,
                   const int* __restrict__ qlen, float* __restrict__ cmd)
{
    const int b = blockIdx.x;
    const int tid = threadIdx.x;
    const int wid = tid >> 5, lane = tid & 31;
    __shared__ float e[CMD];
    __shared__ float att[LQL];
    __shared__ float red[128];
    __shared__ float smx, ssum;

    if (tid < CMD) e[tid] = qcmd[b * CMD + tid] * c2l_w[tid];
    __syncthreads();

    const int en = qlen[b];
    #pragma unroll
    for (int li = 0; li < 4; ++li) {
        const int l = wid + li * 32;
        const float* L = lstm + ((size_t)b * LQL + l) * CMD;
        float acc = 0.f;
        #pragma unroll
        for (int i = 0; i < CMD / 32; ++i)
            acc = fmaf(L[lane + 32 * i], e[lane + 32 * i], acc);
        #pragma unroll
        for (int o = 16; o > 0; o >>= 1)
            acc += __shfl_down_sync(0xFFFFFFFFu, acc, o);
        if (lane == 0) att[l] = (l >= en) ? NEGV : (acc + c2l_b[0]);
    }
    __syncthreads();

    if (tid < 128) red[tid] = att[tid];
    __syncthreads();
    for (int o = 64; o > 0; o >>= 1) {
        if (tid < o) red[tid] = fmaxf(red[tid], red[tid + o]);
        __syncthreads();
    }
    if (tid == 0) smx = red[0];
    __syncthreads();
    float ev = 0.f;
    if (tid < 128) { ev = expf(att[tid] - smx); red[tid] = ev; }
    __syncthreads();
    for (int o = 64; o > 0; o >>= 1) {
        if (tid < o) red[tid] += red[tid + o];
        __syncthreads();
    }
    if (tid == 0) ssum = red[0];
    __syncthreads();
    if (tid < 128) att[tid] = ev / ssum;
    __syncthreads();

    if (tid < CMD) {
        float acc = 0.f;
        const float* L = lstm + (size_t)b * LQL * CMD + tid;
        #pragma unroll 4
        for (int l = 0; l < LQL; ++l)
            acc = fmaf(att[l], L[(size_t)l * CMD], acc);
        cmd[b * CMD + tid] = acc;
    }
}

// masked row softmax (in place)
__global__ void attn_softmax_kernel(float* __restrict__ score, const int* __restrict__ entity_num)
{
    const int row = blockIdx.x;
    const int b = row >> 10;
    const int n = row & 1023;
    const int en = entity_num[b];
    if (n >= en) return;
    float* s = score + (size_t)row * NENT;
    const int tid = threadIdx.x;

    float v[4];
    float mx = -3.4e38f;
    #pragma unroll
    for (int j = 0; j < 4; j++) {
        const int m = tid + j * 256;
        float x = s[m];
        x = (m >= en) ? NEGV : x;
        v[j] = x;
        mx = fmaxf(mx, x);
    }
    __shared__ float red[256];
    red[tid] = mx; __syncthreads();
    for (int o = 128; o > 0; o >>= 1) { if (tid < o) red[tid] = fmaxf(red[tid], red[tid + o]); __syncthreads(); }
    mx = red[0];
    __syncthreads();

    float sum = 0.f;
    #pragma unroll
    for (int j = 0; j < 4; j++) { v[j] = expf(v[j] - mx); sum += v[j]; }
    red[tid] = sum; __syncthreads();
    for (int o = 128; o > 0; o >>= 1) { if (tid < o) red[tid] += red[tid + o]; __syncthreads(); }
    const float inv = 1.f / red[0];

    #pragma unroll
    for (int j = 0; j < 4; j++) s[tid + j * 256] = rna_tf32(v[j] * inv);
}

// ---------------- launch ----------------
template<typename T> static float* symaddr(T& sym) {
    void* p = nullptr;
    cudaGetSymbolAddress(&p, sym);
    return (float*)p;
}

extern "C" void kernel_launch(void* const* d_in, const int* in_sizes, int n_in,
                              void* d_out, int out_size)
{
    const float* images    = (const float*)d_in[0];
    const float* q_enc     = (const float*)d_in[1];
    const float* lstm      = (const float*)d_in[2];
    const int*   q_length  = (const int*)  d_in[3];
    const int*   ent_num   = (const int*)  d_in[4];
    const float* initKB_w  = (const float*)d_in[5];
    const float* initKB_b  = (const float*)d_in[6];
    const float* initMem   = (const float*)d_in[7];
    const float* qInput_w  = (const float*)d_in[8];
    const float* qInput_b  = (const float*)d_in[9];
    const float* qInput2_w = (const float*)d_in[10];
    const float* qInput2_b = (const float*)d_in[11];
    const float* c2l_w     = (const float*)d_in[12];
    const float* c2l_b     = (const float*)d_in[13];
    const float* pxl_w     = (const float*)d_in[14];
    const float* pxl_b     = (const float*)d_in[15];
    const float* pxc_w     = (const float*)d_in[16];
    const float* pxc_b     = (const float*)d_in[17];
    const float* qry_w     = (const float*)d_in[18];
    const float* qry_b     = (const float*)d_in[19];
    const float* key_w     = (const float*)d_in[20];
    const float* key_b     = (const float*)d_in[21];
    const float* val_w     = (const float*)d_in[22];
    const float* val_b     = (const float*)d_in[23];
    const float* pk_w      = (const float*)d_in[24];
    const float* pk_b      = (const float*)d_in[25];
    const float* pv_w      = (const float*)d_in[26];
    const float* pv_b      = (const float*)d_in[27];
    const float* mu_w      = (const float*)d_in[28];
    const float* mu_b      = (const float*)d_in[29];
    const float* ck_w      = (const float*)d_in[30];
    const float* ck_b      = (const float*)d_in[31];

    float* imgr  = symaddr(g_imgr);
    float* invn  = symaddr(g_invnorm);
    float* xloc  = symaddr(g_xloc);
    float* xctxA = symaddr(g_xctx0);
    float* xctxB = symaddr(g_xctx1);
    float* prjl  = symaddr(g_projloc);
    float* pp    = symaddr(g_pp);
    float* q     = symaddr(g_q);
    float* k     = symaddr(g_k);
    float* v     = symaddr(g_v);
    float* vT    = symaddr(g_vT);
    float* msg   = symaddr(g_msg);
    float* qL    = symaddr(g_qL);
    float* kL    = symaddr(g_kL);
    float* vL    = symaddr(g_vL);
    float* score = symaddr(g_score);
    float* qbase = symaddr(g_qbase);
    float* qcmd  = symaddr(g_qcmd);
    float* cmd   = symaddr(g_cmd);
    float* pkg   = symaddr(g_pkg);
    float* pvg   = symaddr(g_pvg);
    float* msgm  = symaddr(g_msgm);
    float* xcm   = symaddr(g_xcm);
    float* wIKB  = symaddr(g_wT_ikb);
    float* wPXL  = symaddr(g_wT_pxl);
    float* wPXC  = symaddr(g_wT_pxc);
    float* wQRY  = symaddr(g_wT_qry);
    float* wKEY  = symaddr(g_wT_key);
    float* wVAL  = symaddr(g_wT_val);
    float* wMU   = symaddr(g_wT_mu);
    float* wCK   = symaddr(g_wT_ck);
    float* wQIN  = symaddr(g_wT_qin);
    float* wQIN2 = symaddr(g_wT_qin2);
    float* wPK   = symaddr(g_wT_pk);
    float* wPV   = symaddr(g_wT_pv);

    cudaFuncSetAttribute(gemm_mma<1,0,false,false,0>, cudaFuncAttributeMaxDynamicSharedMemorySize, SMEM_DYN);
    cudaFuncSetAttribute(gemm_mma<1,0,false,false,3>, cudaFuncAttributeMaxDynamicSharedMemorySize, SMEM_DYN);
    cudaFuncSetAttribute(gemm_mma<1,1,true ,false,0>, cudaFuncAttributeMaxDynamicSharedMemorySize, SMEM_DYN);
    cudaFuncSetAttribute(gemm_mma<1,3,true ,false,0>, cudaFuncAttributeMaxDynamicSharedMemorySize, SMEM_DYN);
    cudaFuncSetAttribute(gemm_mma<1,0,false,false,1>, cudaFuncAttributeMaxDynamicSharedMemorySize, SMEM_DYN);
    cudaFuncSetAttribute(gemm_mma<1,0,true ,false,2>, cudaFuncAttributeMaxDynamicSharedMemorySize, SMEM_DYN);
    cudaFuncSetAttribute(gemm_mma<2,0,true ,true ,3>, cudaFuncAttributeMaxDynamicSharedMemorySize, SMEM_DYN);
    cudaFuncSetAttribute(gemm_mma<2,2,true ,true ,3>, cudaFuncAttributeMaxDynamicSharedMemorySize, SMEM_DYN);
    cudaFuncSetAttribute(gemm_mma<2,2,true ,true ,0>, cudaFuncAttributeMaxDynamicSharedMemorySize, SMEM_DYN);
    cudaFuncSetAttribute(gemm_mma<2,0,true ,false,3>, cudaFuncAttributeMaxDynamicSharedMemorySize, SMEM_DYN);
    cudaFuncSetAttribute(gemm_mma<2,0,false,false,0>, cudaFuncAttributeMaxDynamicSharedMemorySize, SMEM_DYN);

    const float scale = 0.044194173824159216f;   // 1/sqrt(512)
    const dim3 tdim(32, 8);
    const dim3 gridMain(CTX / BNm, MROWS / BMm, 1);
    const dim3 gridScore(NENT / BNm, NENT / BMm, BB);
    const dim3 gridMsg(CTX / BNm, NENT / BMm, BB);
    const dim3 gridSL(CMD / 32, BB);

    // --- order: initKB GEMM at our launch index 3 (ncu -s 5 ≈ harness offset 2) ---
    transpose_kernel<true ><<<dim3(CTX/32, DFEAT/32, 1), tdim>>>(initKB_w, wIKB, DFEAT, CTX, 0, 0); // 0
    rownorm_round_kernel<<<MROWS, 256>>>(images, invn, imgr);                                        // 1
    ctx_init_kernel<<<(MROWS * CTX) / 256, 256>>>(initMem, xctxA, xcm);                              // 2
    // 3: x_loc = normalize(images) @ initKB_w + b   <-- ncu target
    gemm_mma<1,1,true,false,0><<<gridMain, 256, SMEM_DYN>>>(
        imgr, nullptr, nullptr, wIKB, initKB_b, invn, nullptr, nullptr, xloc,
        DFEAT, DFEAT, DFEAT, CTX, 0, 0, 0, 1.f);

    // remaining weight transposes
    transpose_kernel<false><<<dim3(CMD/32, CMD/32, 1), tdim>>>(qInput_w, wQIN, CMD, CMD, 0, 0);
    small_linear_fast<true><<<gridSL, 256>>>(q_enc, wQIN, qInput_b, qbase);
    transpose_kernel<true><<<dim3(CTX/32, CTX/32, 1),   tdim>>>(pxl_w, wPXL, CTX,   CTX, 0, 0);
    transpose_kernel<true><<<dim3(CTX/32, CTX/32, 1),   tdim>>>(pxc_w, wPXC, CTX,   CTX, 0, 0);
    transpose_kernel<true><<<dim3(CTX/32, 3*CTX/32, 1), tdim>>>(qry_w, wQRY, 3*CTX, CTX, 0, 0);
    transpose_kernel<true><<<dim3(CTX/32, 3*CTX/32, 1), tdim>>>(key_w, wKEY, 3*CTX, CTX, 0, 0);
    transpose_kernel<true><<<dim3(CTX/32, 3*CTX/32, 1), tdim>>>(val_w, wVAL, 3*CTX, CTX, 0, 0);
    transpose_kernel<true><<<dim3(CTX/32, 2*CTX/32, 1), tdim>>>(mu_w,  wMU,  2*CTX, CTX, 0, 0);
    transpose_kernel<true><<<dim3(CTX/32, 2*CTX/32, 1), tdim>>>(ck_w,  wCK,  2*CTX, CTX, 0, 0);
    transpose_kernel<false><<<dim3(CMD/32, CMD/32, TT), tdim>>>(qInput2_w, wQIN2, CMD, CMD,
                                                                (size_t)CMD*CMD, (size_t)CMD*CMD);
    transpose_kernel<false><<<dim3(CTX/32, CMD/32, 1), tdim>>>(pk_w, wPK, CMD, CTX, 0, 0);
    transpose_kernel<false><<<dim3(CTX/32, CMD/32, 1), tdim>>>(pv_w, wPV, CMD, CTX, 0, 0);

    // ---- iteration-invariant hoists ----
    gemm_mma<1,0,false,false,0><<<gridMain, 256, SMEM_DYN>>>(
        xloc, nullptr, nullptr, wPXL, pxl_b, nullptr, nullptr, nullptr, prjl,
        CTX, CTX, CTX, CTX, 0, 0, 0, 1.f);
    gemm_mma<1,0,false,false,3><<<gridMain, 256, SMEM_DYN>>>(
        xloc, nullptr, nullptr, wQRY, nullptr, nullptr, nullptr, ent_num, qL,
        CTX, CTX, 3*CTX, CTX, 0, 0, 0, 1.f);
    gemm_mma<1,0,false,false,3><<<gridMain, 256, SMEM_DYN>>>(
        xloc, nullptr, nullptr, wKEY, nullptr, nullptr, nullptr, ent_num, kL,
        CTX, CTX, 3*CTX, CTX, 0, 0, 0, 1.f);
    gemm_mma<1,0,false,false,0><<<gridMain, 256, SMEM_DYN>>>(
        xloc, nullptr, nullptr, wVAL, nullptr, nullptr, nullptr, nullptr, vL,
        CTX, CTX, 3*CTX, CTX, 0, 0, 0, 1.f);

    float* xc = xctxA;
    float* xn = xctxB;
    for (int t = 0; t < TT; t++) {
        small_linear_fast<false><<<gridSL, 256>>>(qbase, wQIN2 + (size_t)t * CMD * CMD,
                                                  qInput2_b + (size_t)t * CMD, qcmd);
        text_cmd_fast<<<BB, 1024>>>(qcmd, lstm, c2l_w, c2l_b, q_length, cmd);
        small_linear_fast<false><<<gridSL, 256>>>(cmd, wPK, pk_b, pkg);
        small_linear_fast<false><<<gridSL, 256>>>(cmd, wPV, pv_b, pvg);

        // pp = (x_ctx @ pxc + b) * proj_loc   (full: v needs all rows)
        gemm_mma<1,3,true,false,0><<<gridMain, 256, SMEM_DYN>>>(
            xc, nullptr, nullptr, wPXC, pxc_b, prjl, nullptr, nullptr, pp,
            CTX, CTX, CTX, CTX, 0, 0, 0, 1.f);

        // q/k: live rows only; v: full (mean(v) needs masked rows)
        gemm_mma<2,0,true,true,3><<<gridMain, 256, SMEM_DYN>>>(
            xc, pp, nullptr, wQRY + CTX, qry_b, nullptr, qL, ent_num, q,
            2*CTX, 0, 3*CTX, CTX, 0, 0, 0, 1.f);
        gemm_mma<2,2,true,true,3><<<gridMain, 256, SMEM_DYN>>>(
            xc, pp, nullptr, wKEY + CTX, key_b, pkg, kL, ent_num, k,
            2*CTX, 0, 3*CTX, CTX, 0, 0, 0, 1.f);
        gemm_mma<2,2,true,true,0><<<gridMain, 256, SMEM_DYN>>>(
            xc, pp, nullptr, wVAL + CTX, val_b, pvg, vL, nullptr, v,
            2*CTX, 0, 3*CTX, CTX, 0, 0, 0, 1.f);

        // score[b] = scale * q[b] @ k[b]^T — live tiles only
        gemm_mma<1,0,false,false,1><<<gridScore, 256, SMEM_DYN>>>(
            q, nullptr, nullptr, k, nullptr, nullptr, nullptr, ent_num, score,
            CTX, CTX, CTX, NENT,
            (size_t)NENT * CTX, (size_t)NENT * CTX, (size_t)NENT * NENT, scale);

        attn_softmax_kernel<<<MROWS, 256>>>(score, ent_num);

        // vT[b] = v[b]^T (tf32-rounded)
        transpose_kernel<true><<<dim3(CTX/32, NENT/32, BB), tdim>>>(
            v, vT, NENT, CTX, (size_t)NENT * CTX, (size_t)CTX * NENT);

        // message live rows; per-batch mean(v) for masked rows
        gemm_mma<1,0,true,false,2><<<gridMsg, 256, SMEM_DYN>>>(
            score, nullptr, nullptr, vT, nullptr, nullptr, nullptr, ent_num, msg,
            NENT, NENT, NENT, CTX,
            (size_t)NENT * NENT, (size_t)CTX * NENT, (size_t)NENT * CTX, 1.f);
        mean_v_kernel<<<dim3(CTX / 256, BB), 256>>>(v, ent_num, msgm);

        // x_ctx' live rows via MMA; masked rows via per-batch broadcast
        gemm_mma<2,0,true,false,3><<<gridMain, 256, SMEM_DYN>>>(
            xc, msg, nullptr, wMU, mu_b, nullptr, nullptr, ent_num, xn,
            2*CTX, 0, 2*CTX, CTX, 0, 0, 0, 1.f);
        ctx_bcast_kernel<<<BB, 256>>>(msgm, wMU, mu_b, ent_num, xcm, xn);

        float* tmp = xc; xc = xn; xn = tmp;
    }

    // out = [x_loc | x_ctx] @ ck + b
    gemm_mma<2,0,false,false,0><<<gridMain, 256, SMEM_DYN>>>(
        xloc, xc, nullptr, wCK, ck_b, nullptr, nullptr, nullptr, (float*)d_out,
        2*CTX, 0, 2*CTX, CTX, 0, 0, 0, 1.f);
}

// round 10
// speedup vs baseline: 6.1146x; 1.1146x over previous
#include <cuda_runtime.h>
#include <math.h>
#include <stdint.h>

#define BB     32
#define NENT   1024
#define LQL    128
#define DFEAT  2112
#define CTX    512
#define CMD    512
#define TT     4
#define MROWS  (BB*NENT)
#define NEGV   (-1e30f)

// ---- mma.sync GEMM tiling ----
#define BMm 128
#define BNm 128
#define BKm 16
#define STAGES 4
#define SROW 20
#define STAGE_F (2 * BMm * SROW)
#define TILE_F  (BMm * SROW)
#define SMEM_DYN (STAGES * STAGE_F * 4)
#define TSST 132                        // transposed-epilogue smem stride

// ---- scratch ----
__device__ float g_imgr   [(size_t)MROWS*DFEAT];
__device__ float g_invnorm[MROWS];
__device__ float g_xloc   [(size_t)MROWS*CTX];
__device__ float g_xctx0  [(size_t)MROWS*CTX];
__device__ float g_xctx1  [(size_t)MROWS*CTX];
__device__ float g_projloc[(size_t)MROWS*CTX];
__device__ float g_pp     [(size_t)MROWS*CTX];
__device__ float g_q      [(size_t)MROWS*CTX];
__device__ float g_k      [(size_t)MROWS*CTX];
__device__ float g_vT     [(size_t)MROWS*CTX];   // [B][CTX][NENT]
__device__ float g_msg    [(size_t)MROWS*CTX];
__device__ float g_qL     [(size_t)MROWS*CTX];
__device__ float g_kL     [(size_t)MROWS*CTX];
__device__ float g_vL     [(size_t)MROWS*CTX];
__device__ float g_score  [(size_t)BB*NENT*NENT];
__device__ float g_qbase  [BB*CMD];
__device__ float g_qcmd   [BB*CMD];
__device__ float g_cmd    [BB*CMD];
__device__ float g_pkg    [BB*CTX];
__device__ float g_pvg    [BB*CTX];
__device__ float g_msgm   [BB*CTX];
__device__ float g_xcm    [BB*CTX];
__device__ float g_wT_ikb[(size_t)CTX*DFEAT];
__device__ float g_wT_pxl[(size_t)CTX*CTX];
__device__ float g_wT_pxc[(size_t)CTX*CTX];
__device__ float g_wT_qry[(size_t)CTX*3*CTX];
__device__ float g_wT_key[(size_t)CTX*3*CTX];
__device__ float g_wT_val[(size_t)CTX*3*CTX];
__device__ float g_wT_mu [(size_t)CTX*2*CTX];
__device__ float g_wT_ck [(size_t)CTX*2*CTX];
__device__ float g_wT_qin [(size_t)CMD*CMD];
__device__ float g_wT_qin2[(size_t)TT*CMD*CMD];
__device__ float g_wT_pk  [(size_t)CMD*CTX];
__device__ float g_wT_pv  [(size_t)CMD*CTX];

__device__ __forceinline__ float rna_tf32(float f) {
    uint32_t r; asm("cvt.rna.tf32.f32 %0, %1;" : "=r"(r) : "f"(f));
    return __uint_as_float(r);
}
__device__ __forceinline__ uint32_t smem_u32(const void* p) {
    uint32_t a;
    asm("{ .reg .u64 t; cvta.to.shared.u64 t, %1; cvt.u32.u64 %0, t; }" : "=r"(a) : "l"(p));
    return a;
}
__device__ __forceinline__ void cp_async16(uint32_t saddr, const void* gptr) {
    asm volatile("cp.async.cg.shared.global [%0], [%1], 16;" :: "r"(saddr), "l"(gptr));
}
#define CP_COMMIT() asm volatile("cp.async.commit_group;" ::: "memory")
#define CP_WAIT2()  asm volatile("cp.async.wait_group 2;" ::: "memory")

__device__ __forceinline__ void ldsm_x4(uint32_t addr, uint32_t& r0, uint32_t& r1,
                                        uint32_t& r2, uint32_t& r3)
{
    asm volatile("ldmatrix.sync.aligned.m8n8.x4.shared.b16 {%0,%1,%2,%3}, [%4];"
                 : "=r"(r0), "=r"(r1), "=r"(r2), "=r"(r3) : "r"(addr));
}

__device__ __forceinline__ void mma_m16n8k8(float* d,
    uint32_t a0, uint32_t a1, uint32_t a2, uint32_t a3,
    uint32_t b0, uint32_t b1)
{
    asm volatile(
        "mma.sync.aligned.m16n8k8.row.col.f32.tf32.tf32.f32 "
        "{%0,%1,%2,%3}, {%4,%5,%6,%7}, {%8,%9}, {%0,%1,%2,%3};"
        : "+f"(d[0]), "+f"(d[1]), "+f"(d[2]), "+f"(d[3])
        : "r"(a0), "r"(a1), "r"(a2), "r"(a3), "r"(b0), "r"(b1));
}

// ---------------- tensor-core GEMM via mma.sync (tf32) ----------------
// MASK 0: none
//      1 (score, z=batch): skip tile if m0>=en || n0>=en
//      2 (message, z=batch): skip tile if m0>=en; truncate K at ceil(en/BKm)
//      3 (row-masked, z=1, batch=m0>>10): skip tile if (m0&1023)>=en
// TRANSC: write C transposed per batch: C is [B][CTX][NENT]; batch = m0>>10.
template<int NSRC, int EPI, bool RND, bool ADD, int MASK, bool TRANSC>
__global__ __launch_bounds__(256, 2)
void gemm_mma(const float* __restrict__ A0, const float* __restrict__ A1,
              const float* __restrict__ A2, const float* __restrict__ Bt,
              const float* __restrict__ bias, const float* __restrict__ extra,
              const float* __restrict__ addC, const int* __restrict__ ennum,
              float* __restrict__ C,
              int K, int lda, int ldb, int ldc,
              size_t sA, size_t sB, size_t sC, float alpha)
{
    extern __shared__ float smem[];
    const uint32_t sbase = smem_u32(smem);

    const int tid = threadIdx.x;
    const int z = blockIdx.z;
    const int m0 = blockIdx.y * BMm;
    const int n0 = blockIdx.x * BNm;

    int Keff = K;
    if (MASK == 1 || MASK == 2) {
        const int en = ennum[z];
        if (m0 >= en) return;
        if (MASK == 1 && n0 >= en) return;
        if (MASK == 2) { const int kc = ((en + BKm - 1) / BKm) * BKm; Keff = kc < K ? kc : K; }
    } else if (MASK == 3) {
        const int en = ennum[m0 >> 10];
        if ((m0 & 1023) >= en) return;
    }

    const float* Abase = A0 + (size_t)z * sA;
    const float* Bbase = Bt + (size_t)z * sB;
    float* Cbase = C + (size_t)z * sC;

    const int wid = tid >> 5, lane = tid & 31;
    const int wm = (wid & 3) * 32;
    const int wn = (wid >> 2) * 64;
    const int gr = lane >> 2;
    const int gc = lane & 3;

    const int lr = lane & 7, lg = lane >> 3;
    const int arow  = wm + lr + (lg & 1) * 8;
    const int akoff = (lg >> 1) * 4;
    const int brow  = wn + lr + (lg >> 1) * 8;
    const int bkoff = (lg & 1) * 4;

    const int prow0 = tid >> 2;
    const int pkq   = (tid & 3) * 4;

    float acc[2][8][4] = {};
    const int NCC = Keff / BKm;

    auto loadChunk = [&](int c, int st) {
        const int k0 = c * BKm;
        const float* Ap; int al, ak;
        if (NSRC == 1) { Ap = Abase; al = lda; ak = k0; }
        else {
            const int src = k0 >> 9;
            Ap = (src == 0) ? A0 : ((src == 1) ? A1 : A2);
            al = CTX; ak = k0 & (CTX - 1);
        }
        const uint32_t sa = sbase + (uint32_t)(st * STAGE_F) * 4;
        const uint32_t sb = sa + (uint32_t)TILE_F * 4;
        #pragma unroll
        for (int t = 0; t < 2; ++t) {
            const int row = prow0 + t * 64;
            cp_async16(sa + (uint32_t)(row * SROW + pkq) * 4,
                       Ap + (size_t)(m0 + row) * al + ak + pkq);
            cp_async16(sb + (uint32_t)(row * SROW + pkq) * 4,
                       Bbase + (size_t)(n0 + row) * ldb + k0 + pkq);
        }
        CP_COMMIT();
    };

    auto compute = [&](int st) {
        const uint32_t SAu = sbase + (uint32_t)(st * STAGE_F) * 4;
        const uint32_t SBu = SAu + (uint32_t)TILE_F * 4;
        #pragma unroll
        for (int kk = 0; kk < BKm; kk += 8) {
            uint32_t b[8][2];
            #pragma unroll
            for (int ntp = 0; ntp < 4; ++ntp) {
                const uint32_t addr = SBu +
                    (uint32_t)(((brow + ntp * 16) * SROW) + kk + bkoff) * 4;
                ldsm_x4(addr, b[2*ntp][0], b[2*ntp][1], b[2*ntp+1][0], b[2*ntp+1][1]);
            }
            #pragma unroll
            for (int mt = 0; mt < 2; ++mt) {
                uint32_t a0, a1, a2, a3;
                const uint32_t addr = SAu +
                    (uint32_t)(((arow + mt * 16) * SROW) + kk + akoff) * 4;
                ldsm_x4(addr, a0, a1, a2, a3);
                #pragma unroll
                for (int nt = 0; nt < 8; ++nt)
                    mma_m16n8k8(acc[mt][nt], a0, a1, a2, a3, b[nt][0], b[nt][1]);
            }
        }
    };

    #pragma unroll
    for (int s = 0; s < STAGES - 1; ++s) {
        if (s < NCC) loadChunk(s, s);
        else CP_COMMIT();
    }
    for (int c = 0; c < NCC; ++c) {
        CP_WAIT2();
        __syncthreads();
        const int nc = c + STAGES - 1;
        if (nc < NCC) loadChunk(nc, nc & (STAGES - 1));
        else CP_COMMIT();
        compute(c & (STAGES - 1));
    }

    if (TRANSC) __syncthreads();   // pipeline smem about to be reused

    #pragma unroll
    for (int mt = 0; mt < 2; ++mt) {
        #pragma unroll
        for (int half = 0; half < 2; ++half) {
            const int m = m0 + wm + mt * 16 + gr + half * 8;
            const float rs = (EPI == 1) ? extra[m] : 0.f;
            #pragma unroll
            for (int nt = 0; nt < 8; ++nt) {
                const int n = n0 + wn + nt * 8 + gc * 2;
                float v0 = acc[mt][nt][half * 2 + 0];
                float v1 = acc[mt][nt][half * 2 + 1];
                if (ADD) {
                    const float2 ad = *reinterpret_cast<const float2*>(addC + (size_t)m * ldc + n);
                    v0 += ad.x; v1 += ad.y;
                }
                const float bb0 = bias ? bias[n]     : 0.f;
                const float bb1 = bias ? bias[n + 1] : 0.f;
                if (EPI == 0)      { v0 = v0 * alpha + bb0;  v1 = v1 * alpha + bb1; }
                else if (EPI == 1) { v0 = v0 * rs + bb0;     v1 = v1 * rs + bb1; }
                else if (EPI == 2) {
                    const float* g = extra + (size_t)(m >> 10) * CTX + n;
                    v0 = (v0 + bb0) * g[0];
                    v1 = (v1 + bb1) * g[1];
                } else {
                    const float* g = extra + (size_t)m * ldc + n;
                    v0 = (v0 + bb0) * g[0];
                    v1 = (v1 + bb1) * g[1];
                }
                if (RND) { v0 = rna_tf32(v0); v1 = rna_tf32(v1); }
                if (!TRANSC) {
                    *reinterpret_cast<float2*>(Cbase + (size_t)m * ldc + n) = make_float2(v0, v1);
                } else {
                    const int ml = wm + mt * 16 + gr + half * 8;
                    const int nl = wn + nt * 8 + gc * 2;
                    smem[(size_t)nl * TSST + ml] = v0;          // conflict-free (proof in notes)
                    smem[(size_t)(nl + 1) * TSST + ml] = v1;
                }
            }
        }
    }

    if (TRANSC) {
        __syncthreads();
        // coalesced write: C[b][n][m], rows = n (128), cols = m (128)
        float* outT = C + (size_t)(m0 >> 10) * CTX * NENT;
        const int bofs = m0 & 1023;
        #pragma unroll
        for (int r = 0; r < 16; ++r) {
            const int row = wid * 16 + r;
            const float4 val = *reinterpret_cast<const float4*>(&smem[(size_t)row * TSST + lane * 4]);
            *reinterpret_cast<float4*>(outT + (size_t)(n0 + row) * NENT + bofs + lane * 4) = val;
        }
    }
}

// ---- per-batch mean over vT rows: msgm[b][d] = mean_k vT[b][d][k] ----
__global__ void mean_vT_kernel(const float* __restrict__ vT, const int* __restrict__ ennum,
                               float* __restrict__ msgm)
{
    const int b = blockIdx.y;
    if (ennum[b] >= NENT) return;
    const int wid = threadIdx.x >> 5, lane = threadIdx.x & 31;
    const int d = blockIdx.x * 8 + wid;
    const float* row = vT + (size_t)b * CTX * NENT + (size_t)d * NENT;
    float s = 0.f;
    #pragma unroll
    for (int i = 0; i < NENT / 32; ++i) s += row[lane + 32 * i];
    #pragma unroll
    for (int o = 16; o > 0; o >>= 1) s += __shfl_down_sync(0xFFFFFFFFu, s, o);
    if (lane == 0) msgm[b * CTX + d] = rna_tf32(s * (1.f / NENT));
}

// ---- masked-row x_ctx update + broadcast ----
__global__ __launch_bounds__(256)
void ctx_bcast_kernel(const float* __restrict__ msgm, const float* __restrict__ wMU,
                      const float* __restrict__ mu_b, const int* __restrict__ ennum,
                      float* __restrict__ xcm, float* __restrict__ xn)
{
    const int b = blockIdx.x;
    const int en = ennum[b];
    if (en >= NENT) return;
    const int tid = threadIdx.x;
    const int wid = tid >> 5, lane = tid & 31;
    __shared__ float x[2 * CTX];
    __shared__ float y[CTX];
    for (int d = tid; d < CTX; d += 256) {
        x[d] = xcm[b * CTX + d];
        x[CTX + d] = msgm[b * CTX + d];
    }
    __syncthreads();
    for (int j = wid; j < CTX; j += 8) {
        const float* w = wMU + (size_t)j * (2 * CTX);
        float acc = 0.f;
        #pragma unroll
        for (int i = 0; i < (2 * CTX) / 32; ++i)
            acc = fmaf(x[lane + 32 * i], w[lane + 32 * i], acc);
        #pragma unroll
        for (int o = 16; o > 0; o >>= 1)
            acc += __shfl_down_sync(0xFFFFFFFFu, acc, o);
        if (lane == 0) y[j] = rna_tf32(acc + mu_b[j]);
    }
    __syncthreads();
    for (int d = tid; d < CTX; d += 256) xcm[b * CTX + d] = y[d];
    float* base = xn + (size_t)b * NENT * CTX;
    for (int m = en; m < NENT; ++m)
        for (int d = tid; d < CTX; d += 256)
            base[(size_t)m * CTX + d] = y[d];
}

// ---- transpose, optional tf32 round ----
template<bool RND>
__global__ void transpose_kernel(const float* __restrict__ in, float* __restrict__ out,
                                 int R, int C, size_t sIn, size_t sOut)
{
    __shared__ float tile[32][33];
    const int z = blockIdx.z;
    in  += (size_t)z * sIn;
    out += (size_t)z * sOut;
    const int r0 = blockIdx.y * 32, c0 = blockIdx.x * 32;
    #pragma unroll
    for (int i = threadIdx.y; i < 32; i += 8) {
        float x = in[(size_t)(r0 + i) * C + c0 + threadIdx.x];
        tile[i][threadIdx.x] = RND ? rna_tf32(x) : x;
    }
    __syncthreads();
    #pragma unroll
    for (int i = threadIdx.y; i < 32; i += 8)
        out[(size_t)(c0 + i) * R + r0 + threadIdx.x] = tile[threadIdx.x][i];
}

// ---- fused row inv-norm + tf32-rounded copy ----
__global__ void rownorm_round_kernel(const float* __restrict__ img, float* __restrict__ invn,
                                     float* __restrict__ imgr)
{
    const int m = blockIdx.x;
    const float4* r4 = reinterpret_cast<const float4*>(img + (size_t)m * DFEAT);
    float4* o4 = reinterpret_cast<float4*>(imgr + (size_t)m * DFEAT);
    const int tid = threadIdx.x;
    float s = 0.f;
    for (int i = tid; i < DFEAT / 4; i += 256) {
        float4 u = r4[i];
        s = fmaf(u.x, u.x, s); s = fmaf(u.y, u.y, s);
        s = fmaf(u.z, u.z, s); s = fmaf(u.w, u.w, s);
        u.x = rna_tf32(u.x); u.y = rna_tf32(u.y);
        u.z = rna_tf32(u.z); u.w = rna_tf32(u.w);
        o4[i] = u;
    }
    __shared__ float red[256];
    red[tid] = s; __syncthreads();
    for (int o = 128; o > 0; o >>= 1) { if (tid < o) red[tid] += red[tid + o]; __syncthreads(); }
    if (tid == 0) invn[m] = 1.f / fmaxf(sqrtf(red[0]), 1e-12f);
}

__global__ void ctx_init_kernel(const float* __restrict__ initMem, float* __restrict__ xctx,
                                float* __restrict__ xcm)
{
    const size_t i = (size_t)blockIdx.x * blockDim.x + threadIdx.x;
    const float val = rna_tf32(initMem[i & (CTX - 1)]);
    xctx[i] = val;
    if (i < BB * CTX) xcm[i] = val;
}

// ---- fast batch-32 linear ----
template<bool ELU>
__global__ void small_linear_fast(const float* __restrict__ in, const float* __restrict__ wT,
                                  const float* __restrict__ bias, float* __restrict__ out)
{
    const int b = blockIdx.y;
    const int jb = blockIdx.x * 32;
    const int tid = threadIdx.x;
    const int wid = tid >> 5, lane = tid & 31;
    __shared__ float x[CMD];
    for (int d = tid; d < CMD; d += 256) x[d] = in[b * CMD + d];
    __syncthreads();
    #pragma unroll
    for (int jj = 0; jj < 4; ++jj) {
        const int j = jb + wid * 4 + jj;
        const float* w = wT + (size_t)j * CMD;
        float acc = 0.f;
        #pragma unroll
        for (int i = 0; i < CMD / 32; ++i)
            acc = fmaf(x[lane + 32 * i], w[lane + 32 * i], acc);
        #pragma unroll
        for (int o = 16; o > 0; o >>= 1)
            acc += __shfl_down_sync(0xFFFFFFFFu, acc, o);
        if (lane == 0) {
            acc += bias[j];
            if (ELU) acc = (acc > 0.f) ? acc : expm1f(acc);
            out[b * CMD + j] = acc;
        }
    }
}

// ---- fast textual command ----
__global__ __launch_bounds__(1024)
void text_cmd_fast(const float* __restrict__ qcmd, const float* __restrict__ lstm,
                   const float* __restrict__ c2l_w, const float* __restrict__ c2l_b,
                   const int* __restrict__ qlen, float* __restrict__ cmd)
{
    const int b = blockIdx.x;
    const int tid = threadIdx.x;
    const int wid = tid >> 5, lane = tid & 31;
    __shared__ float e[CMD];
    __shared__ float att[LQL];
    __shared__ float red[128];
    __shared__ float smx, ssum;

    if (tid < CMD) e[tid] = qcmd[b * CMD + tid] * c2l_w[tid];
    __syncthreads();

    const int en = qlen[b];
    #pragma unroll
    for (int li = 0; li < 4; ++li) {
        const int l = wid + li * 32;
        const float* L = lstm + ((size_t)b * LQL + l) * CMD;
        float acc = 0.f;
        #pragma unroll
        for (int i = 0; i < CMD / 32; ++i)
            acc = fmaf(L[lane + 32 * i], e[lane + 32 * i], acc);
        #pragma unroll
        for (int o = 16; o > 0; o >>= 1)
            acc += __shfl_down_sync(0xFFFFFFFFu, acc, o);
        if (lane == 0) att[l] = (l >= en) ? NEGV : (acc + c2l_b[0]);
    }
    __syncthreads();

    if (tid < 128) red[tid] = att[tid];
    __syncthreads();
    for (int o = 64; o > 0; o >>= 1) {
        if (tid < o) red[tid] = fmaxf(red[tid], red[tid + o]);
        __syncthreads();
    }
    if (tid == 0) smx = red[0];
    __syncthreads();
    float ev = 0.f;
    if (tid < 128) { ev = expf(att[tid] - smx); red[tid] = ev; }
    __syncthreads();
    for (int o = 64; o > 0; o >>= 1) {
        if (tid < o) red[tid] += red[tid + o];
        __syncthreads();
    }
    if (tid == 0) ssum = red[0];
    __syncthreads();
    if (tid < 128) att[tid] = ev / ssum;
    __syncthreads();

    if (tid < CMD) {
        float acc = 0.f;
        const float* L = lstm + (size_t)b * LQL * CMD + tid;
        #pragma unroll 4
        for (int l = 0; l < LQL; ++l)
            acc = fmaf(att[l], L[(size_t)l * CMD], acc);
        cmd[b * CMD + tid] = acc;
    }
}

// masked row softmax (in place); processes only column blocks below ceil(en/16)*16
__global__ void attn_softmax_kernel(float* __restrict__ score, const int* __restrict__ entity_num)
{
    const int row = blockIdx.x;
    const int b = row >> 10;
    const int n = row & 1023;
    const int en = entity_num[b];
    if (n >= en) return;
    float* s = score + (size_t)row * NENT;
    const int tid = threadIdx.x;

    const int kc = ((en + BKm - 1) / BKm) * BKm;   // msg GEMM reads k < kc
    const int nblk = (kc + 255) >> 8;              // 256-wide blocks to process

    float v[4];
    float mx = -3.4e38f;
    #pragma unroll
    for (int j = 0; j < 4; j++) {
        const int m = tid + j * 256;
        float x = NEGV;
        if (j < nblk && m < en) x = s[m];
        v[j] = x;
        mx = fmaxf(mx, x);
    }
    __shared__ float red[256];
    red[tid] = mx; __syncthreads();
    for (int o = 128; o > 0; o >>= 1) { if (tid < o) red[tid] = fmaxf(red[tid], red[tid + o]); __syncthreads(); }
    mx = red[0];
    __syncthreads();

    float sum = 0.f;
    #pragma unroll
    for (int j = 0; j < 4; j++) { v[j] = expf(v[j] - mx); sum += v[j]; }
    red[tid] = sum; __syncthreads();
    for (int o = 128; o > 0; o >>= 1) { if (tid < o) red[tid] += red[tid + o]; __syncthreads(); }
    const float inv = 1.f / red[0];

    #pragma unroll
    for (int j = 0; j < 4; j++)
        if (j < nblk) s[tid + j * 256] = rna_tf32(v[j] * inv);
}

// ---------------- launch ----------------
template<typename T> static float* symaddr(T& sym) {
    void* p = nullptr;
    cudaGetSymbolAddress(&p, sym);
    return (float*)p;
}

extern "C" void kernel_launch(void* const* d_in, const int* in_sizes, int n_in,
                              void* d_out, int out_size)
{
    const float* images    = (const float*)d_in[0];
    const float* q_enc     = (const float*)d_in[1];
    const float* lstm      = (const float*)d_in[2];
    const int*   q_length  = (const int*)  d_in[3];
    const int*   ent_num   = (const int*)  d_in[4];
    const float* initKB_w  = (const float*)d_in[5];
    const float* initKB_b  = (const float*)d_in[6];
    const float* initMem   = (const float*)d_in[7];
    const float* qInput_w  = (const float*)d_in[8];
    const float* qInput_b  = (const float*)d_in[9];
    const float* qInput2_w = (const float*)d_in[10];
    const float* qInput2_b = (const float*)d_in[11];
    const float* c2l_w     = (const float*)d_in[12];
    const float* c2l_b     = (const float*)d_in[13];
    const float* pxl_w     = (const float*)d_in[14];
    const float* pxl_b     = (const float*)d_in[15];
    const float* pxc_w     = (const float*)d_in[16];
    const float* pxc_b     = (const float*)d_in[17];
    const float* qry_w     = (const float*)d_in[18];
    const float* qry_b     = (const float*)d_in[19];
    const float* key_w     = (const float*)d_in[20];
    const float* key_b     = (const float*)d_in[21];
    const float* val_w     = (const float*)d_in[22];
    const float* val_b     = (const float*)d_in[23];
    const float* pk_w      = (const float*)d_in[24];
    const float* pk_b      = (const float*)d_in[25];
    const float* pv_w      = (const float*)d_in[26];
    const float* pv_b      = (const float*)d_in[27];
    const float* mu_w      = (const float*)d_in[28];
    const float* mu_b      = (const float*)d_in[29];
    const float* ck_w      = (const float*)d_in[30];
    const float* ck_b      = (const float*)d_in[31];

    float* imgr  = symaddr(g_imgr);
    float* invn  = symaddr(g_invnorm);
    float* xloc  = symaddr(g_xloc);
    float* xctxA = symaddr(g_xctx0);
    float* xctxB = symaddr(g_xctx1);
    float* prjl  = symaddr(g_projloc);
    float* pp    = symaddr(g_pp);
    float* q     = symaddr(g_q);
    float* k     = symaddr(g_k);
    float* vT    = symaddr(g_vT);
    float* msg   = symaddr(g_msg);
    float* qL    = symaddr(g_qL);
    float* kL    = symaddr(g_kL);
    float* vL    = symaddr(g_vL);
    float* score = symaddr(g_score);
    float* qbase = symaddr(g_qbase);
    float* qcmd  = symaddr(g_qcmd);
    float* cmd   = symaddr(g_cmd);
    float* pkg   = symaddr(g_pkg);
    float* pvg   = symaddr(g_pvg);
    float* msgm  = symaddr(g_msgm);
    float* xcm   = symaddr(g_xcm);
    float* wIKB  = symaddr(g_wT_ikb);
    float* wPXL  = symaddr(g_wT_pxl);
    float* wPXC  = symaddr(g_wT_pxc);
    float* wQRY  = symaddr(g_wT_qry);
    float* wKEY  = symaddr(g_wT_key);
    float* wVAL  = symaddr(g_wT_val);
    float* wMU   = symaddr(g_wT_mu);
    float* wCK   = symaddr(g_wT_ck);
    float* wQIN  = symaddr(g_wT_qin);
    float* wQIN2 = symaddr(g_wT_qin2);
    float* wPK   = symaddr(g_wT_pk);
    float* wPV   = symaddr(g_wT_pv);

    cudaFuncSetAttribute(gemm_mma<1,0,false,false,0,false>, cudaFuncAttributeMaxDynamicSharedMemorySize, SMEM_DYN);
    cudaFuncSetAttribute(gemm_mma<1,0,false,false,3,false>, cudaFuncAttributeMaxDynamicSharedMemorySize, SMEM_DYN);
    cudaFuncSetAttribute(gemm_mma<1,1,true ,false,0,false>, cudaFuncAttributeMaxDynamicSharedMemorySize, SMEM_DYN);
    cudaFuncSetAttribute(gemm_mma<1,3,true ,false,0,false>, cudaFuncAttributeMaxDynamicSharedMemorySize, SMEM_DYN);
    cudaFuncSetAttribute(gemm_mma<1,0,false,false,1,false>, cudaFuncAttributeMaxDynamicSharedMemorySize, SMEM_DYN);
    cudaFuncSetAttribute(gemm_mma<1,0,true ,false,2,false>, cudaFuncAttributeMaxDynamicSharedMemorySize, SMEM_DYN);
    cudaFuncSetAttribute(gemm_mma<2,0,true ,true ,3,false>, cudaFuncAttributeMaxDynamicSharedMemorySize, SMEM_DYN);
    cudaFuncSetAttribute(gemm_mma<2,2,true ,true ,3,false>, cudaFuncAttributeMaxDynamicSharedMemorySize, SMEM_DYN);
    cudaFuncSetAttribute(gemm_mma<2,2,true ,true ,0,true >, cudaFuncAttributeMaxDynamicSharedMemorySize, SMEM_DYN);
    cudaFuncSetAttribute(gemm_mma<2,0,true ,false,3,false>, cudaFuncAttributeMaxDynamicSharedMemorySize, SMEM_DYN);
    cudaFuncSetAttribute(gemm_mma<2,0,false,false,0,false>, cudaFuncAttributeMaxDynamicSharedMemorySize, SMEM_DYN);

    const float scale = 0.044194173824159216f;   // 1/sqrt(512)
    const dim3 tdim(32, 8);
    const dim3 gridMain(CTX / BNm, MROWS / BMm, 1);
    const dim3 gridScore(NENT / BNm, NENT / BMm, BB);
    const dim3 gridMsg(CTX / BNm, NENT / BMm, BB);
    const dim3 gridSL(CMD / 32, BB);

    // --- order: initKB GEMM at launch index 3 (ncu -s 5) ---
    transpose_kernel<true ><<<dim3(CTX/32, DFEAT/32, 1), tdim>>>(initKB_w, wIKB, DFEAT, CTX, 0, 0); // 0
    rownorm_round_kernel<<<MROWS, 256>>>(images, invn, imgr);                                        // 1
    ctx_init_kernel<<<(MROWS * CTX) / 256, 256>>>(initMem, xctxA, xcm);                              // 2
    // 3: x_loc = normalize(images) @ initKB_w + b   <-- ncu target
    gemm_mma<1,1,true,false,0,false><<<gridMain, 256, SMEM_DYN>>>(
        imgr, nullptr, nullptr, wIKB, initKB_b, invn, nullptr, nullptr, xloc,
        DFEAT, DFEAT, DFEAT, CTX, 0, 0, 0, 1.f);

    // remaining weight transposes
    transpose_kernel<false><<<dim3(CMD/32, CMD/32, 1), tdim>>>(qInput_w, wQIN, CMD, CMD, 0, 0);
    small_linear_fast<true><<<gridSL, 256>>>(q_enc, wQIN, qInput_b, qbase);
    transpose_kernel<true><<<dim3(CTX/32, CTX/32, 1),   tdim>>>(pxl_w, wPXL, CTX,   CTX, 0, 0);
    transpose_kernel<true><<<dim3(CTX/32, CTX/32, 1),   tdim>>>(pxc_w, wPXC, CTX,   CTX, 0, 0);
    transpose_kernel<true><<<dim3(CTX/32, 3*CTX/32, 1), tdim>>>(qry_w, wQRY, 3*CTX, CTX, 0, 0);
    transpose_kernel<true><<<dim3(CTX/32, 3*CTX/32, 1), tdim>>>(key_w, wKEY, 3*CTX, CTX, 0, 0);
    transpose_kernel<true><<<dim3(CTX/32, 3*CTX/32, 1), tdim>>>(val_w, wVAL, 3*CTX, CTX, 0, 0);
    transpose_kernel<true><<<dim3(CTX/32, 2*CTX/32, 1), tdim>>>(mu_w,  wMU,  2*CTX, CTX, 0, 0);
    transpose_kernel<true><<<dim3(CTX/32, 2*CTX/32, 1), tdim>>>(ck_w,  wCK,  2*CTX, CTX, 0, 0);
    transpose_kernel<false><<<dim3(CMD/32, CMD/32, TT), tdim>>>(qInput2_w, wQIN2, CMD, CMD,
                                                                (size_t)CMD*CMD, (size_t)CMD*CMD);
    transpose_kernel<false><<<dim3(CTX/32, CMD/32, 1), tdim>>>(pk_w, wPK, CMD, CTX, 0, 0);
    transpose_kernel<false><<<dim3(CTX/32, CMD/32, 1), tdim>>>(pv_w, wPV, CMD, CTX, 0, 0);

    // ---- iteration-invariant hoists ----
    gemm_mma<1,0,false,false,0,false><<<gridMain, 256, SMEM_DYN>>>(
        xloc, nullptr, nullptr, wPXL, pxl_b, nullptr, nullptr, nullptr, prjl,
        CTX, CTX, CTX, CTX, 0, 0, 0, 1.f);
    gemm_mma<1,0,false,false,3,false><<<gridMain, 256, SMEM_DYN>>>(
        xloc, nullptr, nullptr, wQRY, nullptr, nullptr, nullptr, ent_num, qL,
        CTX, CTX, 3*CTX, CTX, 0, 0, 0, 1.f);
    gemm_mma<1,0,false,false,3,false><<<gridMain, 256, SMEM_DYN>>>(
        xloc, nullptr, nullptr, wKEY, nullptr, nullptr, nullptr, ent_num, kL,
        CTX, CTX, 3*CTX, CTX, 0, 0, 0, 1.f);
    gemm_mma<1,0,false,false,0,false><<<gridMain, 256, SMEM_DYN>>>(
        xloc, nullptr, nullptr, wVAL, nullptr, nullptr, nullptr, nullptr, vL,
        CTX, CTX, 3*CTX, CTX, 0, 0, 0, 1.f);

    float* xc = xctxA;
    float* xn = xctxB;
    for (int t = 0; t < TT; t++) {
        small_linear_fast<false><<<gridSL, 256>>>(qbase, wQIN2 + (size_t)t * CMD * CMD,
                                                  qInput2_b + (size_t)t * CMD, qcmd);
        text_cmd_fast<<<BB, 1024>>>(qcmd, lstm, c2l_w, c2l_b, q_length, cmd);
        small_linear_fast<false><<<gridSL, 256>>>(cmd, wPK, pk_b, pkg);
        small_linear_fast<false><<<gridSL, 256>>>(cmd, wPV, pv_b, pvg);

        // pp = (x_ctx @ pxc + b) * proj_loc   (full: v needs all rows)
        gemm_mma<1,3,true,false,0,false><<<gridMain, 256, SMEM_DYN>>>(
            xc, nullptr, nullptr, wPXC, pxc_b, prjl, nullptr, nullptr, pp,
            CTX, CTX, CTX, CTX, 0, 0, 0, 1.f);

        // q/k: live rows only; v: full, written TRANSPOSED directly to vT
        gemm_mma<2,0,true,true,3,false><<<gridMain, 256, SMEM_DYN>>>(
            xc, pp, nullptr, wQRY + CTX, qry_b, nullptr, qL, ent_num, q,
            2*CTX, 0, 3*CTX, CTX, 0, 0, 0, 1.f);
        gemm_mma<2,2,true,true,3,false><<<gridMain, 256, SMEM_DYN>>>(
            xc, pp, nullptr, wKEY + CTX, key_b, pkg, kL, ent_num, k,
            2*CTX, 0, 3*CTX, CTX, 0, 0, 0, 1.f);
        gemm_mma<2,2,true,true,0,true><<<gridMain, 256, SMEM_DYN>>>(
            xc, pp, nullptr, wVAL + CTX, val_b, pvg, vL, nullptr, vT,
            2*CTX, 0, 3*CTX, CTX, 0, 0, 0, 1.f);

        // score[b] = scale * q[b] @ k[b]^T — live tiles only
        gemm_mma<1,0,false,false,1,false><<<gridScore, 256, SMEM_DYN>>>(
            q, nullptr, nullptr, k, nullptr, nullptr, nullptr, ent_num, score,
            CTX, CTX, CTX, NENT,
            (size_t)NENT * CTX, (size_t)NENT * CTX, (size_t)NENT * NENT, scale);

        attn_softmax_kernel<<<MROWS, 256>>>(score, ent_num);

        // message live rows; per-batch mean(v) for masked rows
        gemm_mma<1,0,true,false,2,false><<<gridMsg, 256, SMEM_DYN>>>(
            score, nullptr, nullptr, vT, nullptr, nullptr, nullptr, ent_num, msg,
            NENT, NENT, NENT, CTX,
            (size_t)NENT * NENT, (size_t)CTX * NENT, (size_t)NENT * CTX, 1.f);
        mean_vT_kernel<<<dim3(CTX / 8, BB), 256>>>(vT, ent_num, msgm);

        // x_ctx' live rows via MMA; masked rows via per-batch broadcast
        gemm_mma<2,0,true,false,3,false><<<gridMain, 256, SMEM_DYN>>>(
            xc, msg, nullptr, wMU, mu_b, nullptr, nullptr, ent_num, xn,
            2*CTX, 0, 2*CTX, CTX, 0, 0, 0, 1.f);
        ctx_bcast_kernel<<<BB, 256>>>(msgm, wMU, mu_b, ent_num, xcm, xn);

        float* tmp = xc; xc = xn; xn = tmp;
    }

    // out = [x_loc | x_ctx] @ ck + b
    gemm_mma<2,0,false,false,0,false><<<gridMain, 256, SMEM_DYN>>>(
        xloc, xc, nullptr, wCK, ck_b, nullptr, nullptr, nullptr, (float*)d_out,
        2*CTX, 0, 2*CTX, CTX, 0, 0, 0, 1.f);
}

// round 11
// speedup vs baseline: 6.6599x; 1.0892x over previous
#include <cuda_runtime.h>
#include <math.h>
#include <stdint.h>

#define BB     32
#define NENT   1024
#define LQL    128
#define DFEAT  2112
#define CTX    512
#define CMD    512
#define TT     4
#define MROWS  (BB*NENT)
#define NEGV   (-1e30f)

// ---- mma.sync GEMM tiling ----
#define BMm 128
#define BNm 128
#define BKm 32
#define STAGES 3
#define SROW 36                          // 32 k + 4 pad; conflict-free (proof in notes)
#define STAGE_F (2 * BMm * SROW)         // 9216 floats = 36864 B
#define TILE_F  (BMm * SROW)             // 4608
#define SMEM_DYN (STAGES * STAGE_F * 4)  // 110592 B -> 2 CTAs = 221 KB
#define TSST 132                         // transposed-epilogue smem stride

// ---- scratch ----
__device__ float g_imgr   [(size_t)MROWS*DFEAT];
__device__ float g_invnorm[MROWS];
__device__ float g_xloc   [(size_t)MROWS*CTX];
__device__ float g_xctx0  [(size_t)MROWS*CTX];
__device__ float g_xctx1  [(size_t)MROWS*CTX];
__device__ float g_projloc[(size_t)MROWS*CTX];
__device__ float g_pp     [(size_t)MROWS*CTX];
__device__ float g_q      [(size_t)MROWS*CTX];
__device__ float g_k      [(size_t)MROWS*CTX];
__device__ float g_vT     [(size_t)MROWS*CTX];   // [B][CTX][NENT]
__device__ float g_msg    [(size_t)MROWS*CTX];
__device__ float g_qL     [(size_t)MROWS*CTX];
__device__ float g_kL     [(size_t)MROWS*CTX];
__device__ float g_vL     [(size_t)MROWS*CTX];
__device__ float g_score  [(size_t)BB*NENT*NENT];
__device__ float g_qbase  [BB*CMD];
__device__ float g_qcmd   [BB*CMD];
__device__ float g_cmd    [BB*CMD];
__device__ float g_pkg    [BB*CTX];
__device__ float g_pvg    [BB*CTX];
__device__ float g_msgm   [BB*CTX];
__device__ float g_xcm    [BB*CTX];
__device__ float g_wT_ikb[(size_t)CTX*DFEAT];
__device__ float g_wT_pxl[(size_t)CTX*CTX];
__device__ float g_wT_pxc[(size_t)CTX*CTX];
__device__ float g_wT_qry[(size_t)CTX*3*CTX];
__device__ float g_wT_key[(size_t)CTX*3*CTX];
__device__ float g_wT_val[(size_t)CTX*3*CTX];
__device__ float g_wT_mu [(size_t)CTX*2*CTX];
__device__ float g_wT_ck [(size_t)CTX*2*CTX];
__device__ float g_wT_qin [(size_t)CMD*CMD];
__device__ float g_wT_qin2[(size_t)TT*CMD*CMD];
__device__ float g_wT_pk  [(size_t)CMD*CTX];
__device__ float g_wT_pv  [(size_t)CMD*CTX];

__device__ __forceinline__ float rna_tf32(float f) {
    uint32_t r; asm("cvt.rna.tf32.f32 %0, %1;" : "=r"(r) : "f"(f));
    return __uint_as_float(r);
}
__device__ __forceinline__ uint32_t smem_u32(const void* p) {
    uint32_t a;
    asm("{ .reg .u64 t; cvta.to.shared.u64 t, %1; cvt.u32.u64 %0, t; }" : "=r"(a) : "l"(p));
    return a;
}
__device__ __forceinline__ void cp_async16(uint32_t saddr, const void* gptr) {
    asm volatile("cp.async.cg.shared.global [%0], [%1], 16;" :: "r"(saddr), "l"(gptr));
}
#define CP_COMMIT() asm volatile("cp.async.commit_group;" ::: "memory")
#define CP_WAIT1()  asm volatile("cp.async.wait_group 1;" ::: "memory")

__device__ __forceinline__ void ldsm_x4(uint32_t addr, uint32_t& r0, uint32_t& r1,
                                        uint32_t& r2, uint32_t& r3)
{
    asm volatile("ldmatrix.sync.aligned.m8n8.x4.shared.b16 {%0,%1,%2,%3}, [%4];"
                 : "=r"(r0), "=r"(r1), "=r"(r2), "=r"(r3) : "r"(addr));
}

__device__ __forceinline__ void mma_m16n8k8(float* d,
    uint32_t a0, uint32_t a1, uint32_t a2, uint32_t a3,
    uint32_t b0, uint32_t b1)
{
    asm volatile(
        "mma.sync.aligned.m16n8k8.row.col.f32.tf32.tf32.f32 "
        "{%0,%1,%2,%3}, {%4,%5,%6,%7}, {%8,%9}, {%0,%1,%2,%3};"
        : "+f"(d[0]), "+f"(d[1]), "+f"(d[2]), "+f"(d[3])
        : "r"(a0), "r"(a1), "r"(a2), "r"(a3), "r"(b0), "r"(b1));
}

// ---------------- tensor-core GEMM via mma.sync (tf32) ----------------
// MASK 0: none
//      1 (score, z=batch): skip tile if m0>=en || n0>=en
//      2 (message, z=batch): skip tile if m0>=en; truncate K at ceil(en/BKm)
//      3 (row-masked, z=1, batch=m0>>10): skip tile if (m0&1023)>=en
// TRANSC: write C transposed per batch: C is [B][CTX][NENT]; batch = m0>>10.
template<int NSRC, int EPI, bool RND, bool ADD, int MASK, bool TRANSC>
__global__ __launch_bounds__(256, 2)
void gemm_mma(const float* __restrict__ A0, const float* __restrict__ A1,
              const float* __restrict__ A2, const float* __restrict__ Bt,
              const float* __restrict__ bias, const float* __restrict__ extra,
              const float* __restrict__ addC, const int* __restrict__ ennum,
              float* __restrict__ C,
              int K, int lda, int ldb, int ldc,
              size_t sA, size_t sB, size_t sC, float alpha)
{
    extern __shared__ float smem[];
    const uint32_t sbase = smem_u32(smem);

    const int tid = threadIdx.x;
    const int z = blockIdx.z;
    const int m0 = blockIdx.y * BMm;
    const int n0 = blockIdx.x * BNm;

    int Keff = K;
    if (MASK == 1 || MASK == 2) {
        const int en = ennum[z];
        if (m0 >= en) return;
        if (MASK == 1 && n0 >= en) return;
        if (MASK == 2) { const int kc = ((en + BKm - 1) / BKm) * BKm; Keff = kc < K ? kc : K; }
    } else if (MASK == 3) {
        const int en = ennum[m0 >> 10];
        if ((m0 & 1023) >= en) return;
    }

    const float* Abase = A0 + (size_t)z * sA;
    const float* Bbase = Bt + (size_t)z * sB;
    float* Cbase = C + (size_t)z * sC;

    const int wid = tid >> 5, lane = tid & 31;
    const int wm = (wid & 3) * 32;
    const int wn = (wid >> 2) * 64;
    const int gr = lane >> 2;
    const int gc = lane & 3;

    const int lr = lane & 7, lg = lane >> 3;
    const int arow  = wm + lr + (lg & 1) * 8;
    const int akoff = (lg >> 1) * 4;
    const int brow  = wn + lr + (lg >> 1) * 8;
    const int bkoff = (lg & 1) * 4;

    const int prow0 = tid >> 3;              // 0..31
    const int pkq   = (tid & 7) * 4;         // k float4 offset within 32

    float acc[2][8][4] = {};
    const int NCC = Keff / BKm;

    auto loadChunk = [&](int c, int st) {
        const int k0 = c * BKm;
        const float* Ap; int al, ak;
        if (NSRC == 1) { Ap = Abase; al = lda; ak = k0; }
        else {
            const int src = k0 >> 9;
            Ap = (src == 0) ? A0 : ((src == 1) ? A1 : A2);
            al = CTX; ak = k0 & (CTX - 1);
        }
        const uint32_t sa = sbase + (uint32_t)(st * STAGE_F) * 4;
        const uint32_t sb = sa + (uint32_t)TILE_F * 4;
        #pragma unroll
        for (int t = 0; t < 4; ++t) {
            const int row = prow0 + t * 32;
            cp_async16(sa + (uint32_t)(row * SROW + pkq) * 4,
                       Ap + (size_t)(m0 + row) * al + ak + pkq);
            cp_async16(sb + (uint32_t)(row * SROW + pkq) * 4,
                       Bbase + (size_t)(n0 + row) * ldb + k0 + pkq);
        }
        CP_COMMIT();
    };

    auto compute = [&](int st) {
        const uint32_t SAu = sbase + (uint32_t)(st * STAGE_F) * 4;
        const uint32_t SBu = SAu + (uint32_t)TILE_F * 4;
        #pragma unroll
        for (int kk = 0; kk < BKm; kk += 8) {
            uint32_t b[8][2];
            #pragma unroll
            for (int ntp = 0; ntp < 4; ++ntp) {
                const uint32_t addr = SBu +
                    (uint32_t)(((brow + ntp * 16) * SROW) + kk + bkoff) * 4;
                ldsm_x4(addr, b[2*ntp][0], b[2*ntp][1], b[2*ntp+1][0], b[2*ntp+1][1]);
            }
            #pragma unroll
            for (int mt = 0; mt < 2; ++mt) {
                uint32_t a0, a1, a2, a3;
                const uint32_t addr = SAu +
                    (uint32_t)(((arow + mt * 16) * SROW) + kk + akoff) * 4;
                ldsm_x4(addr, a0, a1, a2, a3);
                #pragma unroll
                for (int nt = 0; nt < 8; ++nt)
                    mma_m16n8k8(acc[mt][nt], a0, a1, a2, a3, b[nt][0], b[nt][1]);
            }
        }
    };

    // 3-stage pipeline: 2 chunks in flight, wait_group 1
    #pragma unroll
    for (int s = 0; s < STAGES - 1; ++s) {
        if (s < NCC) loadChunk(s, s);
        else CP_COMMIT();
    }
    for (int c = 0; c < NCC; ++c) {
        CP_WAIT1();
        __syncthreads();
        const int nc = c + STAGES - 1;
        if (nc < NCC) loadChunk(nc, nc % STAGES);
        else CP_COMMIT();
        compute(c % STAGES);
    }

    if (TRANSC) __syncthreads();   // pipeline smem about to be reused

    #pragma unroll
    for (int mt = 0; mt < 2; ++mt) {
        #pragma unroll
        for (int half = 0; half < 2; ++half) {
            const int m = m0 + wm + mt * 16 + gr + half * 8;
            const float rs = (EPI == 1) ? extra[m] : 0.f;
            #pragma unroll
            for (int nt = 0; nt < 8; ++nt) {
                const int n = n0 + wn + nt * 8 + gc * 2;
                float v0 = acc[mt][nt][half * 2 + 0];
                float v1 = acc[mt][nt][half * 2 + 1];
                if (ADD) {
                    const float2 ad = *reinterpret_cast<const float2*>(addC + (size_t)m * ldc + n);
                    v0 += ad.x; v1 += ad.y;
                }
                const float bb0 = bias ? bias[n]     : 0.f;
                const float bb1 = bias ? bias[n + 1] : 0.f;
                if (EPI == 0)      { v0 = v0 * alpha + bb0;  v1 = v1 * alpha + bb1; }
                else if (EPI == 1) { v0 = v0 * rs + bb0;     v1 = v1 * rs + bb1; }
                else if (EPI == 2) {
                    const float* g = extra + (size_t)(m >> 10) * CTX + n;
                    v0 = (v0 + bb0) * g[0];
                    v1 = (v1 + bb1) * g[1];
                } else {
                    const float* g = extra + (size_t)m * ldc + n;
                    v0 = (v0 + bb0) * g[0];
                    v1 = (v1 + bb1) * g[1];
                }
                if (RND) { v0 = rna_tf32(v0); v1 = rna_tf32(v1); }
                if (!TRANSC) {
                    *reinterpret_cast<float2*>(Cbase + (size_t)m * ldc + n) = make_float2(v0, v1);
                } else {
                    const int ml = wm + mt * 16 + gr + half * 8;
                    const int nl = wn + nt * 8 + gc * 2;
                    smem[(size_t)nl * TSST + ml] = v0;
                    smem[(size_t)(nl + 1) * TSST + ml] = v1;
                }
            }
        }
    }

    if (TRANSC) {
        __syncthreads();
        float* outT = C + (size_t)(m0 >> 10) * CTX * NENT;
        const int bofs = m0 & 1023;
        #pragma unroll
        for (int r = 0; r < 16; ++r) {
            const int row = wid * 16 + r;
            const float4 val = *reinterpret_cast<const float4*>(&smem[(size_t)row * TSST + lane * 4]);
            *reinterpret_cast<float4*>(outT + (size_t)(n0 + row) * NENT + bofs + lane * 4) = val;
        }
    }
}

// ---- per-batch mean over vT rows ----
__global__ void mean_vT_kernel(const float* __restrict__ vT, const int* __restrict__ ennum,
                               float* __restrict__ msgm)
{
    const int b = blockIdx.y;
    if (ennum[b] >= NENT) return;
    const int wid = threadIdx.x >> 5, lane = threadIdx.x & 31;
    const int d = blockIdx.x * 8 + wid;
    const float* row = vT + (size_t)b * CTX * NENT + (size_t)d * NENT;
    float s = 0.f;
    #pragma unroll
    for (int i = 0; i < NENT / 32; ++i) s += row[lane + 32 * i];
    #pragma unroll
    for (int o = 16; o > 0; o >>= 1) s += __shfl_down_sync(0xFFFFFFFFu, s, o);
    if (lane == 0) msgm[b * CTX + d] = rna_tf32(s * (1.f / NENT));
}

// ---- masked-row x_ctx update + broadcast ----
__global__ __launch_bounds__(256)
void ctx_bcast_kernel(const float* __restrict__ msgm, const float* __restrict__ wMU,
                      const float* __restrict__ mu_b, const int* __restrict__ ennum,
                      float* __restrict__ xcm, float* __restrict__ xn)
{
    const int b = blockIdx.x;
    const int en = ennum[b];
    if (en >= NENT) return;
    const int tid = threadIdx.x;
    const int wid = tid >> 5, lane = tid & 31;
    __shared__ float x[2 * CTX];
    __shared__ float y[CTX];
    for (int d = tid; d < CTX; d += 256) {
        x[d] = xcm[b * CTX + d];
        x[CTX + d] = msgm[b * CTX + d];
    }
    __syncthreads();
    for (int j = wid; j < CTX; j += 8) {
        const float* w = wMU + (size_t)j * (2 * CTX);
        float acc = 0.f;
        #pragma unroll
        for (int i = 0; i < (2 * CTX) / 32; ++i)
            acc = fmaf(x[lane + 32 * i], w[lane + 32 * i], acc);
        #pragma unroll
        for (int o = 16; o > 0; o >>= 1)
            acc += __shfl_down_sync(0xFFFFFFFFu, acc, o);
        if (lane == 0) y[j] = rna_tf32(acc + mu_b[j]);
    }
    __syncthreads();
    for (int d = tid; d < CTX; d += 256) xcm[b * CTX + d] = y[d];
    float* base = xn + (size_t)b * NENT * CTX;
    for (int m = en; m < NENT; ++m)
        for (int d = tid; d < CTX; d += 256)
            base[(size_t)m * CTX + d] = y[d];
}

// ---- transpose, optional tf32 round ----
template<bool RND>
__global__ void transpose_kernel(const float* __restrict__ in, float* __restrict__ out,
                                 int R, int C, size_t sIn, size_t sOut)
{
    __shared__ float tile[32][33];
    const int z = blockIdx.z;
    in  += (size_t)z * sIn;
    out += (size_t)z * sOut;
    const int r0 = blockIdx.y * 32, c0 = blockIdx.x * 32;
    #pragma unroll
    for (int i = threadIdx.y; i < 32; i += 8) {
        float x = in[(size_t)(r0 + i) * C + c0 + threadIdx.x];
        tile[i][threadIdx.x] = RND ? rna_tf32(x) : x;
    }
    __syncthreads();
    #pragma unroll
    for (int i = threadIdx.y; i < 32; i += 8)
        out[(size_t)(c0 + i) * R + r0 + threadIdx.x] = tile[threadIdx.x][i];
}

// ---- fused row inv-norm + tf32-rounded copy ----
__global__ void rownorm_round_kernel(const float* __restrict__ img, float* __restrict__ invn,
                                     float* __restrict__ imgr)
{
    const int m = blockIdx.x;
    const float4* r4 = reinterpret_cast<const float4*>(img + (size_t)m * DFEAT);
    float4* o4 = reinterpret_cast<float4*>(imgr + (size_t)m * DFEAT);
    const int tid = threadIdx.x;
    float s = 0.f;
    for (int i = tid; i < DFEAT / 4; i += 256) {
        float4 u = r4[i];
        s = fmaf(u.x, u.x, s); s = fmaf(u.y, u.y, s);
        s = fmaf(u.z, u.z, s); s = fmaf(u.w, u.w, s);
        u.x = rna_tf32(u.x); u.y = rna_tf32(u.y);
        u.z = rna_tf32(u.z); u.w = rna_tf32(u.w);
        o4[i] = u;
    }
    __shared__ float red[256];
    red[tid] = s; __syncthreads();
    for (int o = 128; o > 0; o >>= 1) { if (tid < o) red[tid] += red[tid + o]; __syncthreads(); }
    if (tid == 0) invn[m] = 1.f / fmaxf(sqrtf(red[0]), 1e-12f);
}

__global__ void ctx_init_kernel(const float* __restrict__ initMem, float* __restrict__ xctx,
                                float* __restrict__ xcm)
{
    const size_t i = (size_t)blockIdx.x * blockDim.x + threadIdx.x;
    const float val = rna_tf32(initMem[i & (CTX - 1)]);
    xctx[i] = val;
    if (i < BB * CTX) xcm[i] = val;
}

// ---- fast batch-32 linear ----
template<bool ELU>
__global__ void small_linear_fast(const float* __restrict__ in, const float* __restrict__ wT,
                                  const float* __restrict__ bias, float* __restrict__ out)
{
    const int b = blockIdx.y;
    const int jb = blockIdx.x * 32;
    const int tid = threadIdx.x;
    const int wid = tid >> 5, lane = tid & 31;
    __shared__ float x[CMD];
    for (int d = tid; d < CMD; d += 256) x[d] = in[b * CMD + d];
    __syncthreads();
    #pragma unroll
    for (int jj = 0; jj < 4; ++jj) {
        const int j = jb + wid * 4 + jj;
        const float* w = wT + (size_t)j * CMD;
        float acc = 0.f;
        #pragma unroll
        for (int i = 0; i < CMD / 32; ++i)
            acc = fmaf(x[lane + 32 * i], w[lane + 32 * i], acc);
        #pragma unroll
        for (int o = 16; o > 0; o >>= 1)
            acc += __shfl_down_sync(0xFFFFFFFFu, acc, o);
        if (lane == 0) {
            acc += bias[j];
            if (ELU) acc = (acc > 0.f) ? acc : expm1f(acc);
            out[b * CMD + j] = acc;
        }
    }
}

// ---- fast textual command ----
__global__ __launch_bounds__(1024)
void text_cmd_fast(const float* __restrict__ qcmd, const float* __restrict__ lstm,
                   const float* __restrict__ c2l_w, const float* __restrict__ c2l_b,
                   const int* __restrict__ qlen, float* __restrict__ cmd)
{
    const int b = blockIdx.x;
    const int tid = threadIdx.x;
    const int wid = tid >> 5, lane = tid & 31;
    __shared__ float e[CMD];
    __shared__ float att[LQL];
    __shared__ float red[128];
    __shared__ float smx, ssum;

    if (tid < CMD) e[tid] = qcmd[b * CMD + tid] * c2l_w[tid];
    __syncthreads();

    const int en = qlen[b];
    #pragma unroll
    for (int li = 0; li < 4; ++li) {
        const int l = wid + li * 32;
        const float* L = lstm + ((size_t)b * LQL + l) * CMD;
        float acc = 0.f;
        #pragma unroll
        for (int i = 0; i < CMD / 32; ++i)
            acc = fmaf(L[lane + 32 * i], e[lane + 32 * i], acc);
        #pragma unroll
        for (int o = 16; o > 0; o >>= 1)
            acc += __shfl_down_sync(0xFFFFFFFFu, acc, o);
        if (lane == 0) att[l] = (l >= en) ? NEGV : (acc + c2l_b[0]);
    }
    __syncthreads();

    if (tid < 128) red[tid] = att[tid];
    __syncthreads();
    for (int o = 64; o > 0; o >>= 1) {
        if (tid < o) red[tid] = fmaxf(red[tid], red[tid + o]);
        __syncthreads();
    }
    if (tid == 0) smx = red[0];
    __syncthreads();
    float ev = 0.f;
    if (tid < 128) { ev = expf(att[tid] - smx); red[tid] = ev; }
    __syncthreads();
    for (int o = 64; o > 0; o >>= 1) {
        if (tid < o) red[tid] += red[tid + o];
        __syncthreads();
    }
    if (tid == 0) ssum = red[0];
    __syncthreads();
    if (tid < 128) att[tid] = ev / ssum;
    __syncthreads();

    if (tid < CMD) {
        float acc = 0.f;
        const float* L = lstm + (size_t)b * LQL * CMD + tid;
        #pragma unroll 4
        for (int l = 0; l < LQL; ++l)
            acc = fmaf(att[l], L[(size_t)l * CMD], acc);
        cmd[b * CMD + tid] = acc;
    }
}

// masked row softmax (in place); cleans all cols < nblk*256 (covers BKm=32 K-truncation)
__global__ void attn_softmax_kernel(float* __restrict__ score, const int* __restrict__ entity_num)
{
    const int row = blockIdx.x;
    const int b = row >> 10;
    const int n = row & 1023;
    const int en = entity_num[b];
    if (n >= en) return;
    float* s = score + (size_t)row * NENT;
    const int tid = threadIdx.x;

    const int kc = ((en + 15) / 16) * 16;
    const int nblk = (kc + 255) >> 8;

    float v[4];
    float mx = -3.4e38f;
    #pragma unroll
    for (int j = 0; j < 4; j++) {
        const int m = tid + j * 256;
        float x = NEGV;
        if (j < nblk && m < en) x = s[m];
        v[j] = x;
        mx = fmaxf(mx, x);
    }
    __shared__ float red[256];
    red[tid] = mx; __syncthreads();
    for (int o = 128; o > 0; o >>= 1) { if (tid < o) red[tid] = fmaxf(red[tid], red[tid + o]); __syncthreads(); }
    mx = red[0];
    __syncthreads();

    float sum = 0.f;
    #pragma unroll
    for (int j = 0; j < 4; j++) { v[j] = expf(v[j] - mx); sum += v[j]; }
    red[tid] = sum; __syncthreads();
    for (int o = 128; o > 0; o >>= 1) { if (tid < o) red[tid] += red[tid + o]; __syncthreads(); }
    const float inv = 1.f / red[0];

    #pragma unroll
    for (int j = 0; j < 4; j++)
        if (j < nblk) s[tid + j * 256] = rna_tf32(v[j] * inv);
}

// ---------------- launch ----------------
template<typename T> static float* symaddr(T& sym) {
    void* p = nullptr;
    cudaGetSymbolAddress(&p, sym);
    return (float*)p;
}

extern "C" void kernel_launch(void* const* d_in, const int* in_sizes, int n_in,
                              void* d_out, int out_size)
{
    const float* images    = (const float*)d_in[0];
    const float* q_enc     = (const float*)d_in[1];
    const float* lstm      = (const float*)d_in[2];
    const int*   q_length  = (const int*)  d_in[3];
    const int*   ent_num   = (const int*)  d_in[4];
    const float* initKB_w  = (const float*)d_in[5];
    const float* initKB_b  = (const float*)d_in[6];
    const float* initMem   = (const float*)d_in[7];
    const float* qInput_w  = (const float*)d_in[8];
    const float* qInput_b  = (const float*)d_in[9];
    const float* qInput2_w = (const float*)d_in[10];
    const float* qInput2_b = (const float*)d_in[11];
    const float* c2l_w     = (const float*)d_in[12];
    const float* c2l_b     = (const float*)d_in[13];
    const float* pxl_w     = (const float*)d_in[14];
    const float* pxl_b     = (const float*)d_in[15];
    const float* pxc_w     = (const float*)d_in[16];
    const float* pxc_b     = (const float*)d_in[17];
    const float* qry_w     = (const float*)d_in[18];
    const float* qry_b     = (const float*)d_in[19];
    const float* key_w     = (const float*)d_in[20];
    const float* key_b     = (const float*)d_in[21];
    const float* val_w     = (const float*)d_in[22];
    const float* val_b     = (const float*)d_in[23];
    const float* pk_w      = (const float*)d_in[24];
    const float* pk_b      = (const float*)d_in[25];
    const float* pv_w      = (const float*)d_in[26];
    const float* pv_b      = (const float*)d_in[27];
    const float* mu_w      = (const float*)d_in[28];
    const float* mu_b      = (const float*)d_in[29];
    const float* ck_w      = (const float*)d_in[30];
    const float* ck_b      = (const float*)d_in[31];

    float* imgr  = symaddr(g_imgr);
    float* invn  = symaddr(g_invnorm);
    float* xloc  = symaddr(g_xloc);
    float* xctxA = symaddr(g_xctx0);
    float* xctxB = symaddr(g_xctx1);
    float* prjl  = symaddr(g_projloc);
    float* pp    = symaddr(g_pp);
    float* q     = symaddr(g_q);
    float* k     = symaddr(g_k);
    float* vT    = symaddr(g_vT);
    float* msg   = symaddr(g_msg);
    float* qL    = symaddr(g_qL);
    float* kL    = symaddr(g_kL);
    float* vL    = symaddr(g_vL);
    float* score = symaddr(g_score);
    float* qbase = symaddr(g_qbase);
    float* qcmd  = symaddr(g_qcmd);
    float* cmd   = symaddr(g_cmd);
    float* pkg   = symaddr(g_pkg);
    float* pvg   = symaddr(g_pvg);
    float* msgm  = symaddr(g_msgm);
    float* xcm   = symaddr(g_xcm);
    float* wIKB  = symaddr(g_wT_ikb);
    float* wPXL  = symaddr(g_wT_pxl);
    float* wPXC  = symaddr(g_wT_pxc);
    float* wQRY  = symaddr(g_wT_qry);
    float* wKEY  = symaddr(g_wT_key);
    float* wVAL  = symaddr(g_wT_val);
    float* wMU   = symaddr(g_wT_mu);
    float* wCK   = symaddr(g_wT_ck);
    float* wQIN  = symaddr(g_wT_qin);
    float* wQIN2 = symaddr(g_wT_qin2);
    float* wPK   = symaddr(g_wT_pk);
    float* wPV   = symaddr(g_wT_pv);

    cudaFuncSetAttribute(gemm_mma<1,0,false,false,0,false>, cudaFuncAttributeMaxDynamicSharedMemorySize, SMEM_DYN);
    cudaFuncSetAttribute(gemm_mma<1,0,false,false,3,false>, cudaFuncAttributeMaxDynamicSharedMemorySize, SMEM_DYN);
    cudaFuncSetAttribute(gemm_mma<1,1,true ,false,0,false>, cudaFuncAttributeMaxDynamicSharedMemorySize, SMEM_DYN);
    cudaFuncSetAttribute(gemm_mma<1,3,true ,false,0,false>, cudaFuncAttributeMaxDynamicSharedMemorySize, SMEM_DYN);
    cudaFuncSetAttribute(gemm_mma<1,0,false,false,1,false>, cudaFuncAttributeMaxDynamicSharedMemorySize, SMEM_DYN);
    cudaFuncSetAttribute(gemm_mma<1,0,true ,false,2,false>, cudaFuncAttributeMaxDynamicSharedMemorySize, SMEM_DYN);
    cudaFuncSetAttribute(gemm_mma<2,0,true ,true ,3,false>, cudaFuncAttributeMaxDynamicSharedMemorySize, SMEM_DYN);
    cudaFuncSetAttribute(gemm_mma<2,2,true ,true ,3,false>, cudaFuncAttributeMaxDynamicSharedMemorySize, SMEM_DYN);
    cudaFuncSetAttribute(gemm_mma<2,2,true ,true ,0,true >, cudaFuncAttributeMaxDynamicSharedMemorySize, SMEM_DYN);
    cudaFuncSetAttribute(gemm_mma<2,0,true ,false,3,false>, cudaFuncAttributeMaxDynamicSharedMemorySize, SMEM_DYN);
    cudaFuncSetAttribute(gemm_mma<2,0,false,false,0,false>, cudaFuncAttributeMaxDynamicSharedMemorySize, SMEM_DYN);

    const float scale = 0.044194173824159216f;   // 1/sqrt(512)
    const dim3 tdim(32, 8);
    const dim3 gridMain(CTX / BNm, MROWS / BMm, 1);
    const dim3 gridScore(NENT / BNm, NENT / BMm, BB);
    const dim3 gridMsg(CTX / BNm, NENT / BMm, BB);
    const dim3 gridSL(CMD / 32, BB);

    // --- order: initKB GEMM at launch index 3 (ncu -s 5) ---
    transpose_kernel<true ><<<dim3(CTX/32, DFEAT/32, 1), tdim>>>(initKB_w, wIKB, DFEAT, CTX, 0, 0); // 0
    rownorm_round_kernel<<<MROWS, 256>>>(images, invn, imgr);                                        // 1
    ctx_init_kernel<<<(MROWS * CTX) / 256, 256>>>(initMem, xctxA, xcm);                              // 2
    // 3: x_loc = normalize(images) @ initKB_w + b   <-- ncu target
    gemm_mma<1,1,true,false,0,false><<<gridMain, 256, SMEM_DYN>>>(
        imgr, nullptr, nullptr, wIKB, initKB_b, invn, nullptr, nullptr, xloc,
        DFEAT, DFEAT, DFEAT, CTX, 0, 0, 0, 1.f);

    // remaining weight transposes
    transpose_kernel<false><<<dim3(CMD/32, CMD/32, 1), tdim>>>(qInput_w, wQIN, CMD, CMD, 0, 0);
    small_linear_fast<true><<<gridSL, 256>>>(q_enc, wQIN, qInput_b, qbase);
    transpose_kernel<true><<<dim3(CTX/32, CTX/32, 1),   tdim>>>(pxl_w, wPXL, CTX,   CTX, 0, 0);
    transpose_kernel<true><<<dim3(CTX/32, CTX/32, 1),   tdim>>>(pxc_w, wPXC, CTX,   CTX, 0, 0);
    transpose_kernel<true><<<dim3(CTX/32, 3*CTX/32, 1), tdim>>>(qry_w, wQRY, 3*CTX, CTX, 0, 0);
    transpose_kernel<true><<<dim3(CTX/32, 3*CTX/32, 1), tdim>>>(key_w, wKEY, 3*CTX, CTX, 0, 0);
    transpose_kernel<true><<<dim3(CTX/32, 3*CTX/32, 1), tdim>>>(val_w, wVAL, 3*CTX, CTX, 0, 0);
    transpose_kernel<true><<<dim3(CTX/32, 2*CTX/32, 1), tdim>>>(mu_w,  wMU,  2*CTX, CTX, 0, 0);
    transpose_kernel<true><<<dim3(CTX/32, 2*CTX/32, 1), tdim>>>(ck_w,  wCK,  2*CTX, CTX, 0, 0);
    transpose_kernel<false><<<dim3(CMD/32, CMD/32, TT), tdim>>>(qInput2_w, wQIN2, CMD, CMD,
                                                                (size_t)CMD*CMD, (size_t)CMD*CMD);
    transpose_kernel<false><<<dim3(CTX/32, CMD/32, 1), tdim>>>(pk_w, wPK, CMD, CTX, 0, 0);
    transpose_kernel<false><<<dim3(CTX/32, CMD/32, 1), tdim>>>(pv_w, wPV, CMD, CTX, 0, 0);

    // ---- iteration-invariant hoists ----
    gemm_mma<1,0,false,false,0,false><<<gridMain, 256, SMEM_DYN>>>(
        xloc, nullptr, nullptr, wPXL, pxl_b, nullptr, nullptr, nullptr, prjl,
        CTX, CTX, CTX, CTX, 0, 0, 0, 1.f);
    gemm_mma<1,0,false,false,3,false><<<gridMain, 256, SMEM_DYN>>>(
        xloc, nullptr, nullptr, wQRY, nullptr, nullptr, nullptr, ent_num, qL,
        CTX, CTX, 3*CTX, CTX, 0, 0, 0, 1.f);
    gemm_mma<1,0,false,false,3,false><<<gridMain, 256, SMEM_DYN>>>(
        xloc, nullptr, nullptr, wKEY, nullptr, nullptr, nullptr, ent_num, kL,
        CTX, CTX, 3*CTX, CTX, 0, 0, 0, 1.f);
    gemm_mma<1,0,false,false,0,false><<<gridMain, 256, SMEM_DYN>>>(
        xloc, nullptr, nullptr, wVAL, nullptr, nullptr, nullptr, nullptr, vL,
        CTX, CTX, 3*CTX, CTX, 0, 0, 0, 1.f);

    float* xc = xctxA;
    float* xn = xctxB;
    for (int t = 0; t < TT; t++) {
        small_linear_fast<false><<<gridSL, 256>>>(qbase, wQIN2 + (size_t)t * CMD * CMD,
                                                  qInput2_b + (size_t)t * CMD, qcmd);
        text_cmd_fast<<<BB, 1024>>>(qcmd, lstm, c2l_w, c2l_b, q_length, cmd);
        small_linear_fast<false><<<gridSL, 256>>>(cmd, wPK, pk_b, pkg);
        small_linear_fast<false><<<gridSL, 256>>>(cmd, wPV, pv_b, pvg);

        // pp = (x_ctx @ pxc + b) * proj_loc   (full: v needs all rows)
        gemm_mma<1,3,true,false,0,false><<<gridMain, 256, SMEM_DYN>>>(
            xc, nullptr, nullptr, wPXC, pxc_b, prjl, nullptr, nullptr, pp,
            CTX, CTX, CTX, CTX, 0, 0, 0, 1.f);

        // q/k: live rows only; v: full, written TRANSPOSED directly to vT
        gemm_mma<2,0,true,true,3,false><<<gridMain, 256, SMEM_DYN>>>(
            xc, pp, nullptr, wQRY + CTX, qry_b, nullptr, qL, ent_num, q,
            2*CTX, 0, 3*CTX, CTX, 0, 0, 0, 1.f);
        gemm_mma<2,2,true,true,3,false><<<gridMain, 256, SMEM_DYN>>>(
            xc, pp, nullptr, wKEY + CTX, key_b, pkg, kL, ent_num, k,
            2*CTX, 0, 3*CTX, CTX, 0, 0, 0, 1.f);
        gemm_mma<2,2,true,true,0,true><<<gridMain, 256, SMEM_DYN>>>(
            xc, pp, nullptr, wVAL + CTX, val_b, pvg, vL, nullptr, vT,
            2*CTX, 0, 3*CTX, CTX, 0, 0, 0, 1.f);

        // score[b] = scale * q[b] @ k[b]^T — live tiles only
        gemm_mma<1,0,false,false,1,false><<<gridScore, 256, SMEM_DYN>>>(
            q, nullptr, nullptr, k, nullptr, nullptr, nullptr, ent_num, score,
            CTX, CTX, CTX, NENT,
            (size_t)NENT * CTX, (size_t)NENT * CTX, (size_t)NENT * NENT, scale);

        attn_softmax_kernel<<<MROWS, 256>>>(score, ent_num);

        // message live rows; per-batch mean(v) for masked rows
        gemm_mma<1,0,true,false,2,false><<<gridMsg, 256, SMEM_DYN>>>(
            score, nullptr, nullptr, vT, nullptr, nullptr, nullptr, ent_num, msg,
            NENT, NENT, NENT, CTX,
            (size_t)NENT * NENT, (size_t)CTX * NENT, (size_t)NENT * CTX, 1.f);
        mean_vT_kernel<<<dim3(CTX / 8, BB), 256>>>(vT, ent_num, msgm);

        // x_ctx' live rows via MMA; masked rows via per-batch broadcast
        gemm_mma<2,0,true,false,3,false><<<gridMain, 256, SMEM_DYN>>>(
            xc, msg, nullptr, wMU, mu_b, nullptr, nullptr, ent_num, xn,
            2*CTX, 0, 2*CTX, CTX, 0, 0, 0, 1.f);
        ctx_bcast_kernel<<<BB, 256>>>(msgm, wMU, mu_b, ent_num, xcm, xn);

        float* tmp = xc; xc = xn; xn = tmp;
    }

    // out = [x_loc | x_ctx] @ ck + b
    gemm_mma<2,0,false,false,0,false><<<gridMain, 256, SMEM_DYN>>>(
        xloc, xc, nullptr, wCK, ck_b, nullptr, nullptr, nullptr, (float*)d_out,
        2*CTX, 0, 2*CTX, CTX, 0, 0, 0, 1.f);
}

// round 12
// speedup vs baseline: 6.9253x; 1.0398x over previous
#include <cuda_runtime.h>
#include <math.h>
#include <stdint.h>

#define BB     32
#define NENT   1024
#define LQL    128
#define DFEAT  2112
#define CTX    512
#define CMD    512
#define TT     4
#define MROWS  (BB*NENT)
#define NEGV   (-1e30f)

// ---- mma.sync GEMM tiling ----
#define BMm 128
#define BNm 128
#define BKm 32
#define STAGES 3
#define SROW 36
#define STAGE_F (2 * BMm * SROW)
#define TILE_F  (BMm * SROW)
#define SMEM_DYN (STAGES * STAGE_F * 4)
#define TSST 132

// ---- scratch ----
__device__ float g_imgr   [(size_t)MROWS*DFEAT];
__device__ float g_invnorm[MROWS];
__device__ float g_xloc   [(size_t)MROWS*CTX];
__device__ float g_xctx0  [(size_t)MROWS*CTX];
__device__ float g_xctx1  [(size_t)MROWS*CTX];
__device__ float g_projloc[(size_t)MROWS*CTX];
__device__ float g_pp     [(size_t)MROWS*CTX];
__device__ float g_q      [(size_t)MROWS*CTX];
__device__ float g_k      [(size_t)MROWS*CTX];
__device__ float g_vT     [(size_t)MROWS*CTX];   // [B][CTX][NENT]
__device__ float g_msg    [(size_t)MROWS*CTX];
__device__ float g_qL     [(size_t)MROWS*CTX];
__device__ float g_kL     [(size_t)MROWS*CTX];
__device__ float g_vL     [(size_t)MROWS*CTX];
__device__ float g_score  [(size_t)BB*NENT*NENT];
__device__ float g_qbase  [BB*CMD];
__device__ float g_qcmd   [BB*CMD];
__device__ float g_cmd    [BB*CMD];
__device__ float g_pkg    [BB*CTX];
__device__ float g_pvg    [BB*CTX];
__device__ float g_msgm   [BB*CTX];
__device__ float g_xcm    [BB*CTX];
__device__ float g_wT_ikb[(size_t)CTX*DFEAT];
__device__ float g_wT_pxl[(size_t)CTX*CTX];
__device__ float g_wT_pxc[(size_t)CTX*CTX];
__device__ float g_wT_qry[(size_t)CTX*3*CTX];
__device__ float g_wT_key[(size_t)CTX*3*CTX];
__device__ float g_wT_val[(size_t)CTX*3*CTX];
__device__ float g_wT_mu [(size_t)CTX*2*CTX];
__device__ float g_wT_ck [(size_t)CTX*2*CTX];
__device__ float g_wT_qin [(size_t)CMD*CMD];
__device__ float g_wT_qin2[(size_t)TT*CMD*CMD];
__device__ float g_wT_pk  [(size_t)CMD*CTX];
__device__ float g_wT_pv  [(size_t)CMD*CTX];

__device__ __forceinline__ float rna_tf32(float f) {
    uint32_t r; asm("cvt.rna.tf32.f32 %0, %1;" : "=r"(r) : "f"(f));
    return __uint_as_float(r);
}
__device__ __forceinline__ uint32_t smem_u32(const void* p) {
    uint32_t a;
    asm("{ .reg .u64 t; cvta.to.shared.u64 t, %1; cvt.u32.u64 %0, t; }" : "=r"(a) : "l"(p));
    return a;
}
__device__ __forceinline__ void cp_async16(uint32_t saddr, const void* gptr) {
    asm volatile("cp.async.cg.shared.global [%0], [%1], 16;" :: "r"(saddr), "l"(gptr));
}
#define CP_COMMIT() asm volatile("cp.async.commit_group;" ::: "memory")
#define CP_WAIT1()  asm volatile("cp.async.wait_group 1;" ::: "memory")

__device__ __forceinline__ void ldsm_x4(uint32_t addr, uint32_t& r0, uint32_t& r1,
                                        uint32_t& r2, uint32_t& r3)
{
    asm volatile("ldmatrix.sync.aligned.m8n8.x4.shared.b16 {%0,%1,%2,%3}, [%4];"
                 : "=r"(r0), "=r"(r1), "=r"(r2), "=r"(r3) : "r"(addr));
}

__device__ __forceinline__ void mma_m16n8k8(float* d,
    uint32_t a0, uint32_t a1, uint32_t a2, uint32_t a3,
    uint32_t b0, uint32_t b1)
{
    asm volatile(
        "mma.sync.aligned.m16n8k8.row.col.f32.tf32.tf32.f32 "
        "{%0,%1,%2,%3}, {%4,%5,%6,%7}, {%8,%9}, {%0,%1,%2,%3};"
        : "+f"(d[0]), "+f"(d[1]), "+f"(d[2]), "+f"(d[3])
        : "r"(a0), "r"(a1), "r"(a2), "r"(a3), "r"(b0), "r"(b1));
}

// ---------------- tensor-core GEMM via mma.sync (tf32) ----------------
// MASK 0: none
//      1 (score, z=batch): skip tile if m0>=en || n0>=en
//      2 (message, z=batch): skip tile if m0>=en; truncate K at ceil(en/BKm)
//      3 (row-masked, z=1, batch=m0>>10): skip tile if (m0&1023)>=en
// TRANSC: write C transposed per batch: C is [B][CTX][NENT]; batch = m0>>10.
template<int NSRC, int EPI, bool RND, bool ADD, int MASK, bool TRANSC>
__global__ __launch_bounds__(256, 2)
void gemm_mma(const float* __restrict__ A0, const float* __restrict__ A1,
              const float* __restrict__ A2, const float* __restrict__ Bt,
              const float* __restrict__ bias, const float* __restrict__ extra,
              const float* __restrict__ addC, const int* __restrict__ ennum,
              float* __restrict__ C,
              int K, int lda, int ldb, int ldc,
              size_t sA, size_t sB, size_t sC, float alpha)
{
    extern __shared__ float smem[];
    const uint32_t sbase = smem_u32(smem);

    const int tid = threadIdx.x;
    const int z = blockIdx.z;
    const int m0 = blockIdx.y * BMm;
    const int n0 = blockIdx.x * BNm;

    int Keff = K;
    if (MASK == 1 || MASK == 2) {
        const int en = ennum[z];
        if (m0 >= en) return;
        if (MASK == 1 && n0 >= en) return;
        if (MASK == 2) { const int kc = ((en + BKm - 1) / BKm) * BKm; Keff = kc < K ? kc : K; }
    } else if (MASK == 3) {
        const int en = ennum[m0 >> 10];
        if ((m0 & 1023) >= en) return;
    }

    const float* Abase = A0 + (size_t)z * sA;
    const float* Bbase = Bt + (size_t)z * sB;
    float* Cbase = C + (size_t)z * sC;

    const int wid = tid >> 5, lane = tid & 31;
    const int wm = (wid & 3) * 32;
    const int wn = (wid >> 2) * 64;
    const int gr = lane >> 2;
    const int gc = lane & 3;

    const int lr = lane & 7, lg = lane >> 3;
    const int arow  = wm + lr + (lg & 1) * 8;
    const int akoff = (lg >> 1) * 4;
    const int brow  = wn + lr + (lg >> 1) * 8;
    const int bkoff = (lg & 1) * 4;

    const int prow0 = tid >> 3;              // 0..31
    const int pkq   = (tid & 7) * 4;         // k float4 offset within 32

    float acc[2][8][4] = {};
    const int NCC = Keff / BKm;

    auto loadChunk = [&](int c, int st) {
        const int k0 = c * BKm;
        const float* Ap; int al, ak;
        if (NSRC == 1) { Ap = Abase; al = lda; ak = k0; }
        else {
            const int src = k0 >> 9;
            Ap = (src == 0) ? A0 : ((src == 1) ? A1 : A2);
            al = CTX; ak = k0 & (CTX - 1);
        }
        const uint32_t sa = sbase + (uint32_t)(st * STAGE_F) * 4;
        const uint32_t sb = sa + (uint32_t)TILE_F * 4;
        #pragma unroll
        for (int t = 0; t < 4; ++t) {
            const int row = prow0 + t * 32;
            cp_async16(sa + (uint32_t)(row * SROW + pkq) * 4,
                       Ap + (size_t)(m0 + row) * al + ak + pkq);
            cp_async16(sb + (uint32_t)(row * SROW + pkq) * 4,
                       Bbase + (size_t)(n0 + row) * ldb + k0 + pkq);
        }
        CP_COMMIT();
    };

    auto compute = [&](int st) {
        const uint32_t SAu = sbase + (uint32_t)(st * STAGE_F) * 4;
        const uint32_t SBu = SAu + (uint32_t)TILE_F * 4;
        #pragma unroll
        for (int kk = 0; kk < BKm; kk += 8) {
            uint32_t b[8][2];
            #pragma unroll
            for (int ntp = 0; ntp < 4; ++ntp) {
                const uint32_t addr = SBu +
                    (uint32_t)(((brow + ntp * 16) * SROW) + kk + bkoff) * 4;
                ldsm_x4(addr, b[2*ntp][0], b[2*ntp][1], b[2*ntp+1][0], b[2*ntp+1][1]);
            }
            #pragma unroll
            for (int mt = 0; mt < 2; ++mt) {
                uint32_t a0, a1, a2, a3;
                const uint32_t addr = SAu +
                    (uint32_t)(((arow + mt * 16) * SROW) + kk + akoff) * 4;
                ldsm_x4(addr, a0, a1, a2, a3);
                #pragma unroll
                for (int nt = 0; nt < 8; ++nt)
                    mma_m16n8k8(acc[mt][nt], a0, a1, a2, a3, b[nt][0], b[nt][1]);
            }
        }
    };

    // 3-stage pipeline: 2 chunks in flight, wait_group 1 (stage counters, no %)
    #pragma unroll
    for (int s = 0; s < STAGES - 1; ++s) {
        if (s < NCC) loadChunk(s, s);
        else CP_COMMIT();
    }
    {
        int st = 0;
        for (int c = 0; c < NCC; ++c) {
            CP_WAIT1();
            __syncthreads();
            const int nc = c + STAGES - 1;
            int nst = st + STAGES - 1; if (nst >= STAGES) nst -= STAGES;
            if (nc < NCC) loadChunk(nc, nst);
            else CP_COMMIT();
            compute(st);
            if (++st == STAGES) st = 0;
        }
    }

    if (TRANSC) __syncthreads();

    #pragma unroll
    for (int mt = 0; mt < 2; ++mt) {
        #pragma unroll
        for (int half = 0; half < 2; ++half) {
            const int m = m0 + wm + mt * 16 + gr + half * 8;
            const float rs = (EPI == 1) ? extra[m] : 0.f;
            #pragma unroll
            for (int nt = 0; nt < 8; ++nt) {
                const int n = n0 + wn + nt * 8 + gc * 2;
                float v0 = acc[mt][nt][half * 2 + 0];
                float v1 = acc[mt][nt][half * 2 + 1];
                if (ADD) {
                    const float2 ad = *reinterpret_cast<const float2*>(addC + (size_t)m * ldc + n);
                    v0 += ad.x; v1 += ad.y;
                }
                const float bb0 = bias ? bias[n]     : 0.f;
                const float bb1 = bias ? bias[n + 1] : 0.f;
                if (EPI == 0)      { v0 = v0 * alpha + bb0;  v1 = v1 * alpha + bb1; }
                else if (EPI == 1) { v0 = v0 * rs + bb0;     v1 = v1 * rs + bb1; }
                else if (EPI == 2) {
                    const float* g = extra + (size_t)(m >> 10) * CTX + n;
                    v0 = (v0 + bb0) * g[0];
                    v1 = (v1 + bb1) * g[1];
                } else {
                    const float* g = extra + (size_t)m * ldc + n;
                    v0 = (v0 + bb0) * g[0];
                    v1 = (v1 + bb1) * g[1];
                }
                if (RND) { v0 = rna_tf32(v0); v1 = rna_tf32(v1); }
                if (!TRANSC) {
                    *reinterpret_cast<float2*>(Cbase + (size_t)m * ldc + n) = make_float2(v0, v1);
                } else {
                    const int ml = wm + mt * 16 + gr + half * 8;
                    const int nl = wn + nt * 8 + gc * 2;
                    smem[(size_t)nl * TSST + ml] = v0;
                    smem[(size_t)(nl + 1) * TSST + ml] = v1;
                }
            }
        }
    }

    if (TRANSC) {
        __syncthreads();
        float* outT = C + (size_t)(m0 >> 10) * CTX * NENT;
        const int bofs = m0 & 1023;
        #pragma unroll
        for (int r = 0; r < 16; ++r) {
            const int row = wid * 16 + r;
            const float4 val = *reinterpret_cast<const float4*>(&smem[(size_t)row * TSST + lane * 4]);
            *reinterpret_cast<float4*>(outT + (size_t)(n0 + row) * NENT + bofs + lane * 4) = val;
        }
    }
}

// ---- per-batch mean over vT rows ----
__global__ void mean_vT_kernel(const float* __restrict__ vT, const int* __restrict__ ennum,
                               float* __restrict__ msgm)
{
    const int b = blockIdx.y;
    if (ennum[b] >= NENT) return;
    const int wid = threadIdx.x >> 5, lane = threadIdx.x & 31;
    const int d = blockIdx.x * 8 + wid;
    const float* row = vT + (size_t)b * CTX * NENT + (size_t)d * NENT;
    float s = 0.f;
    #pragma unroll
    for (int i = 0; i < NENT / 32; ++i) s += row[lane + 32 * i];
    #pragma unroll
    for (int o = 16; o > 0; o >>= 1) s += __shfl_down_sync(0xFFFFFFFFu, s, o);
    if (lane == 0) msgm[b * CTX + d] = rna_tf32(s * (1.f / NENT));
}

// ---- masked-row x_ctx compute: y = rna([xcm|msgm]@mu + b); xcm <- y ----
__global__ __launch_bounds__(256)
void ctx_compute_kernel(const float* __restrict__ msgm, const float* __restrict__ wMU,
                        const float* __restrict__ mu_b, const int* __restrict__ ennum,
                        float* __restrict__ xcm)
{
    const int b = blockIdx.x;
    if (ennum[b] >= NENT) return;
    const int tid = threadIdx.x;
    const int wid = tid >> 5, lane = tid & 31;
    __shared__ float x[2 * CTX];
    __shared__ float y[CTX];
    for (int d = tid; d < CTX; d += 256) {
        x[d] = xcm[b * CTX + d];
        x[CTX + d] = msgm[b * CTX + d];
    }
    __syncthreads();
    for (int j = wid; j < CTX; j += 8) {
        const float* w = wMU + (size_t)j * (2 * CTX);
        float acc = 0.f;
        #pragma unroll
        for (int i = 0; i < (2 * CTX) / 32; ++i)
            acc = fmaf(x[lane + 32 * i], w[lane + 32 * i], acc);
        #pragma unroll
        for (int o = 16; o > 0; o >>= 1)
            acc += __shfl_down_sync(0xFFFFFFFFu, acc, o);
        if (lane == 0) y[j] = rna_tf32(acc + mu_b[j]);
    }
    __syncthreads();
    for (int d = tid; d < CTX; d += 256) xcm[b * CTX + d] = y[d];
}

// ---- broadcast xcm row into xn masked rows (parallel over 128-row slices) ----
__global__ __launch_bounds__(256)
void bcast_rows_kernel(const float* __restrict__ xcm, const int* __restrict__ ennum,
                       float* __restrict__ xn)
{
    const int b = blockIdx.y;
    const int en = ennum[b];
    const int r0 = blockIdx.x * 128;
    int start = r0 > en ? r0 : en;
    const int end = r0 + 128;
    if (start >= end) return;
    __shared__ float y[CTX];
    const int tid = threadIdx.x;
    for (int d = tid; d < CTX; d += 256) y[d] = xcm[b * CTX + d];
    __syncthreads();
    const int c4 = (tid & 127) * 4;     // column (float4)
    const int rstep = 2;                // 256 threads cover 2 rows per pass
    const float4 val = *reinterpret_cast<const float4*>(&y[c4]);
    float* base = xn + (size_t)b * NENT * CTX;
    for (int m = start + (tid >> 7); m < end; m += rstep)
        *reinterpret_cast<float4*>(base + (size_t)m * CTX + c4) = val;
}

// ---- transpose, optional tf32 round ----
template<bool RND>
__global__ void transpose_kernel(const float* __restrict__ in, float* __restrict__ out,
                                 int R, int C, size_t sIn, size_t sOut)
{
    __shared__ float tile[32][33];
    const int z = blockIdx.z;
    in  += (size_t)z * sIn;
    out += (size_t)z * sOut;
    const int r0 = blockIdx.y * 32, c0 = blockIdx.x * 32;
    #pragma unroll
    for (int i = threadIdx.y; i < 32; i += 8) {
        float x = in[(size_t)(r0 + i) * C + c0 + threadIdx.x];
        tile[i][threadIdx.x] = RND ? rna_tf32(x) : x;
    }
    __syncthreads();
    #pragma unroll
    for (int i = threadIdx.y; i < 32; i += 8)
        out[(size_t)(c0 + i) * R + r0 + threadIdx.x] = tile[threadIdx.x][i];
}

// ---- fused row inv-norm + tf32-rounded copy ----
__global__ void rownorm_round_kernel(const float* __restrict__ img, float* __restrict__ invn,
                                     float* __restrict__ imgr)
{
    const int m = blockIdx.x;
    const float4* r4 = reinterpret_cast<const float4*>(img + (size_t)m * DFEAT);
    float4* o4 = reinterpret_cast<float4*>(imgr + (size_t)m * DFEAT);
    const int tid = threadIdx.x;
    float s = 0.f;
    for (int i = tid; i < DFEAT / 4; i += 256) {
        float4 u = r4[i];
        s = fmaf(u.x, u.x, s); s = fmaf(u.y, u.y, s);
        s = fmaf(u.z, u.z, s); s = fmaf(u.w, u.w, s);
        u.x = rna_tf32(u.x); u.y = rna_tf32(u.y);
        u.z = rna_tf32(u.z); u.w = rna_tf32(u.w);
        o4[i] = u;
    }
    __shared__ float red[256];
    red[tid] = s; __syncthreads();
    for (int o = 128; o > 0; o >>= 1) { if (tid < o) red[tid] += red[tid + o]; __syncthreads(); }
    if (tid == 0) invn[m] = 1.f / fmaxf(sqrtf(red[0]), 1e-12f);
}

__global__ void ctx_init_kernel(const float* __restrict__ initMem, float* __restrict__ xctx,
                                float* __restrict__ xcm)
{
    const size_t i = (size_t)blockIdx.x * blockDim.x + threadIdx.x;
    const float val = rna_tf32(initMem[i & (CTX - 1)]);
    xctx[i] = val;
    if (i < BB * CTX) xcm[i] = val;
}

// ---- fast batch-32 linear ----
template<bool ELU>
__global__ void small_linear_fast(const float* __restrict__ in, const float* __restrict__ wT,
                                  const float* __restrict__ bias, float* __restrict__ out)
{
    const int b = blockIdx.y;
    const int jb = blockIdx.x * 32;
    const int tid = threadIdx.x;
    const int wid = tid >> 5, lane = tid & 31;
    __shared__ float x[CMD];
    for (int d = tid; d < CMD; d += 256) x[d] = in[b * CMD + d];
    __syncthreads();
    #pragma unroll
    for (int jj = 0; jj < 4; ++jj) {
        const int j = jb + wid * 4 + jj;
        const float* w = wT + (size_t)j * CMD;
        float acc = 0.f;
        #pragma unroll
        for (int i = 0; i < CMD / 32; ++i)
            acc = fmaf(x[lane + 32 * i], w[lane + 32 * i], acc);
        #pragma unroll
        for (int o = 16; o > 0; o >>= 1)
            acc += __shfl_down_sync(0xFFFFFFFFu, acc, o);
        if (lane == 0) {
            acc += bias[j];
            if (ELU) acc = (acc > 0.f) ? acc : expm1f(acc);
            out[b * CMD + j] = acc;
        }
    }
}

// ---- fast textual command ----
__global__ __launch_bounds__(1024)
void text_cmd_fast(const float* __restrict__ qcmd, const float* __restrict__ lstm,
                   const float* __restrict__ c2l_w, const float* __restrict__ c2l_b,
                   const int* __restrict__ qlen, float* __restrict__ cmd)
{
    const int b = blockIdx.x;
    const int tid = threadIdx.x;
    const int wid = tid >> 5, lane = tid & 31;
    __shared__ float e[CMD];
    __shared__ float att[LQL];
    __shared__ float red[128];
    __shared__ float smx, ssum;

    if (tid < CMD) e[tid] = qcmd[b * CMD + tid] * c2l_w[tid];
    __syncthreads();

    const int en = qlen[b];
    #pragma unroll
    for (int li = 0; li < 4; ++li) {
        const int l = wid + li * 32;
        const float* L = lstm + ((size_t)b * LQL + l) * CMD;
        float acc = 0.f;
        #pragma unroll
        for (int i = 0; i < CMD / 32; ++i)
            acc = fmaf(L[lane + 32 * i], e[lane + 32 * i], acc);
        #pragma unroll
        for (int o = 16; o > 0; o >>= 1)
            acc += __shfl_down_sync(0xFFFFFFFFu, acc, o);
        if (lane == 0) att[l] = (l >= en) ? NEGV : (acc + c2l_b[0]);
    }
    __syncthreads();

    if (tid < 128) red[tid] = att[tid];
    __syncthreads();
    for (int o = 64; o > 0; o >>= 1) {
        if (tid < o) red[tid] = fmaxf(red[tid], red[tid + o]);
        __syncthreads();
    }
    if (tid == 0) smx = red[0];
    __syncthreads();
    float ev = 0.f;
    if (tid < 128) { ev = expf(att[tid] - smx); red[tid] = ev; }
    __syncthreads();
    for (int o = 64; o > 0; o >>= 1) {
        if (tid < o) red[tid] += red[tid + o];
        __syncthreads();
    }
    if (tid == 0) ssum = red[0];
    __syncthreads();
    if (tid < 128) att[tid] = ev / ssum;
    __syncthreads();

    if (tid < CMD) {
        float acc = 0.f;
        const float* L = lstm + (size_t)b * LQL * CMD + tid;
        #pragma unroll 4
        for (int l = 0; l < LQL; ++l)
            acc = fmaf(att[l], L[(size_t)l * CMD], acc);
        cmd[b * CMD + tid] = acc;
    }
}

// masked row softmax (in place); cleans all cols < nblk*256 (covers BKm=32 K-truncation)
__global__ void attn_softmax_kernel(float* __restrict__ score, const int* __restrict__ entity_num)
{
    const int row = blockIdx.x;
    const int b = row >> 10;
    const int n = row & 1023;
    const int en = entity_num[b];
    if (n >= en) return;
    float* s = score + (size_t)row * NENT;
    const int tid = threadIdx.x;

    const int kc = ((en + 15) / 16) * 16;
    const int nblk = (kc + 255) >> 8;

    float v[4];
    float mx = -3.4e38f;
    #pragma unroll
    for (int j = 0; j < 4; j++) {
        const int m = tid + j * 256;
        float x = NEGV;
        if (j < nblk && m < en) x = s[m];
        v[j] = x;
        mx = fmaxf(mx, x);
    }
    __shared__ float red[256];
    red[tid] = mx; __syncthreads();
    for (int o = 128; o > 0; o >>= 1) { if (tid < o) red[tid] = fmaxf(red[tid], red[tid + o]); __syncthreads(); }
    mx = red[0];
    __syncthreads();

    float sum = 0.f;
    #pragma unroll
    for (int j = 0; j < 4; j++) { v[j] = expf(v[j] - mx); sum += v[j]; }
    red[tid] = sum; __syncthreads();
    for (int o = 128; o > 0; o >>= 1) { if (tid < o) red[tid] += red[tid + o]; __syncthreads(); }
    const float inv = 1.f / red[0];

    #pragma unroll
    for (int j = 0; j < 4; j++)
        if (j < nblk) s[tid + j * 256] = rna_tf32(v[j] * inv);
}

// ---------------- launch ----------------
template<typename T> static float* symaddr(T& sym) {
    void* p = nullptr;
    cudaGetSymbolAddress(&p, sym);
    return (float*)p;
}

extern "C" void kernel_launch(void* const* d_in, const int* in_sizes, int n_in,
                              void* d_out, int out_size)
{
    const float* images    = (const float*)d_in[0];
    const float* q_enc     = (const float*)d_in[1];
    const float* lstm      = (const float*)d_in[2];
    const int*   q_length  = (const int*)  d_in[3];
    const int*   ent_num   = (const int*)  d_in[4];
    const float* initKB_w  = (const float*)d_in[5];
    const float* initKB_b  = (const float*)d_in[6];
    const float* initMem   = (const float*)d_in[7];
    const float* qInput_w  = (const float*)d_in[8];
    const float* qInput_b  = (const float*)d_in[9];
    const float* qInput2_w = (const float*)d_in[10];
    const float* qInput2_b = (const float*)d_in[11];
    const float* c2l_w     = (const float*)d_in[12];
    const float* c2l_b     = (const float*)d_in[13];
    const float* pxl_w     = (const float*)d_in[14];
    const float* pxl_b     = (const float*)d_in[15];
    const float* pxc_w     = (const float*)d_in[16];
    const float* pxc_b     = (const float*)d_in[17];
    const float* qry_w     = (const float*)d_in[18];
    const float* qry_b     = (const float*)d_in[19];
    const float* key_w     = (const float*)d_in[20];
    const float* key_b     = (const float*)d_in[21];
    const float* val_w     = (const float*)d_in[22];
    const float* val_b     = (const float*)d_in[23];
    const float* pk_w      = (const float*)d_in[24];
    const float* pk_b      = (const float*)d_in[25];
    const float* pv_w      = (const float*)d_in[26];
    const float* pv_b      = (const float*)d_in[27];
    const float* mu_w      = (const float*)d_in[28];
    const float* mu_b      = (const float*)d_in[29];
    const float* ck_w      = (const float*)d_in[30];
    const float* ck_b      = (const float*)d_in[31];

    float* imgr  = symaddr(g_imgr);
    float* invn  = symaddr(g_invnorm);
    float* xloc  = symaddr(g_xloc);
    float* xctxA = symaddr(g_xctx0);
    float* xctxB = symaddr(g_xctx1);
    float* prjl  = symaddr(g_projloc);
    float* pp    = symaddr(g_pp);
    float* q     = symaddr(g_q);
    float* k     = symaddr(g_k);
    float* vT    = symaddr(g_vT);
    float* msg   = symaddr(g_msg);
    float* qL    = symaddr(g_qL);
    float* kL    = symaddr(g_kL);
    float* vL    = symaddr(g_vL);
    float* score = symaddr(g_score);
    float* qbase = symaddr(g_qbase);
    float* qcmd  = symaddr(g_qcmd);
    float* cmd   = symaddr(g_cmd);
    float* pkg   = symaddr(g_pkg);
    float* pvg   = symaddr(g_pvg);
    float* msgm  = symaddr(g_msgm);
    float* xcm   = symaddr(g_xcm);
    float* wIKB  = symaddr(g_wT_ikb);
    float* wPXL  = symaddr(g_wT_pxl);
    float* wPXC  = symaddr(g_wT_pxc);
    float* wQRY  = symaddr(g_wT_qry);
    float* wKEY  = symaddr(g_wT_key);
    float* wVAL  = symaddr(g_wT_val);
    float* wMU   = symaddr(g_wT_mu);
    float* wCK   = symaddr(g_wT_ck);
    float* wQIN  = symaddr(g_wT_qin);
    float* wQIN2 = symaddr(g_wT_qin2);
    float* wPK   = symaddr(g_wT_pk);
    float* wPV   = symaddr(g_wT_pv);

    cudaFuncSetAttribute(gemm_mma<1,0,false,false,0,false>, cudaFuncAttributeMaxDynamicSharedMemorySize, SMEM_DYN);
    cudaFuncSetAttribute(gemm_mma<1,0,false,false,3,false>, cudaFuncAttributeMaxDynamicSharedMemorySize, SMEM_DYN);
    cudaFuncSetAttribute(gemm_mma<1,1,true ,false,0,false>, cudaFuncAttributeMaxDynamicSharedMemorySize, SMEM_DYN);
    cudaFuncSetAttribute(gemm_mma<1,3,true ,false,0,false>, cudaFuncAttributeMaxDynamicSharedMemorySize, SMEM_DYN);
    cudaFuncSetAttribute(gemm_mma<1,0,false,false,1,false>, cudaFuncAttributeMaxDynamicSharedMemorySize, SMEM_DYN);
    cudaFuncSetAttribute(gemm_mma<1,0,true ,false,2,false>, cudaFuncAttributeMaxDynamicSharedMemorySize, SMEM_DYN);
    cudaFuncSetAttribute(gemm_mma<2,0,true ,true ,3,false>, cudaFuncAttributeMaxDynamicSharedMemorySize, SMEM_DYN);
    cudaFuncSetAttribute(gemm_mma<2,2,true ,true ,3,false>, cudaFuncAttributeMaxDynamicSharedMemorySize, SMEM_DYN);
    cudaFuncSetAttribute(gemm_mma<2,2,true ,true ,0,true >, cudaFuncAttributeMaxDynamicSharedMemorySize, SMEM_DYN);
    cudaFuncSetAttribute(gemm_mma<2,0,true ,false,3,false>, cudaFuncAttributeMaxDynamicSharedMemorySize, SMEM_DYN);
    cudaFuncSetAttribute(gemm_mma<2,0,false,false,0,false>, cudaFuncAttributeMaxDynamicSharedMemorySize, SMEM_DYN);

    const float scale = 0.044194173824159216f;   // 1/sqrt(512)
    const dim3 tdim(32, 8);
    const dim3 gridMain(CTX / BNm, MROWS / BMm, 1);
    const dim3 gridScore(NENT / BNm, NENT / BMm, BB);
    const dim3 gridMsg(CTX / BNm, NENT / BMm, BB);
    const dim3 gridSL(CMD / 32, BB);

    // --- order: initKB GEMM at launch index 3 (ncu -s 5) ---
    transpose_kernel<true ><<<dim3(CTX/32, DFEAT/32, 1), tdim>>>(initKB_w, wIKB, DFEAT, CTX, 0, 0); // 0
    rownorm_round_kernel<<<MROWS, 256>>>(images, invn, imgr);                                        // 1
    ctx_init_kernel<<<(MROWS * CTX) / 256, 256>>>(initMem, xctxA, xcm);                              // 2
    // 3: x_loc = normalize(images) @ initKB_w + b   <-- ncu target
    gemm_mma<1,1,true,false,0,false><<<gridMain, 256, SMEM_DYN>>>(
        imgr, nullptr, nullptr, wIKB, initKB_b, invn, nullptr, nullptr, xloc,
        DFEAT, DFEAT, DFEAT, CTX, 0, 0, 0, 1.f);

    // remaining weight transposes
    transpose_kernel<false><<<dim3(CMD/32, CMD/32, 1), tdim>>>(qInput_w, wQIN, CMD, CMD, 0, 0);
    small_linear_fast<true><<<gridSL, 256>>>(q_enc, wQIN, qInput_b, qbase);
    transpose_kernel<true><<<dim3(CTX/32, CTX/32, 1),   tdim>>>(pxl_w, wPXL, CTX,   CTX, 0, 0);
    transpose_kernel<true><<<dim3(CTX/32, CTX/32, 1),   tdim>>>(pxc_w, wPXC, CTX,   CTX, 0, 0);
    transpose_kernel<true><<<dim3(CTX/32, 3*CTX/32, 1), tdim>>>(qry_w, wQRY, 3*CTX, CTX, 0, 0);
    transpose_kernel<true><<<dim3(CTX/32, 3*CTX/32, 1), tdim>>>(key_w, wKEY, 3*CTX, CTX, 0, 0);
    transpose_kernel<true><<<dim3(CTX/32, 3*CTX/32, 1), tdim>>>(val_w, wVAL, 3*CTX, CTX, 0, 0);
    transpose_kernel<true><<<dim3(CTX/32, 2*CTX/32, 1), tdim>>>(mu_w,  wMU,  2*CTX, CTX, 0, 0);
    transpose_kernel<true><<<dim3(CTX/32, 2*CTX/32, 1), tdim>>>(ck_w,  wCK,  2*CTX, CTX, 0, 0);
    transpose_kernel<false><<<dim3(CMD/32, CMD/32, TT), tdim>>>(qInput2_w, wQIN2, CMD, CMD,
                                                                (size_t)CMD*CMD, (size_t)CMD*CMD);
    transpose_kernel<false><<<dim3(CTX/32, CMD/32, 1), tdim>>>(pk_w, wPK, CMD, CTX, 0, 0);
    transpose_kernel<false><<<dim3(CTX/32, CMD/32, 1), tdim>>>(pv_w, wPV, CMD, CTX, 0, 0);

    // ---- iteration-invariant hoists ----
    gemm_mma<1,0,false,false,0,false><<<gridMain, 256, SMEM_DYN>>>(
        xloc, nullptr, nullptr, wPXL, pxl_b, nullptr, nullptr, nullptr, prjl,
        CTX, CTX, CTX, CTX, 0, 0, 0, 1.f);
    gemm_mma<1,0,false,false,3,false><<<gridMain, 256, SMEM_DYN>>>(
        xloc, nullptr, nullptr, wQRY, nullptr, nullptr, nullptr, ent_num, qL,
        CTX, CTX, 3*CTX, CTX, 0, 0, 0, 1.f);
    gemm_mma<1,0,false,false,3,false><<<gridMain, 256, SMEM_DYN>>>(
        xloc, nullptr, nullptr, wKEY, nullptr, nullptr, nullptr, ent_num, kL,
        CTX, CTX, 3*CTX, CTX, 0, 0, 0, 1.f);
    gemm_mma<1,0,false,false,0,false><<<gridMain, 256, SMEM_DYN>>>(
        xloc, nullptr, nullptr, wVAL, nullptr, nullptr, nullptr, nullptr, vL,
        CTX, CTX, 3*CTX, CTX, 0, 0, 0, 1.f);

    float* xc = xctxA;
    float* xn = xctxB;
    for (int t = 0; t < TT; t++) {
        small_linear_fast<false><<<gridSL, 256>>>(qbase, wQIN2 + (size_t)t * CMD * CMD,
                                                  qInput2_b + (size_t)t * CMD, qcmd);
        text_cmd_fast<<<BB, 1024>>>(qcmd, lstm, c2l_w, c2l_b, q_length, cmd);
        small_linear_fast<false><<<gridSL, 256>>>(cmd, wPK, pk_b, pkg);
        small_linear_fast<false><<<gridSL, 256>>>(cmd, wPV, pv_b, pvg);

        // pp = (x_ctx @ pxc + b) * proj_loc   (full: v needs all rows)
        gemm_mma<1,3,true,false,0,false><<<gridMain, 256, SMEM_DYN>>>(
            xc, nullptr, nullptr, wPXC, pxc_b, prjl, nullptr, nullptr, pp,
            CTX, CTX, CTX, CTX, 0, 0, 0, 1.f);

        // q/k: live rows only; v: full, written TRANSPOSED directly to vT
        gemm_mma<2,0,true,true,3,false><<<gridMain, 256, SMEM_DYN>>>(
            xc, pp, nullptr, wQRY + CTX, qry_b, nullptr, qL, ent_num, q,
            2*CTX, 0, 3*CTX, CTX, 0, 0, 0, 1.f);
        gemm_mma<2,2,true,true,3,false><<<gridMain, 256, SMEM_DYN>>>(
            xc, pp, nullptr, wKEY + CTX, key_b, pkg, kL, ent_num, k,
            2*CTX, 0, 3*CTX, CTX, 0, 0, 0, 1.f);
        gemm_mma<2,2,true,true,0,true><<<gridMain, 256, SMEM_DYN>>>(
            xc, pp, nullptr, wVAL + CTX, val_b, pvg, vL, nullptr, vT,
            2*CTX, 0, 3*CTX, CTX, 0, 0, 0, 1.f);

        // score[b] = scale * q[b] @ k[b]^T — live tiles only
        gemm_mma<1,0,false,false,1,false><<<gridScore, 256, SMEM_DYN>>>(
            q, nullptr, nullptr, k, nullptr, nullptr, nullptr, ent_num, score,
            CTX, CTX, CTX, NENT,
            (size_t)NENT * CTX, (size_t)NENT * CTX, (size_t)NENT * NENT, scale);

        attn_softmax_kernel<<<MROWS, 256>>>(score, ent_num);

        // message live rows; per-batch mean(v) for masked rows
        gemm_mma<1,0,true,false,2,false><<<gridMsg, 256, SMEM_DYN>>>(
            score, nullptr, nullptr, vT, nullptr, nullptr, nullptr, ent_num, msg,
            NENT, NENT, NENT, CTX,
            (size_t)NENT * NENT, (size_t)CTX * NENT, (size_t)NENT * CTX, 1.f);
        mean_vT_kernel<<<dim3(CTX / 8, BB), 256>>>(vT, ent_num, msgm);

        // x_ctx' live rows via MMA; masked rows via parallel broadcast
        gemm_mma<2,0,true,false,3,false><<<gridMain, 256, SMEM_DYN>>>(
            xc, msg, nullptr, wMU, mu_b, nullptr, nullptr, ent_num, xn,
            2*CTX, 0, 2*CTX, CTX, 0, 0, 0, 1.f);
        ctx_compute_kernel<<<BB, 256>>>(msgm, wMU, mu_b, ent_num, xcm);
        bcast_rows_kernel<<<dim3(NENT / 128, BB), 256>>>(xcm, ent_num, xn);

        float* tmp = xc; xc = xn; xn = tmp;
    }

    // out = [x_loc | x_ctx] @ ck + b
    gemm_mma<2,0,false,false,0,false><<<gridMain, 256, SMEM_DYN>>>(
        xloc, xc, nullptr, wCK, ck_b, nullptr, nullptr, nullptr, (float*)d_out,
        2*CTX, 0, 2*CTX, CTX, 0, 0, 0, 1.f);
}